// round 6
// baseline (speedup 1.0000x reference)
#include <cuda_runtime.h>
#include <cuda_bf16.h>
#include <math.h>

// Problem constants
#define BB 32
#define TT 32
#define SS 64
#define HH 512
#define EE 512
#define VV 32000
#define T1 (TT-1)
#define TBV ((size_t)T1*BB*VV)
#define BH (BB*HH)
#define MPAD 1024
#define KX 1536
#define JG 2048
#define GZ 8
#define NCTA 128       // persistent grid (16 ntiles x 8 splitK)

// -------- persistent device scratch --------
__device__ float g_h[BH];
__device__ float g_c[BH];
__device__ float g_proj[BB*SS*HH];
__device__ __align__(16) float g_XC[BB*1024];
__device__ float g_Gpart[GZ*BB*JG];
__device__ int   g_argmax[T1*BB];
__device__ float g_logits[T1*BB*VV];
__device__ __align__(16) __nv_bfloat16 g_Wh[(size_t)VV*HH];
__device__ __align__(16) __nv_bfloat16 g_Wl[(size_t)VV*HH];
__device__ __align__(16) __nv_bfloat16 g_Ah[MPAD*HH];   // rows 992..1023 stay 0
__device__ __align__(16) __nv_bfloat16 g_Al[MPAD*HH];
__device__ __align__(16) __nv_bfloat16 g_gWh[JG*KX];
__device__ __align__(16) __nv_bfloat16 g_gWl[JG*KX];
__device__ __align__(16) __nv_bfloat16 g_Xh[BB*KX];
__device__ __align__(16) __nv_bfloat16 g_Xl[BB*KX];
__device__ unsigned g_barcnt;

__device__ __forceinline__ float sigf(float x){ return 1.0f/(1.0f+expf(-x)); }

__device__ __forceinline__ float fexp(float x){
    float t = x * 1.4426950408889634f;
    float n = rintf(t);
    float f = t - n;
    float p = 1.5403530e-4f;
    p = fmaf(p, f, 1.3333558e-3f);
    p = fmaf(p, f, 9.6181291e-3f);
    p = fmaf(p, f, 5.5504109e-2f);
    p = fmaf(p, f, 2.4022651e-1f);
    p = fmaf(p, f, 6.9314718e-1f);
    p = fmaf(p, f, 1.0f);
    int e = (int)n;
    e = e < -126 ? -126 : (e > 127 ? 127 : e);
    float sc = __int_as_float((e+127)<<23);
    return p*sc;
}

// ------------------ low-level helpers ------------------
__device__ __forceinline__ unsigned smem_u32(const void* p){
    unsigned a;
    asm("{ .reg .u64 t; cvta.to.shared.u64 t, %1; cvt.u32.u64 %0, t; }" : "=r"(a) : "l"(p));
    return a;
}
__device__ __forceinline__ void cpa16(unsigned dst, const void* src){
    asm volatile("cp.async.cg.shared.global [%0], [%1], 16;" :: "r"(dst), "l"(src));
}
#define CP_COMMIT() asm volatile("cp.async.commit_group;" ::: "memory")
#define CP_WAIT(n)  asm volatile("cp.async.wait_group %0;" :: "n"(n) : "memory")

__device__ __forceinline__ void ldmx4(unsigned* r, unsigned addr){
    asm volatile("ldmatrix.sync.aligned.m8n8.x4.shared.b16 {%0,%1,%2,%3}, [%4];"
        : "=r"(r[0]), "=r"(r[1]), "=r"(r[2]), "=r"(r[3]) : "r"(addr));
}
__device__ __forceinline__ void mma16816(float* d, const unsigned* a,
                                         unsigned b0, unsigned b1){
    asm volatile(
        "mma.sync.aligned.m16n8k16.row.col.f32.bf16.bf16.f32 "
        "{%0,%1,%2,%3}, {%4,%5,%6,%7}, {%8,%9}, {%0,%1,%2,%3};"
        : "+f"(d[0]), "+f"(d[1]), "+f"(d[2]), "+f"(d[3])
        : "r"(a[0]), "r"(a[1]), "r"(a[2]), "r"(a[3]), "r"(b0), "r"(b1));
}
__device__ __forceinline__ void bsplit(float v, __nv_bfloat16& hi, __nv_bfloat16& lo){
    hi = __float2bfloat16(v);
    lo = __float2bfloat16(v - __bfloat162float(hi));
}

// software grid barrier (counter reset by k_rst before each launch)
__device__ __forceinline__ void gbar(unsigned target){
    __syncthreads();
    if (threadIdx.x == 0){
        __threadfence();
        atomicAdd(&g_barcnt, 1u);
        while (*(volatile unsigned*)&g_barcnt < target) { __nanosleep(20); }
        __threadfence();
    }
    __syncthreads();
}

__global__ void k_rst(){ g_barcnt = 0; }

// ---------------------------------------------------------------------------
// Generic tiled SGEMM (proj precompute only)
// ---------------------------------------------------------------------------
template<int BM,int BN,int BK,int TM,int TN>
__global__ void sgemm(const float* __restrict__ A, const float* __restrict__ B,
                      float* __restrict__ C, int M, int N, int K)
{
    constexpr int THREADS = (BM/TM)*(BN/TN);
    static_assert(THREADS == 256, "256 threads expected");
    __shared__ float As[BK][BM+4];
    __shared__ float Bs[BK][BN+4];
    const int tid = threadIdx.x;
    const int bm = blockIdx.y*BM, bn = blockIdx.x*BN;
    const int tx = tid % (BN/TN);
    const int ty = tid / (BN/TN);
    float acc[TM][TN];
    #pragma unroll
    for (int i=0;i<TM;i++)
        #pragma unroll
        for (int j=0;j<TN;j++) acc[i][j]=0.f;

    for (int k0 = 0; k0 < K; k0 += BK) {
        #pragma unroll
        for (int i=0;i<(BM*BK)/THREADS;i++){
            int idx = tid + i*THREADS; int m = idx/BK, k = idx%BK;
            As[k][m] = A[(size_t)(bm+m)*K + k0 + k];
        }
        #pragma unroll
        for (int i=0;i<(BN*BK)/THREADS;i++){
            int idx = tid + i*THREADS; int n = idx/BK, k = idx%BK;
            Bs[k][n] = B[(size_t)(bn+n)*K + k0 + k];
        }
        __syncthreads();
        #pragma unroll
        for (int kk=0;kk<BK;kk++){
            float a[TM], b[TN];
            #pragma unroll
            for (int i=0;i<TM;i++) a[i] = As[kk][ty*TM+i];
            #pragma unroll
            for (int j=0;j<TN;j++) b[j] = Bs[kk][tx*TN+j];
            #pragma unroll
            for (int i=0;i<TM;i++)
                #pragma unroll
                for (int j=0;j<TN;j++) acc[i][j] += a[i]*b[j];
        }
        __syncthreads();
    }
    #pragma unroll
    for (int i=0;i<TM;i++){
        int gm = bm + ty*TM + i;
        #pragma unroll
        for (int j=0;j<TN;j++)
            C[(size_t)gm*N + bn + tx*TN + j] = acc[i][j];
    }
}

// ---------------------------------------------------------------------------
// Prologue: h,c init + assemble X for step 0
// ---------------------------------------------------------------------------
__global__ void k_prep0(const float* __restrict__ h0, const float* __restrict__ c0,
                        const int* __restrict__ tgt, const float* __restrict__ emb)
{
    int idx = blockIdx.x*256 + threadIdx.x;
    int b = idx >> 9, k = idx & 511;
    g_h[idx] = h0[idx];
    g_c[idx] = c0[idx];
    __nv_bfloat16 hi, lo;
    int w = tgt[b*TT + 0];
    bsplit(emb[(size_t)w*EE + k], hi, lo);
    g_Xh[b*KX + k] = hi;  g_Xl[b*KX + k] = lo;
    g_Xh[b*KX + 512 + k] = __float2bfloat16(0.f);
    g_Xl[b*KX + 512 + k] = __float2bfloat16(0.f);
    bsplit(h0[idx], hi, lo);
    g_Xh[b*KX + 1024 + k] = hi;  g_Xl[b*KX + 1024 + k] = lo;
}

__global__ void k_convG(const float* __restrict__ W_ih, const float* __restrict__ W_hh)
{
    size_t i = ((size_t)blockIdx.x*256 + threadIdx.x)*4;
    if (i >= (size_t)JG*KX) return;
    int j = (int)(i / KX);
    int k = (int)(i % KX);
    float4 v = (k < 1024) ? *(const float4*)(W_ih + (size_t)j*1024 + k)
                          : *(const float4*)(W_hh + (size_t)j*512 + (k-1024));
    __nv_bfloat16 h, l;
    bsplit(v.x, h, l); g_gWh[i+0]=h; g_gWl[i+0]=l;
    bsplit(v.y, h, l); g_gWh[i+1]=h; g_gWl[i+1]=l;
    bsplit(v.z, h, l); g_gWh[i+2]=h; g_gWl[i+2]=l;
    bsplit(v.w, h, l); g_gWh[i+3]=h; g_gWl[i+3]=l;
}

// ---------------------------------------------------------------------------
// Persistent recurrent loop: 128 CTAs x 256 threads, 31 steps, 3 phases/step.
// Dynamic smem = 128KB (union: 2x46KB gate buffers | phaseB scratch | XC stage)
// ---------------------------------------------------------------------------
#define GSTR 72
#define ABUF 46080     // bytes per gates double-buffer

__global__ void __launch_bounds__(256)
k_loop(const float* __restrict__ b_ih, const float* __restrict__ b_hh,
       const int* __restrict__ lens, const float* __restrict__ enc,
       const float* __restrict__ W_c, const float* __restrict__ b_c,
       const int* __restrict__ tgt, const float* __restrict__ emb)
{
    extern __shared__ char dsm[];
    const int ct  = blockIdx.x;
    const int tid = threadIdx.x;
    const int w = tid >> 5, l = tid & 31;
    const unsigned base = smem_u32(dsm);

    // ---- loop-invariant per-CTA state ----
    // gates tile assignment
    const int nt = ct & 15;
    const int z  = ct >> 4;
    const int nbase = nt * 128;
    const int kbase = z * 192;
    const int n0 = w * 16;
    const int arow  = (l & 7) + ((l >> 3) & 1) * 8;
    const int akoff = (l >> 4) * 8;
    const int brow  = (l & 7) + ((l >> 4) & 1) * 8;
    const int bkoff = ((l >> 3) & 1) * 8;

    // W_c rows in registers (CTAs 0..63, one column per warp)
    float wreg[32];
    float wbias = 0.f;
    if (ct < 64){
        const int c = ct*8 + w;
        const float* wr = W_c + (size_t)c*1024;
        #pragma unroll
        for (int q=0;q<32;q++) wreg[q] = wr[l + q*32];
        wbias = b_c[c];
    }

    unsigned nb = 0;   // barrier count

    for (int t = 0; t < T1; t++){
        // ================= Phase A: gates GEMM (all CTAs) =================
        {
            auto issue = [&](int buf, int ck){
                const int koff = kbase + ck*64;
                const unsigned uAh = base + buf*ABUF;
                const unsigned uAl = uAh + 4608;
                const unsigned uBh = uAh + 9216;
                const unsigned uBl = uAh + 27648;
                #pragma unroll
                for (int q = 0; q < 10; q++){
                    int i = q*256 + tid;
                    if (i < 512){
                        int idx = i & 255; int row = idx >> 3, c8 = idx & 7;
                        const __nv_bfloat16* src = (i < 256 ? g_Xh : g_Xl)
                                                   + (size_t)row*KX + koff + c8*8;
                        unsigned dst = (i < 256 ? uAh : uAl) + (unsigned)(row*GSTR + c8*8)*2;
                        cpa16(dst, src);
                    } else {
                        int idx = (i - 512) & 1023; int row = idx >> 3, c8 = idx & 7;
                        const __nv_bfloat16* src = (i < 1536 ? g_gWh : g_gWl)
                                                   + (size_t)(nbase+row)*KX + koff + c8*8;
                        unsigned dst = (i < 1536 ? uBh : uBl) + (unsigned)(row*GSTR + c8*8)*2;
                        cpa16(dst, src);
                    }
                }
            };

            float acc[2][2][4];
            #pragma unroll
            for (int mi=0;mi<2;mi++)
                #pragma unroll
                for (int ni=0;ni<2;ni++)
                    #pragma unroll
                    for (int q=0;q<4;q++) acc[mi][ni][q]=0.f;

            issue(0, 0); CP_COMMIT();

            for (int ck = 0; ck < 3; ck++){
                int buf = ck & 1;
                if (ck < 2){ issue(buf ^ 1, ck + 1); CP_COMMIT(); CP_WAIT(1); }
                else       { CP_WAIT(0); }
                __syncthreads();

                const unsigned uAh = base + buf*ABUF;
                const unsigned uAl = uAh + 4608;
                const unsigned uBh = uAh + 9216;
                const unsigned uBl = uAh + 27648;
                #pragma unroll
                for (int ks = 0; ks < 64; ks += 16){
                    unsigned afh[2][4], afl[2][4], bfh[4], bfl[4];
                    #pragma unroll
                    for (int mi=0;mi<2;mi++){
                        ldmx4(afh[mi], uAh + (unsigned)((mi*16 + arow)*GSTR + ks + akoff)*2);
                        ldmx4(afl[mi], uAl + (unsigned)((mi*16 + arow)*GSTR + ks + akoff)*2);
                    }
                    ldmx4(bfh, uBh + (unsigned)((n0 + brow)*GSTR + ks + bkoff)*2);
                    ldmx4(bfl, uBl + (unsigned)((n0 + brow)*GSTR + ks + bkoff)*2);
                    #pragma unroll
                    for (int mi=0;mi<2;mi++)
                        #pragma unroll
                        for (int ni=0;ni<2;ni++){
                            mma16816(acc[mi][ni], afh[mi], bfh[ni*2], bfh[ni*2+1]);
                            mma16816(acc[mi][ni], afh[mi], bfl[ni*2], bfl[ni*2+1]);
                            mma16816(acc[mi][ni], afl[mi], bfh[ni*2], bfh[ni*2+1]);
                        }
                }
                __syncthreads();
            }

            #pragma unroll
            for (int mi=0;mi<2;mi++){
                #pragma unroll
                for (int ni=0;ni<2;ni++){
                    int row = mi*16 + (l >> 2);
                    int col = nbase + n0 + ni*8 + (l & 3)*2;
                    float* gp = g_Gpart + ((size_t)z*BB + row)*JG + col;
                    gp[0] = acc[mi][ni][0];
                    gp[1] = acc[mi][ni][1];
                    gp += 8*JG;
                    gp[0] = acc[mi][ni][2];
                    gp[1] = acc[mi][ni][3];
                }
            }
        }
        gbar(++nb * NCTA);

        // ============ Phase B: LSTM cell + attention (CTAs 0..31) ============
        if (ct < BB){
            const int b = ct;
            float* hh = (float*)dsm;          // 512 floats
            float* sc = hh + HH;              // 64 floats
            const int len = lens[b];

            #pragma unroll
            for (int rep = 0; rep < 2; rep++){
                int h = tid + rep*256;
                float gv[4];
                #pragma unroll
                for (int q=0;q<4;q++){
                    int j = q*HH + h;
                    float s = b_ih[j] + b_hh[j];
                    #pragma unroll
                    for (int zz=0;zz<GZ;zz++) s += g_Gpart[((size_t)zz*BB + b)*JG + j];
                    gv[q] = s;
                }
                int idx = b*HH + h;
                float ig = sigf(gv[0]);
                float fg = sigf(gv[1]);
                float gg = tanhf(gv[2]);
                float og = sigf(gv[3]);
                float c  = fg * g_c[idx] + ig * gg;
                g_c[idx] = c;
                float h2 = og * tanhf(c);
                g_h[idx] = h2;
                hh[h] = h2;
                g_XC[b*1024 + h] = h2;
                __nv_bfloat16 hi, lo; bsplit(h2, hi, lo);
                g_Xh[b*KX + 1024 + h] = hi;
                g_Xl[b*KX + 1024 + h] = lo;
            }
            __syncthreads();

            // scores: warp w handles s = w*8 .. w*8+7
            #pragma unroll
            for (int i = 0; i < 8; i++){
                int s = w*8 + i;
                const float* pr = &g_proj[((size_t)s*BB + b)*HH];
                float sum = 0.f;
                #pragma unroll
                for (int k = 0; k < 16; k++) sum += hh[l + k*32] * pr[l + k*32];
                #pragma unroll
                for (int off=16; off>0; off>>=1) sum += __shfl_xor_sync(0xffffffffu, sum, off);
                if (l == 0) sc[s] = (s < len) ? sum : -1e9f;
            }
            __syncthreads();

            if (tid < 32){
                float v0 = sc[tid], v1 = sc[tid+32];
                float m = fmaxf(v0, v1);
                #pragma unroll
                for (int off=16; off>0; off>>=1) m = fmaxf(m, __shfl_xor_sync(0xffffffffu, m, off));
                float e0 = expf(v0 - m), e1 = expf(v1 - m);
                float s = e0 + e1;
                #pragma unroll
                for (int off=16; off>0; off>>=1) s += __shfl_xor_sync(0xffffffffu, s, off);
                float inv = 1.0f / s;
                sc[tid]    = e0 * inv;
                sc[tid+32] = e1 * inv;
            }
            __syncthreads();

            #pragma unroll
            for (int rep = 0; rep < 2; rep++){
                int h = tid + rep*256;
                float acc = 0.f;
                #pragma unroll 4
                for (int s = 0; s < SS; s++)
                    acc += sc[s] * enc[((size_t)s*BB + b)*HH + h];
                g_XC[b*1024 + 512 + h] = acc;
            }
        }
        gbar(++nb * NCTA);

        // ============ Phase C: ah2 (CTAs 0..63) | emb gather (64..127) ============
        if (ct < 64){
            float* xc = (float*)dsm;          // 32768 floats = 128KB
            {
                const float4* src = (const float4*)g_XC;
                float4* dst = (float4*)xc;
                for (int i = tid; i < 8192; i += 256) dst[i] = src[i];
            }
            __syncthreads();

            const int c = ct*8 + w;
            for (int b = 0; b < BB; b++){
                const float* xb = xc + b*1024;
                float s = 0.f;
                #pragma unroll
                for (int q=0;q<32;q++) s += wreg[q] * xb[l + q*32];
                #pragma unroll
                for (int off=16; off>0; off>>=1) s += __shfl_xor_sync(0xffffffffu, s, off);
                if (l == 0){
                    float v = tanhf(s + wbias);
                    __nv_bfloat16 hi, lo; bsplit(v, hi, lo);
                    int r = t*BB + b;
                    g_Ah[(size_t)r*HH + c] = hi;
                    g_Al[(size_t)r*HH + c] = lo;
                    g_Xh[b*KX + 512 + c] = hi;
                    g_Xl[b*KX + 512 + c] = lo;
                }
            }
        } else if (t < T1-1){
            int idx = ct - 64;
            int b2 = idx >> 1;
            int k2 = (idx & 1)*256 + tid;
            int wd = tgt[b2*TT + (t+1)];
            __nv_bfloat16 hi, lo;
            bsplit(emb[(size_t)wd*EE + k2], hi, lo);
            g_Xh[b2*KX + k2] = hi;
            g_Xl[b2*KX + k2] = lo;
        }
        gbar(++nb * NCTA);
    }
}

// ---------------------------------------------------------------------------
// bf16 split of W_o
// ---------------------------------------------------------------------------
__global__ void k_convW(const float* __restrict__ W)
{
    size_t i = ((size_t)blockIdx.x*256 + threadIdx.x)*4;
    if (i >= (size_t)VV*HH) return;
    float4 v = *(const float4*)(W + i);
    __nv_bfloat16 h0, h1, h2, h3, l0, l1, l2, l3;
    bsplit(v.x, h0, l0); bsplit(v.y, h1, l1);
    bsplit(v.z, h2, l2); bsplit(v.w, h3, l3);
    *(__nv_bfloat162*)(g_Wh + i)     = __nv_bfloat162(h0, h1);
    *(__nv_bfloat162*)(g_Wh + i + 2) = __nv_bfloat162(h2, h3);
    *(__nv_bfloat162*)(g_Wl + i)     = __nv_bfloat162(l0, l1);
    *(__nv_bfloat162*)(g_Wl + i + 2) = __nv_bfloat162(l2, l3);
}

// ---------------------------------------------------------------------------
// Vocab GEMM via mma.sync (proven round-5 kernel, unchanged)
// ---------------------------------------------------------------------------
#define VK_STR 40

__global__ void __launch_bounds__(256, 2)
k_vocab(const float* __restrict__ b_o, float* __restrict__ logits)
{
    __shared__ __align__(16) __nv_bfloat16 As[2][128*VK_STR];
    __shared__ __align__(16) __nv_bfloat16 Bs[2][64*VK_STR];
    const int tid  = threadIdx.x;
    const int wid  = tid >> 5, lane = tid & 31;
    const int mtile = blockIdx.x;
    const int ntile = blockIdx.y;

    const __nv_bfloat16* Ap[3] = { g_Ah + (size_t)mtile*128*HH,
                                   g_Ah + (size_t)mtile*128*HH,
                                   g_Al + (size_t)mtile*128*HH };
    const __nv_bfloat16* Bp[3] = { g_Wh + (size_t)ntile*64*HH,
                                   g_Wl + (size_t)ntile*64*HH,
                                   g_Wh + (size_t)ntile*64*HH };

    const unsigned sA0 = smem_u32(&As[0][0]);
    const unsigned sA1 = smem_u32(&As[1][0]);
    const unsigned sB0 = smem_u32(&Bs[0][0]);
    const unsigned sB1 = smem_u32(&Bs[1][0]);

    const int aid0 = tid, aid1 = tid + 256;
    const int ar0 = aid0 >> 2, ac0 = (aid0 & 3) * 8;
    const int ar1 = aid1 >> 2, ac1 = (aid1 & 3) * 8;
    const int br  = tid >> 2,  bc  = (tid & 3) * 8;

    auto issue = [&](int buf, int ch){
        int pass = ch >> 4;
        int k0   = (ch & 15) * 32;
        unsigned sa = buf ? sA1 : sA0;
        unsigned sb = buf ? sB1 : sB0;
        const __nv_bfloat16* a = Ap[pass] + k0;
        const __nv_bfloat16* bsrc = Bp[pass] + k0;
        cpa16(sa + (unsigned)(ar0*VK_STR + ac0)*2, a + (size_t)ar0*HH + ac0);
        cpa16(sa + (unsigned)(ar1*VK_STR + ac1)*2, a + (size_t)ar1*HH + ac1);
        cpa16(sb + (unsigned)(br *VK_STR + bc )*2, bsrc + (size_t)br*HH + bc);
    };

    float acc[2][4][4];
    #pragma unroll
    for (int mi=0;mi<2;mi++)
        #pragma unroll
        for (int ni=0;ni<4;ni++)
            #pragma unroll
            for (int q=0;q<4;q++) acc[mi][ni][q]=0.f;

    const int m0 = (wid & 3) * 32;
    const int n0 = (wid >> 2) * 32;

    const int arow  = (lane & 7) + ((lane >> 3) & 1) * 8;
    const int akoff = (lane >> 4) * 8;
    const int brow  = (lane & 7) + ((lane >> 4) & 1) * 8;
    const int bkoff = ((lane >> 3) & 1) * 8;

    issue(0, 0); CP_COMMIT();

    const int NCH = 48;
    for (int ch = 0; ch < NCH; ch++){
        int buf = ch & 1;
        if (ch + 1 < NCH){ issue(buf ^ 1, ch + 1); CP_COMMIT(); CP_WAIT(1); }
        else             { CP_WAIT(0); }
        __syncthreads();

        unsigned sa = buf ? sA1 : sA0;
        unsigned sb = buf ? sB1 : sB0;
        #pragma unroll
        for (int ks = 0; ks < 32; ks += 16){
            unsigned af[2][4], bf[2][4];
            #pragma unroll
            for (int mi=0;mi<2;mi++)
                ldmx4(af[mi], sa + (unsigned)((m0 + mi*16 + arow)*VK_STR + ks + akoff)*2);
            #pragma unroll
            for (int g=0; g<2; g++)
                ldmx4(bf[g], sb + (unsigned)((n0 + g*16 + brow)*VK_STR + ks + bkoff)*2);
            #pragma unroll
            for (int mi=0;mi<2;mi++)
                #pragma unroll
                for (int ni=0;ni<4;ni++)
                    mma16816(acc[mi][ni], af[mi], bf[ni>>1][(ni&1)*2], bf[ni>>1][(ni&1)*2+1]);
        }
        __syncthreads();
    }

    #pragma unroll
    for (int mi=0;mi<2;mi++){
        #pragma unroll
        for (int ni=0;ni<4;ni++){
            int row = mtile*128 + m0 + mi*16 + (lane >> 2);
            int col = ntile*64  + n0 + ni*8  + (lane & 3)*2;
            float bia0 = b_o[col], bia1 = b_o[col+1];
            if (row < T1*BB){
                float* o = logits + (size_t)row*VV + col;
                o[0] = acc[mi][ni][0] + bia0;
                o[1] = acc[mi][ni][1] + bia1;
            }
            if (row + 8 < T1*BB){
                float* o = logits + (size_t)(row+8)*VV + col;
                o[0] = acc[mi][ni][2] + bia0;
                o[1] = acc[mi][ni][3] + bia1;
            }
        }
    }
}

// ---------------------------------------------------------------------------
// Online log-softmax + argmax
// ---------------------------------------------------------------------------
__global__ void k_lsm(float* __restrict__ logits)
{
    __shared__ float ms[256], ss[256];
    __shared__ int   ii[256];
    const int row = blockIdx.x;
    const int tid = threadIdx.x;
    float* x = logits + (size_t)row * VV;

    float m = x[tid]; float s = 1.f; int mi = tid;
    for (int c = tid + 256; c < VV; c += 256){
        float v = x[c];
        if (v > m){ s = s*fexp(m - v) + 1.f; m = v; mi = c; }
        else       s += fexp(v - m);
    }
    ms[tid]=m; ss[tid]=s; ii[tid]=mi;
    __syncthreads();
    for (int st = 128; st > 0; st >>= 1){
        if (tid < st){
            float m1=ms[tid], s1=ss[tid]; int i1=ii[tid];
            float m2=ms[tid+st], s2=ss[tid+st]; int i2=ii[tid+st];
            if (m2 > m1)      { ms[tid]=m2; ss[tid]=s1*fexp(m1-m2)+s2; ii[tid]=i2; }
            else if (m2 < m1) { ss[tid]=s1+s2*fexp(m2-m1); }
            else              { ss[tid]=s1+s2; ii[tid]=min(i1,i2); }
        }
        __syncthreads();
    }
    float lse = ms[0] + logf(ss[0]);
    if (tid == 0) g_argmax[row] = ii[0];
    for (int c = tid; c < VV; c += 256) x[c] -= lse;
}

__global__ void k_tail_f(float* __restrict__ out)
{
    int r = blockIdx.x*blockDim.x + threadIdx.x;
    if (r < T1*BB) out[TBV + r] = (float)g_argmax[r];
}
__global__ void k_tail_i(int* __restrict__ out)
{
    int r = blockIdx.x*blockDim.x + threadIdx.x;
    if (r < T1*BB) out[r] = g_argmax[r];
}

// ---------------------------------------------------------------------------
extern "C" void kernel_launch(void* const* d_in, const int* in_sizes, int n_in,
                              void* d_out, int out_size)
{
    const int*   tgt   = (const int*)  d_in[0];
    const int*   lens  = (const int*)  d_in[1];
    const float* enc   = (const float*)d_in[2];
    const float* h0    = (const float*)d_in[3];
    const float* c0    = (const float*)d_in[4];
    const float* emb   = (const float*)d_in[5];
    const float* W_ih  = (const float*)d_in[6];
    const float* W_hh  = (const float*)d_in[7];
    const float* b_ih  = (const float*)d_in[8];
    const float* b_hh  = (const float*)d_in[9];
    const float* W_a   = (const float*)d_in[10];
    const float* W_c   = (const float*)d_in[11];
    const float* b_c   = (const float*)d_in[12];
    const float* W_o   = (const float*)d_in[13];
    const float* b_o   = (const float*)d_in[14];

    float *p_proj=nullptr, *p_lg=nullptr;
    cudaGetSymbolAddress((void**)&p_proj, g_proj);
    cudaGetSymbolAddress((void**)&p_lg,   g_logits);

    const bool big = (size_t)out_size >= TBV;
    float* logits = big ? (float*)d_out : p_lg;

    cudaFuncSetAttribute(k_loop, cudaFuncAttributeMaxDynamicSharedMemorySize, 131072);

    // prologue
    k_prep0<<<64, 256>>>(h0, c0, tgt, emb);
    k_convW<<<(int)(((size_t)VV*HH/4 + 255)/256), 256>>>(W_o);
    k_convG<<<(int)(((size_t)JG*KX/4 + 255)/256), 256>>>(W_ih, W_hh);
    sgemm<64,64,16,4,4><<<dim3(512/64, 2048/64), 256>>>(
        enc, W_a, p_proj, BB*SS, HH, HH);

    // persistent recurrent loop (barrier counter reset first)
    k_rst<<<1, 1>>>();
    k_loop<<<NCTA, 256, 131072>>>(b_ih, b_hh, lens, enc, W_c, b_c, tgt, emb);

    // vocab projection + log-softmax
    k_vocab<<<dim3(8, 500), 256>>>(b_o, logits);
    k_lsm<<<T1*BB, 256>>>(logits);

    if (big && (size_t)out_size >= TBV + (size_t)T1*BB) {
        k_tail_f<<<4, 256>>>((float*)d_out);
    } else if (!big) {
        k_tail_i<<<4, 256>>>((int*)d_out);
    }
}

// round 7
// speedup vs baseline: 1.1897x; 1.1897x over previous
#include <cuda_runtime.h>
#include <cuda_bf16.h>
#include <math.h>

// Problem constants
#define BB 32
#define TT 32
#define SS 64
#define HH 512
#define EE 512
#define VV 32000
#define T1 (TT-1)
#define TBV ((size_t)T1*BB*VV)
#define BH (BB*HH)
#define MPAD 1024
#define KX 1536
#define JG 2048
#define GZ 8

// -------- persistent device scratch --------
__device__ float g_h[BH];
__device__ float g_c[BH];
__device__ float g_proj[BB*SS*HH];
__device__ __align__(16) float g_XC[BB*1024];
__device__ float g_Gpart[GZ*BB*JG];
__device__ int   g_argmax[T1*BB];
__device__ float g_logits[T1*BB*VV];
__device__ __align__(16) __nv_bfloat16 g_Wh[(size_t)VV*HH];
__device__ __align__(16) __nv_bfloat16 g_Wl[(size_t)VV*HH];
__device__ __align__(16) __nv_bfloat16 g_Ah[MPAD*HH];   // rows 992..1023 stay 0
__device__ __align__(16) __nv_bfloat16 g_Al[MPAD*HH];
__device__ __align__(16) __nv_bfloat16 g_gWh[JG*KX];
__device__ __align__(16) __nv_bfloat16 g_gWl[JG*KX];
__device__ __align__(16) __nv_bfloat16 g_Xh[BB*KX];
__device__ __align__(16) __nv_bfloat16 g_Xl[BB*KX];

__device__ __forceinline__ float sigf(float x){ return 1.0f/(1.0f+expf(-x)); }

__device__ __forceinline__ float fexp(float x){
    float t = x * 1.4426950408889634f;
    float n = rintf(t);
    float f = t - n;
    float p = 1.5403530e-4f;
    p = fmaf(p, f, 1.3333558e-3f);
    p = fmaf(p, f, 9.6181291e-3f);
    p = fmaf(p, f, 5.5504109e-2f);
    p = fmaf(p, f, 2.4022651e-1f);
    p = fmaf(p, f, 6.9314718e-1f);
    p = fmaf(p, f, 1.0f);
    int e = (int)n;
    e = e < -126 ? -126 : (e > 127 ? 127 : e);
    float sc = __int_as_float((e+127)<<23);
    return p*sc;
}

// ------------------ low-level helpers ------------------
__device__ __forceinline__ unsigned smem_u32(const void* p){
    unsigned a;
    asm("{ .reg .u64 t; cvta.to.shared.u64 t, %1; cvt.u32.u64 %0, t; }" : "=r"(a) : "l"(p));
    return a;
}
__device__ __forceinline__ void cpa16(unsigned dst, const void* src){
    asm volatile("cp.async.cg.shared.global [%0], [%1], 16;" :: "r"(dst), "l"(src));
}
#define CP_COMMIT() asm volatile("cp.async.commit_group;" ::: "memory")
#define CP_WAIT(n)  asm volatile("cp.async.wait_group %0;" :: "n"(n) : "memory")

__device__ __forceinline__ void ldmx4(unsigned* r, unsigned addr){
    asm volatile("ldmatrix.sync.aligned.m8n8.x4.shared.b16 {%0,%1,%2,%3}, [%4];"
        : "=r"(r[0]), "=r"(r[1]), "=r"(r[2]), "=r"(r[3]) : "r"(addr));
}
__device__ __forceinline__ void mma16816(float* d, const unsigned* a,
                                         unsigned b0, unsigned b1){
    asm volatile(
        "mma.sync.aligned.m16n8k16.row.col.f32.bf16.bf16.f32 "
        "{%0,%1,%2,%3}, {%4,%5,%6,%7}, {%8,%9}, {%0,%1,%2,%3};"
        : "+f"(d[0]), "+f"(d[1]), "+f"(d[2]), "+f"(d[3])
        : "r"(a[0]), "r"(a[1]), "r"(a[2]), "r"(a[3]), "r"(b0), "r"(b1));
}
__device__ __forceinline__ void bsplit(float v, __nv_bfloat16& hi, __nv_bfloat16& lo){
    hi = __float2bfloat16(v);
    lo = __float2bfloat16(v - __bfloat162float(hi));
}

// ---------------------------------------------------------------------------
// Generic tiled SGEMM (proj precompute). Now 128x64 tile, TM=8, TN=4.
// ---------------------------------------------------------------------------
template<int BM,int BN,int BK,int TM,int TN>
__global__ void sgemm(const float* __restrict__ A, const float* __restrict__ B,
                      float* __restrict__ C, int M, int N, int K)
{
    constexpr int THREADS = (BM/TM)*(BN/TN);
    static_assert(THREADS == 256, "256 threads expected");
    __shared__ float As[BK][BM+4];
    __shared__ float Bs[BK][BN+4];
    const int tid = threadIdx.x;
    const int bm = blockIdx.y*BM, bn = blockIdx.x*BN;
    const int tx = tid % (BN/TN);
    const int ty = tid / (BN/TN);
    float acc[TM][TN];
    #pragma unroll
    for (int i=0;i<TM;i++)
        #pragma unroll
        for (int j=0;j<TN;j++) acc[i][j]=0.f;

    for (int k0 = 0; k0 < K; k0 += BK) {
        #pragma unroll
        for (int i=0;i<(BM*BK)/THREADS;i++){
            int idx = tid + i*THREADS; int m = idx/BK, k = idx%BK;
            As[k][m] = A[(size_t)(bm+m)*K + k0 + k];
        }
        #pragma unroll
        for (int i=0;i<(BN*BK)/THREADS;i++){
            int idx = tid + i*THREADS; int n = idx/BK, k = idx%BK;
            Bs[k][n] = B[(size_t)(bn+n)*K + k0 + k];
        }
        __syncthreads();
        #pragma unroll
        for (int kk=0;kk<BK;kk++){
            float a[TM], b[TN];
            #pragma unroll
            for (int i=0;i<TM;i++) a[i] = As[kk][ty*TM+i];
            #pragma unroll
            for (int j=0;j<TN;j++) b[j] = Bs[kk][tx*TN+j];
            #pragma unroll
            for (int i=0;i<TM;i++)
                #pragma unroll
                for (int j=0;j<TN;j++) acc[i][j] += a[i]*b[j];
        }
        __syncthreads();
    }
    #pragma unroll
    for (int i=0;i<TM;i++){
        int gm = bm + ty*TM + i;
        #pragma unroll
        for (int j=0;j<TN;j++)
            C[(size_t)gm*N + bn + tx*TN + j] = acc[i][j];
    }
}

// ---------------------------------------------------------------------------
// Prologue: h,c init + assemble X for step 0
// ---------------------------------------------------------------------------
__global__ void k_prep0(const float* __restrict__ h0, const float* __restrict__ c0,
                        const int* __restrict__ tgt, const float* __restrict__ emb)
{
    int idx = blockIdx.x*256 + threadIdx.x;
    int b = idx >> 9, k = idx & 511;
    g_h[idx] = h0[idx];
    g_c[idx] = c0[idx];
    __nv_bfloat16 hi, lo;
    int w = tgt[b*TT + 0];
    bsplit(emb[(size_t)w*EE + k], hi, lo);
    g_Xh[b*KX + k] = hi;  g_Xl[b*KX + k] = lo;
    g_Xh[b*KX + 512 + k] = __float2bfloat16(0.f);
    g_Xl[b*KX + 512 + k] = __float2bfloat16(0.f);
    bsplit(h0[idx], hi, lo);
    g_Xh[b*KX + 1024 + k] = hi;  g_Xl[b*KX + 1024 + k] = lo;
}

__global__ void k_convG(const float* __restrict__ W_ih, const float* __restrict__ W_hh)
{
    size_t i = ((size_t)blockIdx.x*256 + threadIdx.x)*4;
    if (i >= (size_t)JG*KX) return;
    int j = (int)(i / KX);
    int k = (int)(i % KX);
    float4 v = (k < 1024) ? *(const float4*)(W_ih + (size_t)j*1024 + k)
                          : *(const float4*)(W_hh + (size_t)j*512 + (k-1024));
    __nv_bfloat16 h, l;
    bsplit(v.x, h, l); g_gWh[i+0]=h; g_gWl[i+0]=l;
    bsplit(v.y, h, l); g_gWh[i+1]=h; g_gWl[i+1]=l;
    bsplit(v.z, h, l); g_gWh[i+2]=h; g_gWl[i+2]=l;
    bsplit(v.w, h, l); g_gWh[i+3]=h; g_gWl[i+3]=l;
}

// ---------------------------------------------------------------------------
// Gates GEMM via HMMA, 3-term, double-buffered cp.async.
// grid (16 ntiles, 8 z), 256 threads, dynamic smem 2x46080.
// ---------------------------------------------------------------------------
#define GSTR 72
#define ABUF 46080

__global__ void __launch_bounds__(256)
k_gmma()
{
    extern __shared__ char dsm[];
    const int tid  = threadIdx.x;
    const int w = tid >> 5, l = tid & 31;
    const int nt   = blockIdx.x;
    const int z    = blockIdx.y;
    const int nbase = nt * 128;
    const int kbase = z * 192;
    const unsigned base = smem_u32(dsm);

    const int n0 = w * 16;
    const int arow  = (l & 7) + ((l >> 3) & 1) * 8;
    const int akoff = (l >> 4) * 8;
    const int brow  = (l & 7) + ((l >> 4) & 1) * 8;
    const int bkoff = ((l >> 3) & 1) * 8;

    auto issue = [&](int buf, int ck){
        const int koff = kbase + ck*64;
        const unsigned uAh = base + buf*ABUF;
        const unsigned uAl = uAh + 4608;
        const unsigned uBh = uAh + 9216;
        const unsigned uBl = uAh + 27648;
        #pragma unroll
        for (int q = 0; q < 10; q++){
            int i = q*256 + tid;
            if (i < 512){
                int idx = i & 255; int row = idx >> 3, c8 = idx & 7;
                const __nv_bfloat16* src = (i < 256 ? g_Xh : g_Xl)
                                           + (size_t)row*KX + koff + c8*8;
                unsigned dst = (i < 256 ? uAh : uAl) + (unsigned)(row*GSTR + c8*8)*2;
                cpa16(dst, src);
            } else {
                int idx = (i - 512) & 1023; int row = idx >> 3, c8 = idx & 7;
                const __nv_bfloat16* src = (i < 1536 ? g_gWh : g_gWl)
                                           + (size_t)(nbase+row)*KX + koff + c8*8;
                unsigned dst = (i < 1536 ? uBh : uBl) + (unsigned)(row*GSTR + c8*8)*2;
                cpa16(dst, src);
            }
        }
    };

    float acc[2][2][4];
    #pragma unroll
    for (int mi=0;mi<2;mi++)
        #pragma unroll
        for (int ni=0;ni<2;ni++)
            #pragma unroll
            for (int q=0;q<4;q++) acc[mi][ni][q]=0.f;

    issue(0, 0); CP_COMMIT();

    for (int ck = 0; ck < 3; ck++){
        int buf = ck & 1;
        if (ck < 2){ issue(buf ^ 1, ck + 1); CP_COMMIT(); CP_WAIT(1); }
        else       { CP_WAIT(0); }
        __syncthreads();

        const unsigned uAh = base + buf*ABUF;
        const unsigned uAl = uAh + 4608;
        const unsigned uBh = uAh + 9216;
        const unsigned uBl = uAh + 27648;
        #pragma unroll
        for (int ks = 0; ks < 64; ks += 16){
            unsigned afh[2][4], afl[2][4], bfh[4], bfl[4];
            #pragma unroll
            for (int mi=0;mi<2;mi++){
                ldmx4(afh[mi], uAh + (unsigned)((mi*16 + arow)*GSTR + ks + akoff)*2);
                ldmx4(afl[mi], uAl + (unsigned)((mi*16 + arow)*GSTR + ks + akoff)*2);
            }
            ldmx4(bfh, uBh + (unsigned)((n0 + brow)*GSTR + ks + bkoff)*2);
            ldmx4(bfl, uBl + (unsigned)((n0 + brow)*GSTR + ks + bkoff)*2);
            #pragma unroll
            for (int mi=0;mi<2;mi++)
                #pragma unroll
                for (int ni=0;ni<2;ni++){
                    mma16816(acc[mi][ni], afh[mi], bfh[ni*2], bfh[ni*2+1]);
                    mma16816(acc[mi][ni], afh[mi], bfl[ni*2], bfl[ni*2+1]);
                    mma16816(acc[mi][ni], afl[mi], bfh[ni*2], bfh[ni*2+1]);
                }
        }
        __syncthreads();
    }

    #pragma unroll
    for (int mi=0;mi<2;mi++){
        #pragma unroll
        for (int ni=0;ni<2;ni++){
            int row = mi*16 + (l >> 2);
            int col = nbase + n0 + ni*8 + (l & 3)*2;
            float* gp = g_Gpart + ((size_t)z*BB + row)*JG + col;
            gp[0] = acc[mi][ni][0];
            gp[1] = acc[mi][ni][1];
            gp += 8*JG;
            gp[0] = acc[mi][ni][2];
            gp[1] = acc[mi][ni][3];
        }
    }
}

// ---------------------------------------------------------------------------
// Fused LSTM cell + attention. 32 blocks x 512 threads. (proven R5)
// ---------------------------------------------------------------------------
__global__ void k_cell_attn(const float* __restrict__ b_ih, const float* __restrict__ b_hh,
                            const int* __restrict__ lens, const float* __restrict__ enc)
{
    __shared__ float hh[HH];
    __shared__ float sc[SS];
    const int b   = blockIdx.x;
    const int tid = threadIdx.x;
    const int len = lens[b];
    const int w = tid >> 5, l = tid & 31;

    float gv[4];
    #pragma unroll
    for (int q=0;q<4;q++){
        int j = q*HH + tid;
        float s = b_ih[j] + b_hh[j];
        #pragma unroll
        for (int z=0;z<GZ;z++) s += g_Gpart[((size_t)z*BB + b)*JG + j];
        gv[q] = s;
    }
    int idx = b*HH + tid;
    float ig = sigf(gv[0]);
    float fg = sigf(gv[1]);
    float gg = tanhf(gv[2]);
    float og = sigf(gv[3]);
    float c  = fg * g_c[idx] + ig * gg;
    g_c[idx] = c;
    float h2 = og * tanhf(c);
    g_h[idx] = h2;
    hh[tid] = h2;
    g_XC[b*1024 + tid] = h2;
    {
        __nv_bfloat16 hi, lo; bsplit(h2, hi, lo);
        g_Xh[b*KX + 1024 + tid] = hi;
        g_Xl[b*KX + 1024 + tid] = lo;
    }
    __syncthreads();

    for (int s = w; s < SS; s += 16) {
        const float* pr = &g_proj[((size_t)s*BB + b)*HH];
        float sum = 0.f;
        for (int k = l; k < HH; k += 32) sum += hh[k] * pr[k];
        #pragma unroll
        for (int off=16; off>0; off>>=1) sum += __shfl_xor_sync(0xffffffffu, sum, off);
        if (l == 0) sc[s] = (s < len) ? sum : -1e9f;
    }
    __syncthreads();

    if (tid < 32) {
        float v0 = sc[tid], v1 = sc[tid+32];
        float m = fmaxf(v0, v1);
        #pragma unroll
        for (int off=16; off>0; off>>=1) m = fmaxf(m, __shfl_xor_sync(0xffffffffu, m, off));
        float e0 = expf(v0 - m), e1 = expf(v1 - m);
        float s = e0 + e1;
        #pragma unroll
        for (int off=16; off>0; off>>=1) s += __shfl_xor_sync(0xffffffffu, s, off);
        float inv = 1.0f / s;
        sc[tid]    = e0 * inv;
        sc[tid+32] = e1 * inv;
    }
    __syncthreads();

    float acc = 0.f;
    #pragma unroll 4
    for (int s = 0; s < SS; s++)
        acc += sc[s] * enc[((size_t)s*BB + b)*HH + tid];
    g_XC[b*1024 + 512 + tid] = acc;
}

// ---------------------------------------------------------------------------
// ah2 (proven R5): W_c rows in registers, XC staged in 128KB smem
// ---------------------------------------------------------------------------
__global__ void __launch_bounds__(256)
k_ah2x(const float* __restrict__ W_c, const float* __restrict__ b_c,
       const int* __restrict__ tgt, const float* __restrict__ emb, int t)
{
    extern __shared__ float xc[];
    const int tid = threadIdx.x;
    const int w = tid >> 5, l = tid & 31;
    const int nt = blockIdx.x;

    if (t < T1-1){
        int b2 = nt >> 1;
        int k2 = (nt & 1)*256 + tid;
        int wd = tgt[b2*TT + (t+1)];
        __nv_bfloat16 hi, lo;
        bsplit(emb[(size_t)wd*EE + k2], hi, lo);
        g_Xh[b2*KX + k2] = hi;
        g_Xl[b2*KX + k2] = lo;
    }

    {
        const float4* src = (const float4*)g_XC;
        float4* dst = (float4*)xc;
        for (int i = tid; i < 8192; i += 256) dst[i] = src[i];
    }
    __syncthreads();

    const int c = nt*8 + w;
    const float* wr = W_c + (size_t)c*1024;
    float wreg[32];
    #pragma unroll
    for (int q=0;q<32;q++) wreg[q] = wr[l + q*32];
    float bias = b_c[c];

    for (int b = 0; b < BB; b++){
        const float* xb = xc + b*1024;
        float s = 0.f;
        #pragma unroll
        for (int q=0;q<32;q++) s += wreg[q] * xb[l + q*32];
        #pragma unroll
        for (int off=16; off>0; off>>=1) s += __shfl_xor_sync(0xffffffffu, s, off);
        if (l == 0){
            float v = tanhf(s + bias);
            __nv_bfloat16 hi, lo; bsplit(v, hi, lo);
            int r = t*BB + b;
            g_Ah[(size_t)r*HH + c] = hi;
            g_Al[(size_t)r*HH + c] = lo;
            g_Xh[b*KX + 512 + c] = hi;
            g_Xl[b*KX + 512 + c] = lo;
        }
    }
}

// ---------------------------------------------------------------------------
// bf16 split of W_o
// ---------------------------------------------------------------------------
__global__ void k_convW(const float* __restrict__ W)
{
    size_t i = ((size_t)blockIdx.x*256 + threadIdx.x)*4;
    if (i >= (size_t)VV*HH) return;
    float4 v = *(const float4*)(W + i);
    __nv_bfloat16 h0, h1, h2, h3, l0, l1, l2, l3;
    bsplit(v.x, h0, l0); bsplit(v.y, h1, l1);
    bsplit(v.z, h2, l2); bsplit(v.w, h3, l3);
    *(__nv_bfloat162*)(g_Wh + i)     = __nv_bfloat162(h0, h1);
    *(__nv_bfloat162*)(g_Wh + i + 2) = __nv_bfloat162(h2, h3);
    *(__nv_bfloat162*)(g_Wl + i)     = __nv_bfloat162(l0, l1);
    *(__nv_bfloat162*)(g_Wl + i + 2) = __nv_bfloat162(l2, l3);
}

// ---------------------------------------------------------------------------
// Vocab GEMM, single K-pass with all 3 split-precision terms per chunk.
// B (Wh/Wl) read ONCE per (mtile,ntile). 16 chunks of K=32, double-buffered.
// Dynamic smem 61440B: Ah[2][128*40] Al[2][128*40] Bh[2][64*40] Bl[2][64*40]
// ---------------------------------------------------------------------------
#define VK_STR 40

__global__ void __launch_bounds__(256, 2)
k_vocab(const float* __restrict__ b_o, float* __restrict__ logits)
{
    extern __shared__ char vsm[];
    const int tid  = threadIdx.x;
    const int wid  = tid >> 5, lane = tid & 31;
    const int mtile = blockIdx.x;   // 0..7
    const int ntile = blockIdx.y;   // 0..499

    const __nv_bfloat16* Asrc_h = g_Ah + (size_t)mtile*128*HH;
    const __nv_bfloat16* Asrc_l = g_Al + (size_t)mtile*128*HH;
    const __nv_bfloat16* Bsrc_h = g_Wh + (size_t)ntile*64*HH;
    const __nv_bfloat16* Bsrc_l = g_Wl + (size_t)ntile*64*HH;

    const unsigned base = smem_u32(vsm);
    const unsigned uAh = base;            // 2 x 10240
    const unsigned uAl = base + 20480;    // 2 x 10240
    const unsigned uBh = base + 40960;    // 2 x 5120
    const unsigned uBl = base + 51200;    // 2 x 5120

    auto issue = [&](int buf, int ch){
        const int k0 = ch*32;
        const unsigned a_h = uAh + buf*10240;
        const unsigned a_l = uAl + buf*10240;
        const unsigned b_h = uBh + buf*5120;
        const unsigned b_l = uBl + buf*5120;
        #pragma unroll
        for (int q = 0; q < 6; q++){
            int i = q*256 + tid;
            if (i < 1024){
                int j = i & 511; int r = j >> 2, c8 = (j & 3)*8;
                const __nv_bfloat16* src = (i < 512 ? Asrc_h : Asrc_l)
                                           + (size_t)r*HH + k0 + c8;
                unsigned dst = (i < 512 ? a_h : a_l) + (unsigned)(r*VK_STR + c8)*2;
                cpa16(dst, src);
            } else {
                int j = (i - 1024) & 255; int r = j >> 2, c8 = (j & 3)*8;
                const __nv_bfloat16* src = (i < 1280 ? Bsrc_h : Bsrc_l)
                                           + (size_t)r*HH + k0 + c8;
                unsigned dst = (i < 1280 ? b_h : b_l) + (unsigned)(r*VK_STR + c8)*2;
                cpa16(dst, src);
            }
        }
    };

    float acc[2][4][4];
    #pragma unroll
    for (int mi=0;mi<2;mi++)
        #pragma unroll
        for (int ni=0;ni<4;ni++)
            #pragma unroll
            for (int q=0;q<4;q++) acc[mi][ni][q]=0.f;

    const int m0 = (wid & 3) * 32;
    const int n0 = (wid >> 2) * 32;

    const int arow  = (lane & 7) + ((lane >> 3) & 1) * 8;
    const int akoff = (lane >> 4) * 8;
    const int brow  = (lane & 7) + ((lane >> 4) & 1) * 8;
    const int bkoff = ((lane >> 3) & 1) * 8;

    issue(0, 0); CP_COMMIT();

    const int NCH = 16;
    for (int ch = 0; ch < NCH; ch++){
        int buf = ch & 1;
        if (ch + 1 < NCH){ issue(buf ^ 1, ch + 1); CP_COMMIT(); CP_WAIT(1); }
        else             { CP_WAIT(0); }
        __syncthreads();

        const unsigned a_h = uAh + buf*10240;
        const unsigned a_l = uAl + buf*10240;
        const unsigned b_h = uBh + buf*5120;
        const unsigned b_l = uBl + buf*5120;
        #pragma unroll
        for (int ks = 0; ks < 32; ks += 16){
            unsigned afh[2][4], afl[2][4], bfh[2][4], bfl[2][4];
            #pragma unroll
            for (int mi=0;mi<2;mi++){
                ldmx4(afh[mi], a_h + (unsigned)((m0 + mi*16 + arow)*VK_STR + ks + akoff)*2);
                ldmx4(afl[mi], a_l + (unsigned)((m0 + mi*16 + arow)*VK_STR + ks + akoff)*2);
            }
            #pragma unroll
            for (int g=0; g<2; g++){
                ldmx4(bfh[g], b_h + (unsigned)((n0 + g*16 + brow)*VK_STR + ks + bkoff)*2);
                ldmx4(bfl[g], b_l + (unsigned)((n0 + g*16 + brow)*VK_STR + ks + bkoff)*2);
            }
            #pragma unroll
            for (int mi=0;mi<2;mi++)
                #pragma unroll
                for (int ni=0;ni<4;ni++){
                    unsigned h0 = bfh[ni>>1][(ni&1)*2], h1 = bfh[ni>>1][(ni&1)*2+1];
                    unsigned l0 = bfl[ni>>1][(ni&1)*2], l1 = bfl[ni>>1][(ni&1)*2+1];
                    mma16816(acc[mi][ni], afh[mi], h0, h1);
                    mma16816(acc[mi][ni], afh[mi], l0, l1);
                    mma16816(acc[mi][ni], afl[mi], h0, h1);
                }
        }
        __syncthreads();
    }

    #pragma unroll
    for (int mi=0;mi<2;mi++){
        #pragma unroll
        for (int ni=0;ni<4;ni++){
            int row = mtile*128 + m0 + mi*16 + (lane >> 2);
            int col = ntile*64  + n0 + ni*8  + (lane & 3)*2;
            float bia0 = b_o[col], bia1 = b_o[col+1];
            if (row < T1*BB){
                float* o = logits + (size_t)row*VV + col;
                o[0] = acc[mi][ni][0] + bia0;
                o[1] = acc[mi][ni][1] + bia1;
            }
            if (row + 8 < T1*BB){
                float* o = logits + (size_t)(row+8)*VV + col;
                o[0] = acc[mi][ni][2] + bia0;
                o[1] = acc[mi][ni][3] + bia1;
            }
        }
    }
}

// ---------------------------------------------------------------------------
// Online log-softmax + argmax
// ---------------------------------------------------------------------------
__global__ void k_lsm(float* __restrict__ logits)
{
    __shared__ float ms[256], ss[256];
    __shared__ int   ii[256];
    const int row = blockIdx.x;
    const int tid = threadIdx.x;
    float* x = logits + (size_t)row * VV;

    float m = x[tid]; float s = 1.f; int mi = tid;
    for (int c = tid + 256; c < VV; c += 256){
        float v = x[c];
        if (v > m){ s = s*fexp(m - v) + 1.f; m = v; mi = c; }
        else       s += fexp(v - m);
    }
    ms[tid]=m; ss[tid]=s; ii[tid]=mi;
    __syncthreads();
    for (int st = 128; st > 0; st >>= 1){
        if (tid < st){
            float m1=ms[tid], s1=ss[tid]; int i1=ii[tid];
            float m2=ms[tid+st], s2=ss[tid+st]; int i2=ii[tid+st];
            if (m2 > m1)      { ms[tid]=m2; ss[tid]=s1*fexp(m1-m2)+s2; ii[tid]=i2; }
            else if (m2 < m1) { ss[tid]=s1+s2*fexp(m2-m1); }
            else              { ss[tid]=s1+s2; ii[tid]=min(i1,i2); }
        }
        __syncthreads();
    }
    float lse = ms[0] + logf(ss[0]);
    if (tid == 0) g_argmax[row] = ii[0];
    for (int c = tid; c < VV; c += 256) x[c] -= lse;
}

__global__ void k_tail_f(float* __restrict__ out)
{
    int r = blockIdx.x*blockDim.x + threadIdx.x;
    if (r < T1*BB) out[TBV + r] = (float)g_argmax[r];
}
__global__ void k_tail_i(int* __restrict__ out)
{
    int r = blockIdx.x*blockDim.x + threadIdx.x;
    if (r < T1*BB) out[r] = g_argmax[r];
}

// ---------------------------------------------------------------------------
extern "C" void kernel_launch(void* const* d_in, const int* in_sizes, int n_in,
                              void* d_out, int out_size)
{
    const int*   tgt   = (const int*)  d_in[0];
    const int*   lens  = (const int*)  d_in[1];
    const float* enc   = (const float*)d_in[2];
    const float* h0    = (const float*)d_in[3];
    const float* c0    = (const float*)d_in[4];
    const float* emb   = (const float*)d_in[5];
    const float* W_ih  = (const float*)d_in[6];
    const float* W_hh  = (const float*)d_in[7];
    const float* b_ih  = (const float*)d_in[8];
    const float* b_hh  = (const float*)d_in[9];
    const float* W_a   = (const float*)d_in[10];
    const float* W_c   = (const float*)d_in[11];
    const float* b_c   = (const float*)d_in[12];
    const float* W_o   = (const float*)d_in[13];
    const float* b_o   = (const float*)d_in[14];

    float *p_proj=nullptr, *p_lg=nullptr;
    cudaGetSymbolAddress((void**)&p_proj, g_proj);
    cudaGetSymbolAddress((void**)&p_lg,   g_logits);

    const bool big = (size_t)out_size >= TBV;
    float* logits = big ? (float*)d_out : p_lg;

    cudaFuncSetAttribute(k_gmma,  cudaFuncAttributeMaxDynamicSharedMemorySize, 2*ABUF);
    cudaFuncSetAttribute(k_ah2x,  cudaFuncAttributeMaxDynamicSharedMemorySize, 131072);
    cudaFuncSetAttribute(k_vocab, cudaFuncAttributeMaxDynamicSharedMemorySize, 61440);

    // prologue
    k_prep0<<<64, 256>>>(h0, c0, tgt, emb);
    k_convW<<<(int)(((size_t)VV*HH/4 + 255)/256), 256>>>(W_o);
    k_convG<<<(int)(((size_t)JG*KX/4 + 255)/256), 256>>>(W_ih, W_hh);
    // proj = enc @ W_a^T : [2048, 512], 128x64 tiles, grid (8,16)=128 CTAs
    sgemm<128,64,16,8,4><<<dim3(512/64, 2048/128), 256>>>(
        enc, W_a, p_proj, BB*SS, HH, HH);

    // 31 recurrent steps
    for (int t = 0; t < T1; t++) {
        k_gmma<<<dim3(16, GZ), 256, 2*ABUF>>>();
        k_cell_attn<<<BB, HH>>>(b_ih, b_hh, lens, enc);
        k_ah2x<<<64, 256, 131072>>>(W_c, b_c, tgt, emb, t);
    }

    // vocab projection + log-softmax
    k_vocab<<<dim3(8, 500), 256, 61440>>>(b_o, logits);
    k_lsm<<<T1*BB, 256>>>(logits);

    if (big && (size_t)out_size >= TBV + (size_t)T1*BB) {
        k_tail_f<<<4, 256>>>((float*)d_out);
    } else if (!big) {
        k_tail_i<<<4, 256>>>((int*)d_out);
    }
}

// round 8
// speedup vs baseline: 1.2358x; 1.0388x over previous
#include <cuda_runtime.h>
#include <cuda_bf16.h>
#include <math.h>

// Problem constants
#define BB 32
#define TT 32
#define SS 64
#define HH 512
#define EE 512
#define VV 32000
#define T1 (TT-1)
#define TBV ((size_t)T1*BB*VV)
#define BH (BB*HH)
#define MPAD 1024
#define KX 1536
#define JG 2048
#define GZ 8
#define NCTA 128

// -------- persistent device scratch --------
__device__ float g_h[BH];
__device__ float g_c[BH];
__device__ float g_proj[BB*SS*HH];
__device__ __align__(16) float g_XC[BB*1024];
__device__ float g_Gpart[GZ*BB*JG];
__device__ int   g_argmax[T1*BB];
__device__ float g_logits[T1*BB*VV];
__device__ __align__(16) __nv_bfloat16 g_Wh[(size_t)VV*HH];
__device__ __align__(16) __nv_bfloat16 g_Wl[(size_t)VV*HH];
__device__ __align__(16) __nv_bfloat16 g_Ah[MPAD*HH];   // rows 992..1023 stay 0
__device__ __align__(16) __nv_bfloat16 g_Al[MPAD*HH];
__device__ __align__(16) __nv_bfloat16 g_gWh[JG*KX];
__device__ __align__(16) __nv_bfloat16 g_gWl[JG*KX];
__device__ __align__(16) __nv_bfloat16 g_Xh[BB*KX];
__device__ __align__(16) __nv_bfloat16 g_Xl[BB*KX];
__device__ unsigned g_barcnt;

__device__ __forceinline__ float sigf(float x){ return 1.0f/(1.0f+expf(-x)); }

__device__ __forceinline__ float fexp(float x){
    float t = x * 1.4426950408889634f;
    float n = rintf(t);
    float f = t - n;
    float p = 1.5403530e-4f;
    p = fmaf(p, f, 1.3333558e-3f);
    p = fmaf(p, f, 9.6181291e-3f);
    p = fmaf(p, f, 5.5504109e-2f);
    p = fmaf(p, f, 2.4022651e-1f);
    p = fmaf(p, f, 6.9314718e-1f);
    p = fmaf(p, f, 1.0f);
    int e = (int)n;
    e = e < -126 ? -126 : (e > 127 ? 127 : e);
    float sc = __int_as_float((e+127)<<23);
    return p*sc;
}

// ------------------ low-level helpers ------------------
__device__ __forceinline__ unsigned smem_u32(const void* p){
    unsigned a;
    asm("{ .reg .u64 t; cvta.to.shared.u64 t, %1; cvt.u32.u64 %0, t; }" : "=r"(a) : "l"(p));
    return a;
}
__device__ __forceinline__ void cpa16(unsigned dst, const void* src){
    asm volatile("cp.async.cg.shared.global [%0], [%1], 16;" :: "r"(dst), "l"(src));
}
#define CP_COMMIT() asm volatile("cp.async.commit_group;" ::: "memory")
#define CP_WAIT(n)  asm volatile("cp.async.wait_group %0;" :: "n"(n) : "memory")

__device__ __forceinline__ void ldmx4(unsigned* r, unsigned addr){
    asm volatile("ldmatrix.sync.aligned.m8n8.x4.shared.b16 {%0,%1,%2,%3}, [%4];"
        : "=r"(r[0]), "=r"(r[1]), "=r"(r[2]), "=r"(r[3]) : "r"(addr));
}
__device__ __forceinline__ void mma16816(float* d, const unsigned* a,
                                         unsigned b0, unsigned b1){
    asm volatile(
        "mma.sync.aligned.m16n8k16.row.col.f32.bf16.bf16.f32 "
        "{%0,%1,%2,%3}, {%4,%5,%6,%7}, {%8,%9}, {%0,%1,%2,%3};"
        : "+f"(d[0]), "+f"(d[1]), "+f"(d[2]), "+f"(d[3])
        : "r"(a[0]), "r"(a[1]), "r"(a[2]), "r"(a[3]), "r"(b0), "r"(b1));
}
__device__ __forceinline__ void bsplit(float v, __nv_bfloat16& hi, __nv_bfloat16& lo){
    hi = __float2bfloat16(v);
    lo = __float2bfloat16(v - __bfloat162float(hi));
}

// pure-spin grid barrier (no nanosleep); counter reset by k_rst pre-launch
__device__ __forceinline__ void gbar(unsigned target){
    __syncthreads();
    if (threadIdx.x == 0){
        __threadfence();
        atomicAdd(&g_barcnt, 1u);
        unsigned v;
        do {
            asm volatile("ld.global.acquire.gpu.b32 %0, [%1];"
                         : "=r"(v) : "l"(&g_barcnt));
        } while (v < target);
    }
    __syncthreads();
}

__global__ void k_rst(){ g_barcnt = 0; }

// ---------------------------------------------------------------------------
// Generic tiled SGEMM (proj precompute)
// ---------------------------------------------------------------------------
template<int BM,int BN,int BK,int TM,int TN>
__global__ void sgemm(const float* __restrict__ A, const float* __restrict__ B,
                      float* __restrict__ C, int M, int N, int K)
{
    constexpr int THREADS = (BM/TM)*(BN/TN);
    static_assert(THREADS == 256, "256 threads expected");
    __shared__ float As[BK][BM+4];
    __shared__ float Bs[BK][BN+4];
    const int tid = threadIdx.x;
    const int bm = blockIdx.y*BM, bn = blockIdx.x*BN;
    const int tx = tid % (BN/TN);
    const int ty = tid / (BN/TN);
    float acc[TM][TN];
    #pragma unroll
    for (int i=0;i<TM;i++)
        #pragma unroll
        for (int j=0;j<TN;j++) acc[i][j]=0.f;

    for (int k0 = 0; k0 < K; k0 += BK) {
        #pragma unroll
        for (int i=0;i<(BM*BK)/THREADS;i++){
            int idx = tid + i*THREADS; int m = idx/BK, k = idx%BK;
            As[k][m] = A[(size_t)(bm+m)*K + k0 + k];
        }
        #pragma unroll
        for (int i=0;i<(BN*BK)/THREADS;i++){
            int idx = tid + i*THREADS; int n = idx/BK, k = idx%BK;
            Bs[k][n] = B[(size_t)(bn+n)*K + k0 + k];
        }
        __syncthreads();
        #pragma unroll
        for (int kk=0;kk<BK;kk++){
            float a[TM], b[TN];
            #pragma unroll
            for (int i=0;i<TM;i++) a[i] = As[kk][ty*TM+i];
            #pragma unroll
            for (int j=0;j<TN;j++) b[j] = Bs[kk][tx*TN+j];
            #pragma unroll
            for (int i=0;i<TM;i++)
                #pragma unroll
                for (int j=0;j<TN;j++) acc[i][j] += a[i]*b[j];
        }
        __syncthreads();
    }
    #pragma unroll
    for (int i=0;i<TM;i++){
        int gm = bm + ty*TM + i;
        #pragma unroll
        for (int j=0;j<TN;j++)
            C[(size_t)gm*N + bn + tx*TN + j] = acc[i][j];
    }
}

// ---------------------------------------------------------------------------
// Prologue: h,c init + assemble X for step 0
// ---------------------------------------------------------------------------
__global__ void k_prep0(const float* __restrict__ h0, const float* __restrict__ c0,
                        const int* __restrict__ tgt, const float* __restrict__ emb)
{
    int idx = blockIdx.x*256 + threadIdx.x;
    int b = idx >> 9, k = idx & 511;
    g_h[idx] = h0[idx];
    g_c[idx] = c0[idx];
    __nv_bfloat16 hi, lo;
    int w = tgt[b*TT + 0];
    bsplit(emb[(size_t)w*EE + k], hi, lo);
    g_Xh[b*KX + k] = hi;  g_Xl[b*KX + k] = lo;
    g_Xh[b*KX + 512 + k] = __float2bfloat16(0.f);
    g_Xl[b*KX + 512 + k] = __float2bfloat16(0.f);
    bsplit(h0[idx], hi, lo);
    g_Xh[b*KX + 1024 + k] = hi;  g_Xl[b*KX + 1024 + k] = lo;
}

__global__ void k_convG(const float* __restrict__ W_ih, const float* __restrict__ W_hh)
{
    size_t i = ((size_t)blockIdx.x*256 + threadIdx.x)*4;
    if (i >= (size_t)JG*KX) return;
    int j = (int)(i / KX);
    int k = (int)(i % KX);
    float4 v = (k < 1024) ? *(const float4*)(W_ih + (size_t)j*1024 + k)
                          : *(const float4*)(W_hh + (size_t)j*512 + (k-1024));
    __nv_bfloat16 h, l;
    bsplit(v.x, h, l); g_gWh[i+0]=h; g_gWl[i+0]=l;
    bsplit(v.y, h, l); g_gWh[i+1]=h; g_gWl[i+1]=l;
    bsplit(v.z, h, l); g_gWh[i+2]=h; g_gWl[i+2]=l;
    bsplit(v.w, h, l); g_gWh[i+3]=h; g_gWl[i+3]=l;
}

// ---------------------------------------------------------------------------
// convW slice (folded into loop idle windows): convert float4 group i4 of W_o
// ---------------------------------------------------------------------------
__device__ __forceinline__ void convW_item(const float* __restrict__ W, unsigned i4)
{
    size_t i = (size_t)i4 * 4;
    float4 v = *(const float4*)(W + i);
    __nv_bfloat16 h0, h1, h2, h3, l0, l1, l2, l3;
    bsplit(v.x, h0, l0); bsplit(v.y, h1, l1);
    bsplit(v.z, h2, l2); bsplit(v.w, h3, l3);
    *(__nv_bfloat162*)(g_Wh + i)     = __nv_bfloat162(h0, h1);
    *(__nv_bfloat162*)(g_Wh + i + 2) = __nv_bfloat162(h2, h3);
    *(__nv_bfloat162*)(g_Wl + i)     = __nv_bfloat162(l0, l1);
    *(__nv_bfloat162*)(g_Wl + i + 2) = __nv_bfloat162(l2, l3);
}
#define WF4 4096000u    // VV*HH/4

// ---------------------------------------------------------------------------
// Persistent recurrent loop: 128 CTAs x 256 threads.
// Phase A: gates HMMA (all CTAs, double-buffered cp.async)
// Phase B: cell+attn (CTAs 0..31) | emb gather + convW (CTAs 64..127)
// Phase C: ah2 (CTAs 0..63) | convW (CTAs 64..127)
// ---------------------------------------------------------------------------
#define GSTR 72
#define ABUF 46080

__global__ void __launch_bounds__(256)
k_loop(const float* __restrict__ b_ih, const float* __restrict__ b_hh,
       const int* __restrict__ lens, const float* __restrict__ enc,
       const float* __restrict__ W_c, const float* __restrict__ b_c,
       const int* __restrict__ tgt, const float* __restrict__ emb,
       const float* __restrict__ W_o)
{
    extern __shared__ char dsm[];
    const int ct  = blockIdx.x;
    const int tid = threadIdx.x;
    const int w = tid >> 5, l = tid & 31;
    const unsigned base = smem_u32(dsm);

    // gates tile assignment
    const int nt = ct & 15;
    const int z  = ct >> 4;
    const int nbase = nt * 128;
    const int kbase = z * 192;
    const int n0 = w * 16;
    const int arow  = (l & 7) + ((l >> 3) & 1) * 8;
    const int akoff = (l >> 4) * 8;
    const int brow  = (l & 7) + ((l >> 4) & 1) * 8;
    const int bkoff = ((l >> 3) & 1) * 8;

    // W_c row for phase C (CTAs 0..63): held in registers for all steps
    float wreg[32];
    float wbias = 0.f;
    if (ct < 64){
        const int c = ct*8 + w;
        const float* wr = W_c + (size_t)c*1024;
        #pragma unroll
        for (int q=0;q<32;q++) wreg[q] = wr[l + q*32];
        wbias = b_c[c];
    }

    unsigned nb = 0;

    for (int t = 0; t < T1; t++){
        // ================= Phase A: gates GEMM (all CTAs) =================
        {
            auto issue = [&](int buf, int ck){
                const int koff = kbase + ck*64;
                const unsigned uAh = base + buf*ABUF;
                const unsigned uAl = uAh + 4608;
                const unsigned uBh = uAh + 9216;
                const unsigned uBl = uAh + 27648;
                #pragma unroll
                for (int q = 0; q < 10; q++){
                    int i = q*256 + tid;
                    if (i < 512){
                        int idx = i & 255; int row = idx >> 3, c8 = idx & 7;
                        const __nv_bfloat16* src = (i < 256 ? g_Xh : g_Xl)
                                                   + (size_t)row*KX + koff + c8*8;
                        unsigned dst = (i < 256 ? uAh : uAl) + (unsigned)(row*GSTR + c8*8)*2;
                        cpa16(dst, src);
                    } else {
                        int idx = (i - 512) & 1023; int row = idx >> 3, c8 = idx & 7;
                        const __nv_bfloat16* src = (i < 1536 ? g_gWh : g_gWl)
                                                   + (size_t)(nbase+row)*KX + koff + c8*8;
                        unsigned dst = (i < 1536 ? uBh : uBl) + (unsigned)(row*GSTR + c8*8)*2;
                        cpa16(dst, src);
                    }
                }
            };

            float acc[2][2][4];
            #pragma unroll
            for (int mi=0;mi<2;mi++)
                #pragma unroll
                for (int ni=0;ni<2;ni++)
                    #pragma unroll
                    for (int q=0;q<4;q++) acc[mi][ni][q]=0.f;

            issue(0, 0); CP_COMMIT();

            for (int ck = 0; ck < 3; ck++){
                int buf = ck & 1;
                if (ck < 2){ issue(buf ^ 1, ck + 1); CP_COMMIT(); CP_WAIT(1); }
                else       { CP_WAIT(0); }
                __syncthreads();

                const unsigned uAh = base + buf*ABUF;
                const unsigned uAl = uAh + 4608;
                const unsigned uBh = uAh + 9216;
                const unsigned uBl = uAh + 27648;
                #pragma unroll
                for (int ks = 0; ks < 64; ks += 16){
                    unsigned afh[2][4], afl[2][4], bfh[4], bfl[4];
                    #pragma unroll
                    for (int mi=0;mi<2;mi++){
                        ldmx4(afh[mi], uAh + (unsigned)((mi*16 + arow)*GSTR + ks + akoff)*2);
                        ldmx4(afl[mi], uAl + (unsigned)((mi*16 + arow)*GSTR + ks + akoff)*2);
                    }
                    ldmx4(bfh, uBh + (unsigned)((n0 + brow)*GSTR + ks + bkoff)*2);
                    ldmx4(bfl, uBl + (unsigned)((n0 + brow)*GSTR + ks + bkoff)*2);
                    #pragma unroll
                    for (int mi=0;mi<2;mi++)
                        #pragma unroll
                        for (int ni=0;ni<2;ni++){
                            mma16816(acc[mi][ni], afh[mi], bfh[ni*2], bfh[ni*2+1]);
                            mma16816(acc[mi][ni], afh[mi], bfl[ni*2], bfl[ni*2+1]);
                            mma16816(acc[mi][ni], afl[mi], bfh[ni*2], bfh[ni*2+1]);
                        }
                }
                __syncthreads();
            }

            #pragma unroll
            for (int mi=0;mi<2;mi++){
                #pragma unroll
                for (int ni=0;ni<2;ni++){
                    int row = mi*16 + (l >> 2);
                    int col = nbase + n0 + ni*8 + (l & 3)*2;
                    float* gp = g_Gpart + ((size_t)z*BB + row)*JG + col;
                    gp[0] = acc[mi][ni][0];
                    gp[1] = acc[mi][ni][1];
                    gp += 8*JG;
                    gp[0] = acc[mi][ni][2];
                    gp[1] = acc[mi][ni][3];
                }
            }
        }
        gbar(++nb * NCTA);

        // ===== Phase B: cell+attn (0..31) | emb gather + convW (64..127) =====
        if (ct < BB){
            const int b = ct;
            float* hh = (float*)dsm;
            float* sc = hh + HH;
            const int len = lens[b];

            #pragma unroll
            for (int rep = 0; rep < 2; rep++){
                int h = tid + rep*256;
                float gv[4];
                #pragma unroll
                for (int q=0;q<4;q++){
                    int j = q*HH + h;
                    float s = b_ih[j] + b_hh[j];
                    #pragma unroll
                    for (int zz=0;zz<GZ;zz++) s += g_Gpart[((size_t)zz*BB + b)*JG + j];
                    gv[q] = s;
                }
                int idx = b*HH + h;
                float ig = sigf(gv[0]);
                float fg = sigf(gv[1]);
                float gg = tanhf(gv[2]);
                float og = sigf(gv[3]);
                float c  = fg * g_c[idx] + ig * gg;
                g_c[idx] = c;
                float h2 = og * tanhf(c);
                g_h[idx] = h2;
                hh[h] = h2;
                g_XC[b*1024 + h] = h2;
                __nv_bfloat16 hi, lo; bsplit(h2, hi, lo);
                g_Xh[b*KX + 1024 + h] = hi;
                g_Xl[b*KX + 1024 + h] = lo;
            }
            __syncthreads();

            #pragma unroll
            for (int i = 0; i < 8; i++){
                int s = w*8 + i;
                const float* pr = &g_proj[((size_t)s*BB + b)*HH];
                float sum = 0.f;
                #pragma unroll
                for (int k = 0; k < 16; k++) sum += hh[l + k*32] * pr[l + k*32];
                #pragma unroll
                for (int off=16; off>0; off>>=1) sum += __shfl_xor_sync(0xffffffffu, sum, off);
                if (l == 0) sc[s] = (s < len) ? sum : -1e9f;
            }
            __syncthreads();

            if (tid < 32){
                float v0 = sc[tid], v1 = sc[tid+32];
                float m = fmaxf(v0, v1);
                #pragma unroll
                for (int off=16; off>0; off>>=1) m = fmaxf(m, __shfl_xor_sync(0xffffffffu, m, off));
                float e0 = expf(v0 - m), e1 = expf(v1 - m);
                float s = e0 + e1;
                #pragma unroll
                for (int off=16; off>0; off>>=1) s += __shfl_xor_sync(0xffffffffu, s, off);
                float inv = 1.0f / s;
                sc[tid]    = e0 * inv;
                sc[tid+32] = e1 * inv;
            }
            __syncthreads();

            #pragma unroll
            for (int rep = 0; rep < 2; rep++){
                int h = tid + rep*256;
                float a0=0.f, a1=0.f, a2=0.f, a3=0.f;
                #pragma unroll 4
                for (int s0 = 0; s0 < 16; s0++){
                    a0 += sc[s0]      * enc[((size_t)(s0)*BB      + b)*HH + h];
                    a1 += sc[s0 + 16] * enc[((size_t)(s0+16)*BB + b)*HH + h];
                    a2 += sc[s0 + 32] * enc[((size_t)(s0+32)*BB + b)*HH + h];
                    a3 += sc[s0 + 48] * enc[((size_t)(s0+48)*BB + b)*HH + h];
                }
                g_XC[b*1024 + 512 + h] = (a0 + a1) + (a2 + a3);
            }
        } else if (ct >= 64){
            // emb gather for step t+1
            if (t < T1-1){
                int idx = ct - 64;
                int b2 = idx >> 1;
                int k2 = (idx & 1)*256 + tid;
                int wd = tgt[b2*TT + (t+1)];
                __nv_bfloat16 hi, lo;
                bsplit(emb[(size_t)wd*EE + k2], hi, lo);
                g_Xh[b2*KX + k2] = hi;
                g_Xl[b2*KX + k2] = lo;
            }
            // convW slice (window ph=0)
            unsigned winbase = (unsigned)(t*2 + 0) * 81920u;
            #pragma unroll
            for (int j = 0; j < 5; j++){
                unsigned i4 = winbase + (unsigned)j*16384u + (unsigned)(ct-64)*256u + tid;
                if (i4 < WF4) convW_item(W_o, i4);
            }
        }
        gbar(++nb * NCTA);

        // ============ Phase C: ah2 (0..63) | convW (64..127) ============
        if (ct < 64){
            float* xc = (float*)dsm;
            {
                const float4* src = (const float4*)g_XC;
                float4* dst = (float4*)xc;
                for (int i = tid; i < 8192; i += 256) dst[i] = src[i];
            }
            __syncthreads();

            const int c = ct*8 + w;
            for (int b = 0; b < BB; b++){
                const float* xb = xc + b*1024;
                float s = 0.f;
                #pragma unroll
                for (int q=0;q<32;q++) s += wreg[q] * xb[l + q*32];
                #pragma unroll
                for (int off=16; off>0; off>>=1) s += __shfl_xor_sync(0xffffffffu, s, off);
                if (l == 0){
                    float v = tanhf(s + wbias);
                    __nv_bfloat16 hi, lo; bsplit(v, hi, lo);
                    int r = t*BB + b;
                    g_Ah[(size_t)r*HH + c] = hi;
                    g_Al[(size_t)r*HH + c] = lo;
                    g_Xh[b*KX + 512 + c] = hi;
                    g_Xl[b*KX + 512 + c] = lo;
                }
            }
        } else {
            unsigned winbase = (unsigned)(t*2 + 1) * 81920u;
            #pragma unroll
            for (int j = 0; j < 5; j++){
                unsigned i4 = winbase + (unsigned)j*16384u + (unsigned)(ct-64)*256u + tid;
                if (i4 < WF4) convW_item(W_o, i4);
            }
        }
        gbar(++nb * NCTA);
    }
}

// ---------------------------------------------------------------------------
// Vocab GEMM (proven R7 single-pass 3-term)
// ---------------------------------------------------------------------------
#define VK_STR 40

__global__ void __launch_bounds__(256, 2)
k_vocab(const float* __restrict__ b_o, float* __restrict__ logits)
{
    extern __shared__ char vsm[];
    const int tid  = threadIdx.x;
    const int wid  = tid >> 5, lane = tid & 31;
    const int mtile = blockIdx.x;
    const int ntile = blockIdx.y;

    const __nv_bfloat16* Asrc_h = g_Ah + (size_t)mtile*128*HH;
    const __nv_bfloat16* Asrc_l = g_Al + (size_t)mtile*128*HH;
    const __nv_bfloat16* Bsrc_h = g_Wh + (size_t)ntile*64*HH;
    const __nv_bfloat16* Bsrc_l = g_Wl + (size_t)ntile*64*HH;

    const unsigned base = smem_u32(vsm);
    const unsigned uAh = base;
    const unsigned uAl = base + 20480;
    const unsigned uBh = base + 40960;
    const unsigned uBl = base + 51200;

    auto issue = [&](int buf, int ch){
        const int k0 = ch*32;
        const unsigned a_h = uAh + buf*10240;
        const unsigned a_l = uAl + buf*10240;
        const unsigned b_h = uBh + buf*5120;
        const unsigned b_l = uBl + buf*5120;
        #pragma unroll
        for (int q = 0; q < 6; q++){
            int i = q*256 + tid;
            if (i < 1024){
                int j = i & 511; int r = j >> 2, c8 = (j & 3)*8;
                const __nv_bfloat16* src = (i < 512 ? Asrc_h : Asrc_l)
                                           + (size_t)r*HH + k0 + c8;
                unsigned dst = (i < 512 ? a_h : a_l) + (unsigned)(r*VK_STR + c8)*2;
                cpa16(dst, src);
            } else {
                int j = (i - 1024) & 255; int r = j >> 2, c8 = (j & 3)*8;
                const __nv_bfloat16* src = (i < 1280 ? Bsrc_h : Bsrc_l)
                                           + (size_t)r*HH + k0 + c8;
                unsigned dst = (i < 1280 ? b_h : b_l) + (unsigned)(r*VK_STR + c8)*2;
                cpa16(dst, src);
            }
        }
    };

    float acc[2][4][4];
    #pragma unroll
    for (int mi=0;mi<2;mi++)
        #pragma unroll
        for (int ni=0;ni<4;ni++)
            #pragma unroll
            for (int q=0;q<4;q++) acc[mi][ni][q]=0.f;

    const int m0 = (wid & 3) * 32;
    const int n0 = (wid >> 2) * 32;

    const int arow  = (lane & 7) + ((lane >> 3) & 1) * 8;
    const int akoff = (lane >> 4) * 8;
    const int brow  = (lane & 7) + ((lane >> 4) & 1) * 8;
    const int bkoff = ((lane >> 3) & 1) * 8;

    issue(0, 0); CP_COMMIT();

    const int NCH = 16;
    for (int ch = 0; ch < NCH; ch++){
        int buf = ch & 1;
        if (ch + 1 < NCH){ issue(buf ^ 1, ch + 1); CP_COMMIT(); CP_WAIT(1); }
        else             { CP_WAIT(0); }
        __syncthreads();

        const unsigned a_h = uAh + buf*10240;
        const unsigned a_l = uAl + buf*10240;
        const unsigned b_h = uBh + buf*5120;
        const unsigned b_l = uBl + buf*5120;
        #pragma unroll
        for (int ks = 0; ks < 32; ks += 16){
            unsigned afh[2][4], afl[2][4], bfh[2][4], bfl[2][4];
            #pragma unroll
            for (int mi=0;mi<2;mi++){
                ldmx4(afh[mi], a_h + (unsigned)((m0 + mi*16 + arow)*VK_STR + ks + akoff)*2);
                ldmx4(afl[mi], a_l + (unsigned)((m0 + mi*16 + arow)*VK_STR + ks + akoff)*2);
            }
            #pragma unroll
            for (int g=0; g<2; g++){
                ldmx4(bfh[g], b_h + (unsigned)((n0 + g*16 + brow)*VK_STR + ks + bkoff)*2);
                ldmx4(bfl[g], b_l + (unsigned)((n0 + g*16 + brow)*VK_STR + ks + bkoff)*2);
            }
            #pragma unroll
            for (int mi=0;mi<2;mi++)
                #pragma unroll
                for (int ni=0;ni<4;ni++){
                    unsigned h0 = bfh[ni>>1][(ni&1)*2], h1 = bfh[ni>>1][(ni&1)*2+1];
                    unsigned l0 = bfl[ni>>1][(ni&1)*2], l1 = bfl[ni>>1][(ni&1)*2+1];
                    mma16816(acc[mi][ni], afh[mi], h0, h1);
                    mma16816(acc[mi][ni], afh[mi], l0, l1);
                    mma16816(acc[mi][ni], afl[mi], h0, h1);
                }
        }
        __syncthreads();
    }

    #pragma unroll
    for (int mi=0;mi<2;mi++){
        #pragma unroll
        for (int ni=0;ni<4;ni++){
            int row = mtile*128 + m0 + mi*16 + (lane >> 2);
            int col = ntile*64  + n0 + ni*8  + (lane & 3)*2;
            float bia0 = b_o[col], bia1 = b_o[col+1];
            if (row < T1*BB){
                float* o = logits + (size_t)row*VV + col;
                o[0] = acc[mi][ni][0] + bia0;
                o[1] = acc[mi][ni][1] + bia1;
            }
            if (row + 8 < T1*BB){
                float* o = logits + (size_t)(row+8)*VV + col;
                o[0] = acc[mi][ni][2] + bia0;
                o[1] = acc[mi][ni][3] + bia1;
            }
        }
    }
}

// ---------------------------------------------------------------------------
// Online log-softmax + argmax
// ---------------------------------------------------------------------------
__global__ void k_lsm(float* __restrict__ logits)
{
    __shared__ float ms[256], ss[256];
    __shared__ int   ii[256];
    const int row = blockIdx.x;
    const int tid = threadIdx.x;
    float* x = logits + (size_t)row * VV;

    float m = x[tid]; float s = 1.f; int mi = tid;
    for (int c = tid + 256; c < VV; c += 256){
        float v = x[c];
        if (v > m){ s = s*fexp(m - v) + 1.f; m = v; mi = c; }
        else       s += fexp(v - m);
    }
    ms[tid]=m; ss[tid]=s; ii[tid]=mi;
    __syncthreads();
    for (int st = 128; st > 0; st >>= 1){
        if (tid < st){
            float m1=ms[tid], s1=ss[tid]; int i1=ii[tid];
            float m2=ms[tid+st], s2=ss[tid+st]; int i2=ii[tid+st];
            if (m2 > m1)      { ms[tid]=m2; ss[tid]=s1*fexp(m1-m2)+s2; ii[tid]=i2; }
            else if (m2 < m1) { ss[tid]=s1+s2*fexp(m2-m1); }
            else              { ss[tid]=s1+s2; ii[tid]=min(i1,i2); }
        }
        __syncthreads();
    }
    float lse = ms[0] + logf(ss[0]);
    if (tid == 0) g_argmax[row] = ii[0];
    for (int c = tid; c < VV; c += 256) x[c] -= lse;
}

__global__ void k_tail_f(float* __restrict__ out)
{
    int r = blockIdx.x*blockDim.x + threadIdx.x;
    if (r < T1*BB) out[TBV + r] = (float)g_argmax[r];
}
__global__ void k_tail_i(int* __restrict__ out)
{
    int r = blockIdx.x*blockDim.x + threadIdx.x;
    if (r < T1*BB) out[r] = g_argmax[r];
}

// ---------------------------------------------------------------------------
extern "C" void kernel_launch(void* const* d_in, const int* in_sizes, int n_in,
                              void* d_out, int out_size)
{
    const int*   tgt   = (const int*)  d_in[0];
    const int*   lens  = (const int*)  d_in[1];
    const float* enc   = (const float*)d_in[2];
    const float* h0    = (const float*)d_in[3];
    const float* c0    = (const float*)d_in[4];
    const float* emb   = (const float*)d_in[5];
    const float* W_ih  = (const float*)d_in[6];
    const float* W_hh  = (const float*)d_in[7];
    const float* b_ih  = (const float*)d_in[8];
    const float* b_hh  = (const float*)d_in[9];
    const float* W_a   = (const float*)d_in[10];
    const float* W_c   = (const float*)d_in[11];
    const float* b_c   = (const float*)d_in[12];
    const float* W_o   = (const float*)d_in[13];
    const float* b_o   = (const float*)d_in[14];

    float *p_proj=nullptr, *p_lg=nullptr;
    cudaGetSymbolAddress((void**)&p_proj, g_proj);
    cudaGetSymbolAddress((void**)&p_lg,   g_logits);

    const bool big = (size_t)out_size >= TBV;
    float* logits = big ? (float*)d_out : p_lg;

    cudaFuncSetAttribute(k_loop,  cudaFuncAttributeMaxDynamicSharedMemorySize, 131072);
    cudaFuncSetAttribute(k_vocab, cudaFuncAttributeMaxDynamicSharedMemorySize, 61440);

    // prologue (convW is folded into the loop's idle CTAs)
    k_prep0<<<64, 256>>>(h0, c0, tgt, emb);
    k_convG<<<(int)(((size_t)JG*KX/4 + 255)/256), 256>>>(W_ih, W_hh);
    sgemm<128,64,16,8,4><<<dim3(512/64, 2048/128), 256>>>(
        enc, W_a, p_proj, BB*SS, HH, HH);

    // persistent recurrent loop
    k_rst<<<1, 1>>>();
    k_loop<<<NCTA, 256, 131072>>>(b_ih, b_hh, lens, enc, W_c, b_c, tgt, emb, W_o);

    // vocab projection + log-softmax
    k_vocab<<<dim3(8, 500), 256, 61440>>>(b_o, logits);
    k_lsm<<<T1*BB, 256>>>(logits);

    if (big && (size_t)out_size >= TBV + (size_t)T1*BB) {
        k_tail_f<<<4, 256>>>((float*)d_out);
    } else if (!big) {
        k_tail_i<<<4, 256>>>((int*)d_out);
    }
}

// round 9
// speedup vs baseline: 1.2945x; 1.0475x over previous
#include <cuda_runtime.h>
#include <cuda_bf16.h>
#include <math.h>

// Problem constants
#define BB 32
#define TT 32
#define SS 64
#define HH 512
#define EE 512
#define VV 32000
#define T1 (TT-1)
#define TBV ((size_t)T1*BB*VV)
#define BH (BB*HH)
#define MPAD 1024
#define KX 1536
#define JG 2048
#define NCTA 128
#define WF4 4096000u    // VV*HH/4

// -------- persistent device scratch --------
__device__ float g_h[BH];
__device__ float g_c[BH];
__device__ float g_proj[BB*SS*HH];
__device__ __align__(16) float g_XC[BB*1024];
__device__ float g_GpartA[8*BB*JG];                // ah-part partials (z=8, K=64)
__device__ float g_GpartH[4*BB*JG];                // h-part partials (z2=4, K=128)
__device__ float g_Gemb[MPAD*JG];                  // emb-part + biases, all steps
__device__ int   g_argmax[T1*BB];
__device__ float g_logits[T1*BB*VV];
__device__ __align__(16) __nv_bfloat16 g_Wh[(size_t)VV*HH];
__device__ __align__(16) __nv_bfloat16 g_Wl[(size_t)VV*HH];
__device__ __align__(16) __nv_bfloat16 g_Ah[MPAD*HH];   // rows 992..1023 stay 0
__device__ __align__(16) __nv_bfloat16 g_Al[MPAD*HH];
__device__ __align__(16) __nv_bfloat16 g_gWh[JG*KX];
__device__ __align__(16) __nv_bfloat16 g_gWl[JG*KX];
__device__ __align__(16) __nv_bfloat16 g_Xh[BB*KX];     // [unused|ah|h] layout kept
__device__ __align__(16) __nv_bfloat16 g_Xl[BB*KX];
__device__ __align__(16) __nv_bfloat16 g_Eh[MPAD*EE];   // gathered emb rows (hi)
__device__ __align__(16) __nv_bfloat16 g_El[MPAD*EE];   // gathered emb rows (lo)
__device__ unsigned g_barcnt;

__device__ __forceinline__ float sigf(float x){ return 1.0f/(1.0f+expf(-x)); }

__device__ __forceinline__ float fexp(float x){
    float t = x * 1.4426950408889634f;
    float n = rintf(t);
    float f = t - n;
    float p = 1.5403530e-4f;
    p = fmaf(p, f, 1.3333558e-3f);
    p = fmaf(p, f, 9.6181291e-3f);
    p = fmaf(p, f, 5.5504109e-2f);
    p = fmaf(p, f, 2.4022651e-1f);
    p = fmaf(p, f, 6.9314718e-1f);
    p = fmaf(p, f, 1.0f);
    int e = (int)n;
    e = e < -126 ? -126 : (e > 127 ? 127 : e);
    float sc = __int_as_float((e+127)<<23);
    return p*sc;
}

// ------------------ low-level helpers ------------------
__device__ __forceinline__ unsigned smem_u32(const void* p){
    unsigned a;
    asm("{ .reg .u64 t; cvta.to.shared.u64 t, %1; cvt.u32.u64 %0, t; }" : "=r"(a) : "l"(p));
    return a;
}
__device__ __forceinline__ void cpa16(unsigned dst, const void* src){
    asm volatile("cp.async.cg.shared.global [%0], [%1], 16;" :: "r"(dst), "l"(src));
}
#define CP_COMMIT() asm volatile("cp.async.commit_group;" ::: "memory")
#define CP_WAIT(n)  asm volatile("cp.async.wait_group %0;" :: "n"(n) : "memory")

__device__ __forceinline__ void ldmx4(unsigned* r, unsigned addr){
    asm volatile("ldmatrix.sync.aligned.m8n8.x4.shared.b16 {%0,%1,%2,%3}, [%4];"
        : "=r"(r[0]), "=r"(r[1]), "=r"(r[2]), "=r"(r[3]) : "r"(addr));
}
__device__ __forceinline__ void mma16816(float* d, const unsigned* a,
                                         unsigned b0, unsigned b1){
    asm volatile(
        "mma.sync.aligned.m16n8k16.row.col.f32.bf16.bf16.f32 "
        "{%0,%1,%2,%3}, {%4,%5,%6,%7}, {%8,%9}, {%0,%1,%2,%3};"
        : "+f"(d[0]), "+f"(d[1]), "+f"(d[2]), "+f"(d[3])
        : "r"(a[0]), "r"(a[1]), "r"(a[2]), "r"(a[3]), "r"(b0), "r"(b1));
}
__device__ __forceinline__ void bsplit(float v, __nv_bfloat16& hi, __nv_bfloat16& lo){
    hi = __float2bfloat16(v);
    lo = __float2bfloat16(v - __bfloat162float(hi));
}

// pure-spin grid barrier (counter reset in k_prep0 each replay)
__device__ __forceinline__ void gbar(unsigned target){
    __syncthreads();
    if (threadIdx.x == 0){
        __threadfence();
        atomicAdd(&g_barcnt, 1u);
        unsigned v;
        do {
            asm volatile("ld.global.acquire.gpu.b32 %0, [%1];"
                         : "=r"(v) : "l"(&g_barcnt));
        } while (v < target);
    }
    __syncthreads();
}

// ---------------------------------------------------------------------------
// Generic tiled SGEMM (proj precompute)
// ---------------------------------------------------------------------------
template<int BM,int BN,int BK,int TM,int TN>
__global__ void sgemm(const float* __restrict__ A, const float* __restrict__ B,
                      float* __restrict__ C, int M, int N, int K)
{
    constexpr int THREADS = (BM/TM)*(BN/TN);
    static_assert(THREADS == 256, "256 threads expected");
    __shared__ float As[BK][BM+4];
    __shared__ float Bs[BK][BN+4];
    const int tid = threadIdx.x;
    const int bm = blockIdx.y*BM, bn = blockIdx.x*BN;
    const int tx = tid % (BN/TN);
    const int ty = tid / (BN/TN);
    float acc[TM][TN];
    #pragma unroll
    for (int i=0;i<TM;i++)
        #pragma unroll
        for (int j=0;j<TN;j++) acc[i][j]=0.f;

    for (int k0 = 0; k0 < K; k0 += BK) {
        #pragma unroll
        for (int i=0;i<(BM*BK)/THREADS;i++){
            int idx = tid + i*THREADS; int m = idx/BK, k = idx%BK;
            As[k][m] = A[(size_t)(bm+m)*K + k0 + k];
        }
        #pragma unroll
        for (int i=0;i<(BN*BK)/THREADS;i++){
            int idx = tid + i*THREADS; int n = idx/BK, k = idx%BK;
            Bs[k][n] = B[(size_t)(bn+n)*K + k0 + k];
        }
        __syncthreads();
        #pragma unroll
        for (int kk=0;kk<BK;kk++){
            float a[TM], b[TN];
            #pragma unroll
            for (int i=0;i<TM;i++) a[i] = As[kk][ty*TM+i];
            #pragma unroll
            for (int j=0;j<TN;j++) b[j] = Bs[kk][tx*TN+j];
            #pragma unroll
            for (int i=0;i<TM;i++)
                #pragma unroll
                for (int j=0;j<TN;j++) acc[i][j] += a[i]*b[j];
        }
        __syncthreads();
    }
    #pragma unroll
    for (int i=0;i<TM;i++){
        int gm = bm + ty*TM + i;
        #pragma unroll
        for (int j=0;j<TN;j++)
            C[(size_t)gm*N + bn + tx*TN + j] = acc[i][j];
    }
}

// ---------------------------------------------------------------------------
// Prologue: h,c init + X (ah=0, h=h0) + barrier reset
// ---------------------------------------------------------------------------
__global__ void k_prep0(const float* __restrict__ h0, const float* __restrict__ c0)
{
    if (blockIdx.x == 0 && threadIdx.x == 0) g_barcnt = 0;
    int idx = blockIdx.x*256 + threadIdx.x;
    int b = idx >> 9, k = idx & 511;
    g_h[idx] = h0[idx];
    g_c[idx] = c0[idx];
    __nv_bfloat16 hi, lo;
    g_Xh[b*KX + 512 + k] = __float2bfloat16(0.f);
    g_Xl[b*KX + 512 + k] = __float2bfloat16(0.f);
    bsplit(h0[idx], hi, lo);
    g_Xh[b*KX + 1024 + k] = hi;  g_Xl[b*KX + 1024 + k] = lo;
}

// gather emb rows for all (t,b) pairs, bf16 hi/lo split, zero-pad to 1024 rows
__global__ void k_gemb(const int* __restrict__ tgt, const float* __restrict__ emb)
{
    int i = (blockIdx.x*256 + threadIdx.x)*4;      // over 1024*512
    int r = i >> 9, k = i & 511;
    float4 v = make_float4(0.f,0.f,0.f,0.f);
    if (r < T1*BB){
        int t = r >> 5, b = r & 31;
        int w = tgt[b*TT + t];
        v = *(const float4*)(emb + (size_t)w*EE + k);
    }
    __nv_bfloat16 h0,h1,h2,h3,l0,l1,l2,l3;
    bsplit(v.x,h0,l0); bsplit(v.y,h1,l1); bsplit(v.z,h2,l2); bsplit(v.w,h3,l3);
    *(__nv_bfloat162*)(g_Eh + i)     = __nv_bfloat162(h0,h1);
    *(__nv_bfloat162*)(g_Eh + i + 2) = __nv_bfloat162(h2,h3);
    *(__nv_bfloat162*)(g_El + i)     = __nv_bfloat162(l0,l1);
    *(__nv_bfloat162*)(g_El + i + 2) = __nv_bfloat162(l2,l3);
}

__global__ void k_convG(const float* __restrict__ W_ih, const float* __restrict__ W_hh)
{
    size_t i = ((size_t)blockIdx.x*256 + threadIdx.x)*4;
    if (i >= (size_t)JG*KX) return;
    int j = (int)(i / KX);
    int k = (int)(i % KX);
    float4 v = (k < 1024) ? *(const float4*)(W_ih + (size_t)j*1024 + k)
                          : *(const float4*)(W_hh + (size_t)j*512 + (k-1024));
    __nv_bfloat16 h, l;
    bsplit(v.x, h, l); g_gWh[i+0]=h; g_gWl[i+0]=l;
    bsplit(v.y, h, l); g_gWh[i+1]=h; g_gWl[i+1]=l;
    bsplit(v.z, h, l); g_gWh[i+2]=h; g_gWl[i+2]=l;
    bsplit(v.w, h, l); g_gWh[i+3]=h; g_gWl[i+3]=l;
}

// ---------------------------------------------------------------------------
// Gemb = E @ gW[:, 0:512]^T + (b_ih + b_hh) : HMMA, [1024 x 2048], K=512
// grid (8 mtiles, 32 ntiles), 256 threads, smem 61440
// ---------------------------------------------------------------------------
#define VK_STR 40

__global__ void __launch_bounds__(256, 2)
k_gembmm(const float* __restrict__ b_ih, const float* __restrict__ b_hh)
{
    extern __shared__ char vsm[];
    const int tid  = threadIdx.x;
    const int wid  = tid >> 5, lane = tid & 31;
    const int mtile = blockIdx.x;
    const int ntile = blockIdx.y;

    const __nv_bfloat16* Asrc_h = g_Eh + (size_t)mtile*128*EE;
    const __nv_bfloat16* Asrc_l = g_El + (size_t)mtile*128*EE;
    const __nv_bfloat16* Bsrc_h = g_gWh + (size_t)ntile*64*KX;
    const __nv_bfloat16* Bsrc_l = g_gWl + (size_t)ntile*64*KX;

    const unsigned base = smem_u32(vsm);
    const unsigned uAh = base;
    const unsigned uAl = base + 20480;
    const unsigned uBh = base + 40960;
    const unsigned uBl = base + 51200;

    auto issue = [&](int buf, int ch){
        const int k0 = ch*32;
        const unsigned a_h = uAh + buf*10240;
        const unsigned a_l = uAl + buf*10240;
        const unsigned b_h = uBh + buf*5120;
        const unsigned b_l = uBl + buf*5120;
        #pragma unroll
        for (int q = 0; q < 6; q++){
            int i = q*256 + tid;
            if (i < 1024){
                int j = i & 511; int r = j >> 2, c8 = (j & 3)*8;
                const __nv_bfloat16* src = (i < 512 ? Asrc_h : Asrc_l)
                                           + (size_t)r*EE + k0 + c8;
                unsigned dst = (i < 512 ? a_h : a_l) + (unsigned)(r*VK_STR + c8)*2;
                cpa16(dst, src);
            } else {
                int j = (i - 1024) & 255; int r = j >> 2, c8 = (j & 3)*8;
                const __nv_bfloat16* src = (i < 1280 ? Bsrc_h : Bsrc_l)
                                           + (size_t)r*KX + k0 + c8;
                unsigned dst = (i < 1280 ? b_h : b_l) + (unsigned)(r*VK_STR + c8)*2;
                cpa16(dst, src);
            }
        }
    };

    float acc[2][4][4];
    #pragma unroll
    for (int mi=0;mi<2;mi++)
        #pragma unroll
        for (int ni=0;ni<4;ni++)
            #pragma unroll
            for (int q=0;q<4;q++) acc[mi][ni][q]=0.f;

    const int m0 = (wid & 3) * 32;
    const int n0 = (wid >> 2) * 32;
    const int arow  = (lane & 7) + ((lane >> 3) & 1) * 8;
    const int akoff = (lane >> 4) * 8;
    const int brow  = (lane & 7) + ((lane >> 4) & 1) * 8;
    const int bkoff = ((lane >> 3) & 1) * 8;

    issue(0, 0); CP_COMMIT();
    const int NCH = 16;
    for (int ch = 0; ch < NCH; ch++){
        int buf = ch & 1;
        if (ch + 1 < NCH){ issue(buf ^ 1, ch + 1); CP_COMMIT(); CP_WAIT(1); }
        else             { CP_WAIT(0); }
        __syncthreads();
        const unsigned a_h = uAh + buf*10240;
        const unsigned a_l = uAl + buf*10240;
        const unsigned b_h = uBh + buf*5120;
        const unsigned b_l = uBl + buf*5120;
        #pragma unroll
        for (int ks = 0; ks < 32; ks += 16){
            unsigned afh[2][4], afl[2][4], bfh[2][4], bfl[2][4];
            #pragma unroll
            for (int mi=0;mi<2;mi++){
                ldmx4(afh[mi], a_h + (unsigned)((m0 + mi*16 + arow)*VK_STR + ks + akoff)*2);
                ldmx4(afl[mi], a_l + (unsigned)((m0 + mi*16 + arow)*VK_STR + ks + akoff)*2);
            }
            #pragma unroll
            for (int g=0; g<2; g++){
                ldmx4(bfh[g], b_h + (unsigned)((n0 + g*16 + brow)*VK_STR + ks + bkoff)*2);
                ldmx4(bfl[g], b_l + (unsigned)((n0 + g*16 + brow)*VK_STR + ks + bkoff)*2);
            }
            #pragma unroll
            for (int mi=0;mi<2;mi++)
                #pragma unroll
                for (int ni=0;ni<4;ni++){
                    unsigned h0 = bfh[ni>>1][(ni&1)*2], h1 = bfh[ni>>1][(ni&1)*2+1];
                    unsigned l0 = bfl[ni>>1][(ni&1)*2], l1 = bfl[ni>>1][(ni&1)*2+1];
                    mma16816(acc[mi][ni], afh[mi], h0, h1);
                    mma16816(acc[mi][ni], afh[mi], l0, l1);
                    mma16816(acc[mi][ni], afl[mi], h0, h1);
                }
        }
        __syncthreads();
    }

    #pragma unroll
    for (int mi=0;mi<2;mi++){
        #pragma unroll
        for (int ni=0;ni<4;ni++){
            int row = mtile*128 + m0 + mi*16 + (lane >> 2);
            int col = ntile*64  + n0 + ni*8  + (lane & 3)*2;
            float bia0 = b_ih[col] + b_hh[col];
            float bia1 = b_ih[col+1] + b_hh[col+1];
            float* o = g_Gemb + (size_t)row*JG + col;
            o[0] = acc[mi][ni][0] + bia0;
            o[1] = acc[mi][ni][1] + bia1;
            o += 8*JG;
            o[0] = acc[mi][ni][2] + bia0;
            o[1] = acc[mi][ni][3] + bia1;
        }
    }
}

// ---------------------------------------------------------------------------
// gates-h-part GEMM (K=512 h slice, z2 in 0..3, K=128 each, 2 chunks of 64)
// shared by k_gh0 prologue and phase C of the loop
// ---------------------------------------------------------------------------
#define GSTR 72
#define ABUF 46080

__device__ __forceinline__ void ghpart_run(unsigned base, int tid, int nt, int z2)
{
    const int w = tid >> 5, l = tid & 31;
    const int nbase = nt * 128;
    const int n0 = w * 16;
    const int arow  = (l & 7) + ((l >> 3) & 1) * 8;
    const int akoff = (l >> 4) * 8;
    const int brow  = (l & 7) + ((l >> 4) & 1) * 8;
    const int bkoff = ((l >> 3) & 1) * 8;

    auto issue = [&](int buf, int ck){
        const int koff = 1024 + z2*128 + ck*64;
        const unsigned uAh = base + buf*ABUF;
        const unsigned uAl = uAh + 4608;
        const unsigned uBh = uAh + 9216;
        const unsigned uBl = uAh + 27648;
        #pragma unroll
        for (int q = 0; q < 10; q++){
            int i = q*256 + tid;
            if (i < 512){
                int idx = i & 255; int row = idx >> 3, c8 = idx & 7;
                const __nv_bfloat16* src = (i < 256 ? g_Xh : g_Xl)
                                           + (size_t)row*KX + koff + c8*8;
                unsigned dst = (i < 256 ? uAh : uAl) + (unsigned)(row*GSTR + c8*8)*2;
                cpa16(dst, src);
            } else {
                int idx = (i - 512) & 1023; int row = idx >> 3, c8 = idx & 7;
                const __nv_bfloat16* src = (i < 1536 ? g_gWh : g_gWl)
                                           + (size_t)(nbase+row)*KX + koff + c8*8;
                unsigned dst = (i < 1536 ? uBh : uBl) + (unsigned)(row*GSTR + c8*8)*2;
                cpa16(dst, src);
            }
        }
    };

    float acc[2][2][4];
    #pragma unroll
    for (int mi=0;mi<2;mi++)
        #pragma unroll
        for (int ni=0;ni<2;ni++)
            #pragma unroll
            for (int q=0;q<4;q++) acc[mi][ni][q]=0.f;

    issue(0, 0); CP_COMMIT();
    for (int ck = 0; ck < 2; ck++){
        int buf = ck;
        if (ck == 0){ issue(1, 1); CP_COMMIT(); CP_WAIT(1); }
        else        { CP_WAIT(0); }
        __syncthreads();
        const unsigned uAh = base + buf*ABUF;
        const unsigned uAl = uAh + 4608;
        const unsigned uBh = uAh + 9216;
        const unsigned uBl = uAh + 27648;
        #pragma unroll
        for (int ks = 0; ks < 64; ks += 16){
            unsigned afh[2][4], afl[2][4], bfh[4], bfl[4];
            #pragma unroll
            for (int mi=0;mi<2;mi++){
                ldmx4(afh[mi], uAh + (unsigned)((mi*16 + arow)*GSTR + ks + akoff)*2);
                ldmx4(afl[mi], uAl + (unsigned)((mi*16 + arow)*GSTR + ks + akoff)*2);
            }
            ldmx4(bfh, uBh + (unsigned)((n0 + brow)*GSTR + ks + bkoff)*2);
            ldmx4(bfl, uBl + (unsigned)((n0 + brow)*GSTR + ks + bkoff)*2);
            #pragma unroll
            for (int mi=0;mi<2;mi++)
                #pragma unroll
                for (int ni=0;ni<2;ni++){
                    mma16816(acc[mi][ni], afh[mi], bfh[ni*2], bfh[ni*2+1]);
                    mma16816(acc[mi][ni], afh[mi], bfl[ni*2], bfl[ni*2+1]);
                    mma16816(acc[mi][ni], afl[mi], bfh[ni*2], bfh[ni*2+1]);
                }
        }
        __syncthreads();
    }

    #pragma unroll
    for (int mi=0;mi<2;mi++){
        #pragma unroll
        for (int ni=0;ni<2;ni++){
            int row = mi*16 + (l >> 2);
            int col = nbase + n0 + ni*8 + (l & 3)*2;
            float* gp = g_GpartH + ((size_t)z2*BB + row)*JG + col;
            gp[0] = acc[mi][ni][0];
            gp[1] = acc[mi][ni][1];
            gp += 8*JG;
            gp[0] = acc[mi][ni][2];
            gp[1] = acc[mi][ni][3];
        }
    }
}

// prologue: gates-h partials for t=0 (reads h0 already staged in g_Xh/g_Xl)
__global__ void __launch_bounds__(256)
k_gh0()
{
    extern __shared__ char dsm[];
    const int ct = blockIdx.x;
    ghpart_run(smem_u32(dsm), threadIdx.x, ct & 15, ct >> 4);
}

// ---------------------------------------------------------------------------
// convW slice (in-loop, idle CTAs): convert float4 group i4 of W_o
// ---------------------------------------------------------------------------
__device__ __forceinline__ void convW_item(const float* __restrict__ W, unsigned i4)
{
    size_t i = (size_t)i4 * 4;
    float4 v = *(const float4*)(W + i);
    __nv_bfloat16 h0, h1, h2, h3, l0, l1, l2, l3;
    bsplit(v.x, h0, l0); bsplit(v.y, h1, l1);
    bsplit(v.z, h2, l2); bsplit(v.w, h3, l3);
    *(__nv_bfloat162*)(g_Wh + i)     = __nv_bfloat162(h0, h1);
    *(__nv_bfloat162*)(g_Wh + i + 2) = __nv_bfloat162(h2, h3);
    *(__nv_bfloat162*)(g_Wl + i)     = __nv_bfloat162(l0, l1);
    *(__nv_bfloat162*)(g_Wl + i + 2) = __nv_bfloat162(l2, l3);
}

// ---------------------------------------------------------------------------
// Persistent recurrent loop: 128 CTAs x 256 threads.
// Phase A: gates ah-part (all CTAs, 1 chunk, K=64 per z-slice)
// Phase B: cell+attn (0..31) | convW (32..127)
// Phase C: ah2 (0..63) | gates h-part for t+1 (64..127)
// ---------------------------------------------------------------------------
__global__ void __launch_bounds__(256)
k_loop(const float* __restrict__ lens_f_unused, const int* __restrict__ lens,
       const float* __restrict__ enc,
       const float* __restrict__ W_c, const float* __restrict__ b_c,
       const float* __restrict__ W_o)
{
    extern __shared__ char dsm[];
    const int ct  = blockIdx.x;
    const int tid = threadIdx.x;
    const int w = tid >> 5, l = tid & 31;
    const unsigned base = smem_u32(dsm);

    // phase A tile assignment
    const int nt = ct & 15;
    const int z  = ct >> 4;
    const int nbase = nt * 128;
    const int n0 = w * 16;
    const int arow  = (l & 7) + ((l >> 3) & 1) * 8;
    const int akoff = (l >> 4) * 8;
    const int brow  = (l & 7) + ((l >> 4) & 1) * 8;
    const int bkoff = ((l >> 3) & 1) * 8;

    // W_c row for phase C (CTAs 0..63)
    float wreg[32];
    float wbias = 0.f;
    if (ct < 64){
        const int c = ct*8 + w;
        const float* wr = W_c + (size_t)c*1024;
        #pragma unroll
        for (int q=0;q<32;q++) wreg[q] = wr[l + q*32];
        wbias = b_c[c];
    }

    unsigned nb = 0;

    for (int t = 0; t < T1; t++){
        // ============ Phase A: gates ah-part (all CTAs, single chunk) ============
        {
            const int koff = 512 + z*64;
            const unsigned uAh = base;
            const unsigned uAl = uAh + 4608;
            const unsigned uBh = uAh + 9216;
            const unsigned uBl = uAh + 27648;
            #pragma unroll
            for (int q = 0; q < 10; q++){
                int i = q*256 + tid;
                if (i < 512){
                    int idx = i & 255; int row = idx >> 3, c8 = idx & 7;
                    const __nv_bfloat16* src = (i < 256 ? g_Xh : g_Xl)
                                               + (size_t)row*KX + koff + c8*8;
                    unsigned dst = (i < 256 ? uAh : uAl) + (unsigned)(row*GSTR + c8*8)*2;
                    cpa16(dst, src);
                } else {
                    int idx = (i - 512) & 1023; int row = idx >> 3, c8 = idx & 7;
                    const __nv_bfloat16* src = (i < 1536 ? g_gWh : g_gWl)
                                               + (size_t)(nbase+row)*KX + koff + c8*8;
                    unsigned dst = (i < 1536 ? uBh : uBl) + (unsigned)(row*GSTR + c8*8)*2;
                    cpa16(dst, src);
                }
            }
            CP_COMMIT(); CP_WAIT(0);
            __syncthreads();

            float acc[2][2][4];
            #pragma unroll
            for (int mi=0;mi<2;mi++)
                #pragma unroll
                for (int ni=0;ni<2;ni++)
                    #pragma unroll
                    for (int q=0;q<4;q++) acc[mi][ni][q]=0.f;

            #pragma unroll
            for (int ks = 0; ks < 64; ks += 16){
                unsigned afh[2][4], afl[2][4], bfh[4], bfl[4];
                #pragma unroll
                for (int mi=0;mi<2;mi++){
                    ldmx4(afh[mi], uAh + (unsigned)((mi*16 + arow)*GSTR + ks + akoff)*2);
                    ldmx4(afl[mi], uAl + (unsigned)((mi*16 + arow)*GSTR + ks + akoff)*2);
                }
                ldmx4(bfh, uBh + (unsigned)((n0 + brow)*GSTR + ks + bkoff)*2);
                ldmx4(bfl, uBl + (unsigned)((n0 + brow)*GSTR + ks + bkoff)*2);
                #pragma unroll
                for (int mi=0;mi<2;mi++)
                    #pragma unroll
                    for (int ni=0;ni<2;ni++){
                        mma16816(acc[mi][ni], afh[mi], bfh[ni*2], bfh[ni*2+1]);
                        mma16816(acc[mi][ni], afh[mi], bfl[ni*2], bfl[ni*2+1]);
                        mma16816(acc[mi][ni], afl[mi], bfh[ni*2], bfh[ni*2+1]);
                    }
            }
            __syncthreads();

            #pragma unroll
            for (int mi=0;mi<2;mi++){
                #pragma unroll
                for (int ni=0;ni<2;ni++){
                    int row = mi*16 + (l >> 2);
                    int col = nbase + n0 + ni*8 + (l & 3)*2;
                    float* gp = g_GpartA + ((size_t)z*BB + row)*JG + col;
                    gp[0] = acc[mi][ni][0];
                    gp[1] = acc[mi][ni][1];
                    gp += 8*JG;
                    gp[0] = acc[mi][ni][2];
                    gp[1] = acc[mi][ni][3];
                }
            }
        }
        gbar(++nb * NCTA);

        // ============ Phase B: cell+attn (0..31) | convW (32..127) ============
        if (ct < BB){
            const int b = ct;
            float* hh = (float*)dsm;
            float* sc = hh + HH;
            const int len = lens[b];

            #pragma unroll
            for (int rep = 0; rep < 2; rep++){
                int h = tid + rep*256;
                float gv[4];
                #pragma unroll
                for (int q=0;q<4;q++){
                    int j = q*HH + h;
                    float s = g_Gemb[((size_t)t*BB + b)*JG + j];
                    #pragma unroll
                    for (int zz=0;zz<8;zz++) s += g_GpartA[((size_t)zz*BB + b)*JG + j];
                    #pragma unroll
                    for (int zz=0;zz<4;zz++) s += g_GpartH[((size_t)zz*BB + b)*JG + j];
                    gv[q] = s;
                }
                int idx = b*HH + h;
                float ig = sigf(gv[0]);
                float fg = sigf(gv[1]);
                float gg = tanhf(gv[2]);
                float og = sigf(gv[3]);
                float c  = fg * g_c[idx] + ig * gg;
                g_c[idx] = c;
                float h2 = og * tanhf(c);
                g_h[idx] = h2;
                hh[h] = h2;
                g_XC[b*1024 + h] = h2;
                __nv_bfloat16 hi, lo; bsplit(h2, hi, lo);
                g_Xh[b*KX + 1024 + h] = hi;
                g_Xl[b*KX + 1024 + h] = lo;
            }
            __syncthreads();

            #pragma unroll
            for (int i = 0; i < 8; i++){
                int s = w*8 + i;
                const float* pr = &g_proj[((size_t)s*BB + b)*HH];
                float sum = 0.f;
                #pragma unroll
                for (int k = 0; k < 16; k++) sum += hh[l + k*32] * pr[l + k*32];
                #pragma unroll
                for (int off=16; off>0; off>>=1) sum += __shfl_xor_sync(0xffffffffu, sum, off);
                if (l == 0) sc[s] = (s < len) ? sum : -1e9f;
            }
            __syncthreads();

            if (tid < 32){
                float v0 = sc[tid], v1 = sc[tid+32];
                float m = fmaxf(v0, v1);
                #pragma unroll
                for (int off=16; off>0; off>>=1) m = fmaxf(m, __shfl_xor_sync(0xffffffffu, m, off));
                float e0 = expf(v0 - m), e1 = expf(v1 - m);
                float s = e0 + e1;
                #pragma unroll
                for (int off=16; off>0; off>>=1) s += __shfl_xor_sync(0xffffffffu, s, off);
                float inv = 1.0f / s;
                sc[tid]    = e0 * inv;
                sc[tid+32] = e1 * inv;
            }
            __syncthreads();

            #pragma unroll
            for (int rep = 0; rep < 2; rep++){
                int h = tid + rep*256;
                float a0=0.f, a1=0.f, a2=0.f, a3=0.f;
                #pragma unroll 4
                for (int s0 = 0; s0 < 16; s0++){
                    a0 += sc[s0]      * enc[((size_t)(s0)*BB    + b)*HH + h];
                    a1 += sc[s0 + 16] * enc[((size_t)(s0+16)*BB + b)*HH + h];
                    a2 += sc[s0 + 32] * enc[((size_t)(s0+32)*BB + b)*HH + h];
                    a3 += sc[s0 + 48] * enc[((size_t)(s0+48)*BB + b)*HH + h];
                }
                g_XC[b*1024 + 512 + h] = (a0 + a1) + (a2 + a3);
            }
        } else {
            // convW window t: 96 CTAs x 256 threads x 6 items
            unsigned winbase = (unsigned)t * 147456u;
            #pragma unroll
            for (int j = 0; j < 6; j++){
                unsigned i4 = winbase + (unsigned)j*24576u + (unsigned)(ct-32)*256u + tid;
                if (i4 < WF4) convW_item(W_o, i4);
            }
        }
        gbar(++nb * NCTA);

        // ============ Phase C: ah2 (0..63) | gates-h(t+1) (64..127) ============
        if (ct < 64){
            float* xc = (float*)dsm;
            {
                const float4* src = (const float4*)g_XC;
                float4* dst = (float4*)xc;
                for (int i = tid; i < 8192; i += 256) dst[i] = src[i];
            }
            __syncthreads();

            const int c = ct*8 + w;
            for (int b = 0; b < BB; b++){
                const float* xb = xc + b*1024;
                float s = 0.f;
                #pragma unroll
                for (int q=0;q<32;q++) s += wreg[q] * xb[l + q*32];
                #pragma unroll
                for (int off=16; off>0; off>>=1) s += __shfl_xor_sync(0xffffffffu, s, off);
                if (l == 0){
                    float v = tanhf(s + wbias);
                    __nv_bfloat16 hi, lo; bsplit(v, hi, lo);
                    int r = t*BB + b;
                    g_Ah[(size_t)r*HH + c] = hi;
                    g_Al[(size_t)r*HH + c] = lo;
                    g_Xh[b*KX + 512 + c] = hi;
                    g_Xl[b*KX + 512 + c] = lo;
                }
            }
        } else if (t + 1 < T1){
            ghpart_run(base, tid, (ct-64) & 15, (ct-64) >> 4);
        }
        gbar(++nb * NCTA);
    }
}

// ---------------------------------------------------------------------------
// Vocab GEMM (proven single-pass 3-term)
// ---------------------------------------------------------------------------
__global__ void __launch_bounds__(256, 2)
k_vocab(const float* __restrict__ b_o, float* __restrict__ logits)
{
    extern __shared__ char vsm[];
    const int tid  = threadIdx.x;
    const int wid  = tid >> 5, lane = tid & 31;
    const int mtile = blockIdx.x;
    const int ntile = blockIdx.y;

    const __nv_bfloat16* Asrc_h = g_Ah + (size_t)mtile*128*HH;
    const __nv_bfloat16* Asrc_l = g_Al + (size_t)mtile*128*HH;
    const __nv_bfloat16* Bsrc_h = g_Wh + (size_t)ntile*64*HH;
    const __nv_bfloat16* Bsrc_l = g_Wl + (size_t)ntile*64*HH;

    const unsigned base = smem_u32(vsm);
    const unsigned uAh = base;
    const unsigned uAl = base + 20480;
    const unsigned uBh = base + 40960;
    const unsigned uBl = base + 51200;

    auto issue = [&](int buf, int ch){
        const int k0 = ch*32;
        const unsigned a_h = uAh + buf*10240;
        const unsigned a_l = uAl + buf*10240;
        const unsigned b_h = uBh + buf*5120;
        const unsigned b_l = uBl + buf*5120;
        #pragma unroll
        for (int q = 0; q < 6; q++){
            int i = q*256 + tid;
            if (i < 1024){
                int j = i & 511; int r = j >> 2, c8 = (j & 3)*8;
                const __nv_bfloat16* src = (i < 512 ? Asrc_h : Asrc_l)
                                           + (size_t)r*HH + k0 + c8;
                unsigned dst = (i < 512 ? a_h : a_l) + (unsigned)(r*VK_STR + c8)*2;
                cpa16(dst, src);
            } else {
                int j = (i - 1024) & 255; int r = j >> 2, c8 = (j & 3)*8;
                const __nv_bfloat16* src = (i < 1280 ? Bsrc_h : Bsrc_l)
                                           + (size_t)r*HH + k0 + c8;
                unsigned dst = (i < 1280 ? b_h : b_l) + (unsigned)(r*VK_STR + c8)*2;
                cpa16(dst, src);
            }
        }
    };

    float acc[2][4][4];
    #pragma unroll
    for (int mi=0;mi<2;mi++)
        #pragma unroll
        for (int ni=0;ni<4;ni++)
            #pragma unroll
            for (int q=0;q<4;q++) acc[mi][ni][q]=0.f;

    const int m0 = (wid & 3) * 32;
    const int n0 = (wid >> 2) * 32;
    const int arow  = (lane & 7) + ((lane >> 3) & 1) * 8;
    const int akoff = (lane >> 4) * 8;
    const int brow  = (lane & 7) + ((lane >> 4) & 1) * 8;
    const int bkoff = ((lane >> 3) & 1) * 8;

    issue(0, 0); CP_COMMIT();
    const int NCH = 16;
    for (int ch = 0; ch < NCH; ch++){
        int buf = ch & 1;
        if (ch + 1 < NCH){ issue(buf ^ 1, ch + 1); CP_COMMIT(); CP_WAIT(1); }
        else             { CP_WAIT(0); }
        __syncthreads();
        const unsigned a_h = uAh + buf*10240;
        const unsigned a_l = uAl + buf*10240;
        const unsigned b_h = uBh + buf*5120;
        const unsigned b_l = uBl + buf*5120;
        #pragma unroll
        for (int ks = 0; ks < 32; ks += 16){
            unsigned afh[2][4], afl[2][4], bfh[2][4], bfl[2][4];
            #pragma unroll
            for (int mi=0;mi<2;mi++){
                ldmx4(afh[mi], a_h + (unsigned)((m0 + mi*16 + arow)*VK_STR + ks + akoff)*2);
                ldmx4(afl[mi], a_l + (unsigned)((m0 + mi*16 + arow)*VK_STR + ks + akoff)*2);
            }
            #pragma unroll
            for (int g=0; g<2; g++){
                ldmx4(bfh[g], b_h + (unsigned)((n0 + g*16 + brow)*VK_STR + ks + bkoff)*2);
                ldmx4(bfl[g], b_l + (unsigned)((n0 + g*16 + brow)*VK_STR + ks + bkoff)*2);
            }
            #pragma unroll
            for (int mi=0;mi<2;mi++)
                #pragma unroll
                for (int ni=0;ni<4;ni++){
                    unsigned h0 = bfh[ni>>1][(ni&1)*2], h1 = bfh[ni>>1][(ni&1)*2+1];
                    unsigned l0 = bfl[ni>>1][(ni&1)*2], l1 = bfl[ni>>1][(ni&1)*2+1];
                    mma16816(acc[mi][ni], afh[mi], h0, h1);
                    mma16816(acc[mi][ni], afh[mi], l0, l1);
                    mma16816(acc[mi][ni], afl[mi], h0, h1);
                }
        }
        __syncthreads();
    }

    #pragma unroll
    for (int mi=0;mi<2;mi++){
        #pragma unroll
        for (int ni=0;ni<4;ni++){
            int row = mtile*128 + m0 + mi*16 + (lane >> 2);
            int col = ntile*64  + n0 + ni*8  + (lane & 3)*2;
            float bia0 = b_o[col], bia1 = b_o[col+1];
            if (row < T1*BB){
                float* o = logits + (size_t)row*VV + col;
                o[0] = acc[mi][ni][0] + bia0;
                o[1] = acc[mi][ni][1] + bia1;
            }
            if (row + 8 < T1*BB){
                float* o = logits + (size_t)(row+8)*VV + col;
                o[0] = acc[mi][ni][2] + bia0;
                o[1] = acc[mi][ni][3] + bia1;
            }
        }
    }
}

// ---------------------------------------------------------------------------
// Online log-softmax + argmax
// ---------------------------------------------------------------------------
__global__ void k_lsm(float* __restrict__ logits)
{
    __shared__ float ms[256], ss[256];
    __shared__ int   ii[256];
    const int row = blockIdx.x;
    const int tid = threadIdx.x;
    float* x = logits + (size_t)row * VV;

    float m = x[tid]; float s = 1.f; int mi = tid;
    for (int c = tid + 256; c < VV; c += 256){
        float v = x[c];
        if (v > m){ s = s*fexp(m - v) + 1.f; m = v; mi = c; }
        else       s += fexp(v - m);
    }
    ms[tid]=m; ss[tid]=s; ii[tid]=mi;
    __syncthreads();
    for (int st = 128; st > 0; st >>= 1){
        if (tid < st){
            float m1=ms[tid], s1=ss[tid]; int i1=ii[tid];
            float m2=ms[tid+st], s2=ss[tid+st]; int i2=ii[tid+st];
            if (m2 > m1)      { ms[tid]=m2; ss[tid]=s1*fexp(m1-m2)+s2; ii[tid]=i2; }
            else if (m2 < m1) { ss[tid]=s1+s2*fexp(m2-m1); }
            else              { ss[tid]=s1+s2; ii[tid]=min(i1,i2); }
        }
        __syncthreads();
    }
    float lse = ms[0] + logf(ss[0]);
    if (tid == 0) g_argmax[row] = ii[0];
    for (int c = tid; c < VV; c += 256) x[c] -= lse;
}

__global__ void k_tail_f(float* __restrict__ out)
{
    int r = blockIdx.x*blockDim.x + threadIdx.x;
    if (r < T1*BB) out[TBV + r] = (float)g_argmax[r];
}
__global__ void k_tail_i(int* __restrict__ out)
{
    int r = blockIdx.x*blockDim.x + threadIdx.x;
    if (r < T1*BB) out[r] = g_argmax[r];
}

// ---------------------------------------------------------------------------
extern "C" void kernel_launch(void* const* d_in, const int* in_sizes, int n_in,
                              void* d_out, int out_size)
{
    const int*   tgt   = (const int*)  d_in[0];
    const int*   lens  = (const int*)  d_in[1];
    const float* enc   = (const float*)d_in[2];
    const float* h0    = (const float*)d_in[3];
    const float* c0    = (const float*)d_in[4];
    const float* emb   = (const float*)d_in[5];
    const float* W_ih  = (const float*)d_in[6];
    const float* W_hh  = (const float*)d_in[7];
    const float* b_ih  = (const float*)d_in[8];
    const float* b_hh  = (const float*)d_in[9];
    const float* W_a   = (const float*)d_in[10];
    const float* W_c   = (const float*)d_in[11];
    const float* b_c   = (const float*)d_in[12];
    const float* W_o   = (const float*)d_in[13];
    const float* b_o   = (const float*)d_in[14];

    float *p_proj=nullptr, *p_lg=nullptr;
    cudaGetSymbolAddress((void**)&p_proj, g_proj);
    cudaGetSymbolAddress((void**)&p_lg,   g_logits);

    const bool big = (size_t)out_size >= TBV;
    float* logits = big ? (float*)d_out : p_lg;

    cudaFuncSetAttribute(k_loop,   cudaFuncAttributeMaxDynamicSharedMemorySize, 131072);
    cudaFuncSetAttribute(k_gh0,    cudaFuncAttributeMaxDynamicSharedMemorySize, 2*ABUF);
    cudaFuncSetAttribute(k_vocab,  cudaFuncAttributeMaxDynamicSharedMemorySize, 61440);
    cudaFuncSetAttribute(k_gembmm, cudaFuncAttributeMaxDynamicSharedMemorySize, 61440);

    // prologue
    k_prep0<<<64, 256>>>(h0, c0);
    k_gemb<<<512, 256>>>(tgt, emb);
    k_convG<<<(int)(((size_t)JG*KX/4 + 255)/256), 256>>>(W_ih, W_hh);
    k_gembmm<<<dim3(8, 32), 256, 61440>>>(b_ih, b_hh);
    sgemm<128,64,16,8,4><<<dim3(512/64, 2048/128), 256>>>(
        enc, W_a, p_proj, BB*SS, HH, HH);
    k_gh0<<<64, 256, 2*ABUF>>>();

    // persistent recurrent loop
    k_loop<<<NCTA, 256, 131072>>>(nullptr, lens, enc, W_c, b_c, W_o);

    // vocab projection + log-softmax
    k_vocab<<<dim3(8, 500), 256, 61440>>>(b_o, logits);
    k_lsm<<<T1*BB, 256>>>(logits);

    if (big && (size_t)out_size >= TBV + (size_t)T1*BB) {
        k_tail_f<<<4, 256>>>((float*)d_out);
    } else if (!big) {
        k_tail_i<<<4, 256>>>((int*)d_out);
    }
}

// round 10
// speedup vs baseline: 1.3096x; 1.0117x over previous
#include <cuda_runtime.h>
#include <cuda_bf16.h>
#include <math.h>

// Problem constants
#define BB 32
#define TT 32
#define SS 64
#define HH 512
#define EE 512
#define VV 32000
#define T1 (TT-1)
#define TBV ((size_t)T1*BB*VV)
#define BH (BB*HH)
#define MPAD 1024
#define KX 1536
#define JG 2048
#define NCTA 128
#define WF4 4096000u    // VV*HH/4

// -------- persistent device scratch --------
__device__ float g_h[BH];
__device__ float g_c[BH];
__device__ float g_proj[2048*HH];
__device__ __align__(16) float g_XC[BB*1024];
__device__ float g_GpartA[8*BB*JG];                // ah-part partials
__device__ float g_GpartH[4*BB*JG];                // h-part partials
__device__ float g_Gemb[MPAD*JG];                  // emb-part + biases, all steps
__device__ int   g_argmax[T1*BB];
__device__ float g_logits[T1*BB*VV];
__device__ __align__(16) __nv_bfloat16 g_Wh[(size_t)VV*HH];
__device__ __align__(16) __nv_bfloat16 g_Wl[(size_t)VV*HH];
__device__ __align__(16) __nv_bfloat16 g_Ah[MPAD*HH];   // rows 992..1023 stay 0
__device__ __align__(16) __nv_bfloat16 g_Al[MPAD*HH];
__device__ __align__(16) __nv_bfloat16 g_gWh[JG*KX];
__device__ __align__(16) __nv_bfloat16 g_gWl[JG*KX];
__device__ __align__(16) __nv_bfloat16 g_Xh[BB*KX];
__device__ __align__(16) __nv_bfloat16 g_Xl[BB*KX];
__device__ __align__(16) __nv_bfloat16 g_Eh[MPAD*EE];
__device__ __align__(16) __nv_bfloat16 g_El[MPAD*EE];
__device__ __align__(16) __nv_bfloat16 g_ENh[2048*HH];  // enc split
__device__ __align__(16) __nv_bfloat16 g_ENl[2048*HH];
__device__ __align__(16) __nv_bfloat16 g_WAh[HH*HH];    // W_a split
__device__ __align__(16) __nv_bfloat16 g_WAl[HH*HH];
__device__ unsigned g_barcnt;

__device__ __forceinline__ float sigf(float x){ return 1.0f/(1.0f+expf(-x)); }

__device__ __forceinline__ float fexp(float x){
    float t = x * 1.4426950408889634f;
    float n = rintf(t);
    float f = t - n;
    float p = 1.5403530e-4f;
    p = fmaf(p, f, 1.3333558e-3f);
    p = fmaf(p, f, 9.6181291e-3f);
    p = fmaf(p, f, 5.5504109e-2f);
    p = fmaf(p, f, 2.4022651e-1f);
    p = fmaf(p, f, 6.9314718e-1f);
    p = fmaf(p, f, 1.0f);
    int e = (int)n;
    e = e < -126 ? -126 : (e > 127 ? 127 : e);
    float sc = __int_as_float((e+127)<<23);
    return p*sc;
}

// ------------------ low-level helpers ------------------
__device__ __forceinline__ unsigned smem_u32(const void* p){
    unsigned a;
    asm("{ .reg .u64 t; cvta.to.shared.u64 t, %1; cvt.u32.u64 %0, t; }" : "=r"(a) : "l"(p));
    return a;
}
__device__ __forceinline__ void cpa16(unsigned dst, const void* src){
    asm volatile("cp.async.cg.shared.global [%0], [%1], 16;" :: "r"(dst), "l"(src));
}
#define CP_COMMIT() asm volatile("cp.async.commit_group;" ::: "memory")
#define CP_WAIT(n)  asm volatile("cp.async.wait_group %0;" :: "n"(n) : "memory")

__device__ __forceinline__ void ldmx4(unsigned* r, unsigned addr){
    asm volatile("ldmatrix.sync.aligned.m8n8.x4.shared.b16 {%0,%1,%2,%3}, [%4];"
        : "=r"(r[0]), "=r"(r[1]), "=r"(r[2]), "=r"(r[3]) : "r"(addr));
}
__device__ __forceinline__ void mma16816(float* d, const unsigned* a,
                                         unsigned b0, unsigned b1){
    asm volatile(
        "mma.sync.aligned.m16n8k16.row.col.f32.bf16.bf16.f32 "
        "{%0,%1,%2,%3}, {%4,%5,%6,%7}, {%8,%9}, {%0,%1,%2,%3};"
        : "+f"(d[0]), "+f"(d[1]), "+f"(d[2]), "+f"(d[3])
        : "r"(a[0]), "r"(a[1]), "r"(a[2]), "r"(a[3]), "r"(b0), "r"(b1));
}
__device__ __forceinline__ void bsplit(float v, __nv_bfloat16& hi, __nv_bfloat16& lo){
    hi = __float2bfloat16(v);
    lo = __float2bfloat16(v - __bfloat162float(hi));
}

// pure-spin grid barrier (counter reset in k_prep0 each replay)
__device__ __forceinline__ void gbar(unsigned target){
    __syncthreads();
    if (threadIdx.x == 0){
        __threadfence();
        atomicAdd(&g_barcnt, 1u);
        unsigned v;
        do {
            asm volatile("ld.global.acquire.gpu.b32 %0, [%1];"
                         : "=r"(v) : "l"(&g_barcnt));
        } while (v < target);
    }
    __syncthreads();
}

// ---------------------------------------------------------------------------
// Prologue: h,c init + X (ah=0, h=h0) + barrier reset
// ---------------------------------------------------------------------------
__global__ void k_prep0(const float* __restrict__ h0, const float* __restrict__ c0)
{
    if (blockIdx.x == 0 && threadIdx.x == 0) g_barcnt = 0;
    int idx = blockIdx.x*256 + threadIdx.x;
    int b = idx >> 9, k = idx & 511;
    g_h[idx] = h0[idx];
    g_c[idx] = c0[idx];
    __nv_bfloat16 hi, lo;
    g_Xh[b*KX + 512 + k] = __float2bfloat16(0.f);
    g_Xl[b*KX + 512 + k] = __float2bfloat16(0.f);
    bsplit(h0[idx], hi, lo);
    g_Xh[b*KX + 1024 + k] = hi;  g_Xl[b*KX + 1024 + k] = lo;
}

// gather emb rows for all (t,b) pairs, bf16 hi/lo split, zero-pad to 1024 rows
__global__ void k_gemb(const int* __restrict__ tgt, const float* __restrict__ emb)
{
    int i = (blockIdx.x*256 + threadIdx.x)*4;
    int r = i >> 9, k = i & 511;
    float4 v = make_float4(0.f,0.f,0.f,0.f);
    if (r < T1*BB){
        int t = r >> 5, b = r & 31;
        int w = tgt[b*TT + t];
        v = *(const float4*)(emb + (size_t)w*EE + k);
    }
    __nv_bfloat16 h0,h1,h2,h3,l0,l1,l2,l3;
    bsplit(v.x,h0,l0); bsplit(v.y,h1,l1); bsplit(v.z,h2,l2); bsplit(v.w,h3,l3);
    *(__nv_bfloat162*)(g_Eh + i)     = __nv_bfloat162(h0,h1);
    *(__nv_bfloat162*)(g_Eh + i + 2) = __nv_bfloat162(h2,h3);
    *(__nv_bfloat162*)(g_El + i)     = __nv_bfloat162(l0,l1);
    *(__nv_bfloat162*)(g_El + i + 2) = __nv_bfloat162(l2,l3);
}

__global__ void k_convG(const float* __restrict__ W_ih, const float* __restrict__ W_hh)
{
    size_t i = ((size_t)blockIdx.x*256 + threadIdx.x)*4;
    if (i >= (size_t)JG*KX) return;
    int j = (int)(i / KX);
    int k = (int)(i % KX);
    float4 v = (k < 1024) ? *(const float4*)(W_ih + (size_t)j*1024 + k)
                          : *(const float4*)(W_hh + (size_t)j*512 + (k-1024));
    __nv_bfloat16 h, l;
    bsplit(v.x, h, l); g_gWh[i+0]=h; g_gWl[i+0]=l;
    bsplit(v.y, h, l); g_gWh[i+1]=h; g_gWl[i+1]=l;
    bsplit(v.z, h, l); g_gWh[i+2]=h; g_gWl[i+2]=l;
    bsplit(v.w, h, l); g_gWh[i+3]=h; g_gWl[i+3]=l;
}

// enc + W_a split to bf16 hi/lo
__global__ void k_convEA(const float* __restrict__ enc, const float* __restrict__ W_a)
{
    size_t i = ((size_t)blockIdx.x*256 + threadIdx.x)*4;
    const size_t NE = (size_t)2048*HH;
    if (i >= NE + (size_t)HH*HH) return;
    const float* src; __nv_bfloat16 *dh, *dl; size_t off;
    if (i < NE){ src = enc;  dh = g_ENh; dl = g_ENl; off = i; }
    else       { src = W_a;  dh = g_WAh; dl = g_WAl; off = i - NE; }
    float4 v = *(const float4*)(src + off);
    __nv_bfloat16 h0,h1,h2,h3,l0,l1,l2,l3;
    bsplit(v.x,h0,l0); bsplit(v.y,h1,l1); bsplit(v.z,h2,l2); bsplit(v.w,h3,l3);
    *(__nv_bfloat162*)(dh + off)     = __nv_bfloat162(h0,h1);
    *(__nv_bfloat162*)(dh + off + 2) = __nv_bfloat162(h2,h3);
    *(__nv_bfloat162*)(dl + off)     = __nv_bfloat162(l0,l1);
    *(__nv_bfloat162*)(dl + off + 2) = __nv_bfloat162(l2,l3);
}

// ---------------------------------------------------------------------------
// Generic HMMA GEMM: C[M,N] = A[M,K=512] @ B[N,K=512]^T (+bias1+bias2)
// 3-term split precision. BM=128, BN=64, 256 threads. Used for Gemb and proj.
// ---------------------------------------------------------------------------
#define VK_STR 40

__global__ void __launch_bounds__(256, 2)
k_hmm(const __nv_bfloat16* __restrict__ Ah, const __nv_bfloat16* __restrict__ Al, int lda,
      const __nv_bfloat16* __restrict__ Bh, const __nv_bfloat16* __restrict__ Bl, int ldb,
      float* __restrict__ C, int ldc,
      const float* __restrict__ bias1, const float* __restrict__ bias2)
{
    extern __shared__ char vsm[];
    const int tid  = threadIdx.x;
    const int wid  = tid >> 5, lane = tid & 31;
    const int mtile = blockIdx.x;
    const int ntile = blockIdx.y;

    const __nv_bfloat16* Asrc_h = Ah + (size_t)mtile*128*lda;
    const __nv_bfloat16* Asrc_l = Al + (size_t)mtile*128*lda;
    const __nv_bfloat16* Bsrc_h = Bh + (size_t)ntile*64*ldb;
    const __nv_bfloat16* Bsrc_l = Bl + (size_t)ntile*64*ldb;

    const unsigned base = smem_u32(vsm);
    const unsigned uAh = base;
    const unsigned uAl = base + 20480;
    const unsigned uBh = base + 40960;
    const unsigned uBl = base + 51200;

    auto issue = [&](int buf, int ch){
        const int k0 = ch*32;
        const unsigned a_h = uAh + buf*10240;
        const unsigned a_l = uAl + buf*10240;
        const unsigned b_h = uBh + buf*5120;
        const unsigned b_l = uBl + buf*5120;
        #pragma unroll
        for (int q = 0; q < 6; q++){
            int i = q*256 + tid;
            if (i < 1024){
                int j = i & 511; int r = j >> 2, c8 = (j & 3)*8;
                const __nv_bfloat16* src = (i < 512 ? Asrc_h : Asrc_l)
                                           + (size_t)r*lda + k0 + c8;
                unsigned dst = (i < 512 ? a_h : a_l) + (unsigned)(r*VK_STR + c8)*2;
                cpa16(dst, src);
            } else {
                int j = (i - 1024) & 255; int r = j >> 2, c8 = (j & 3)*8;
                const __nv_bfloat16* src = (i < 1280 ? Bsrc_h : Bsrc_l)
                                           + (size_t)r*ldb + k0 + c8;
                unsigned dst = (i < 1280 ? b_h : b_l) + (unsigned)(r*VK_STR + c8)*2;
                cpa16(dst, src);
            }
        }
    };

    float acc[2][4][4];
    #pragma unroll
    for (int mi=0;mi<2;mi++)
        #pragma unroll
        for (int ni=0;ni<4;ni++)
            #pragma unroll
            for (int q=0;q<4;q++) acc[mi][ni][q]=0.f;

    const int m0 = (wid & 3) * 32;
    const int n0 = (wid >> 2) * 32;
    const int arow  = (lane & 7) + ((lane >> 3) & 1) * 8;
    const int akoff = (lane >> 4) * 8;
    const int brow  = (lane & 7) + ((lane >> 4) & 1) * 8;
    const int bkoff = ((lane >> 3) & 1) * 8;

    issue(0, 0); CP_COMMIT();
    const int NCH = 16;
    for (int ch = 0; ch < NCH; ch++){
        int buf = ch & 1;
        if (ch + 1 < NCH){ issue(buf ^ 1, ch + 1); CP_COMMIT(); CP_WAIT(1); }
        else             { CP_WAIT(0); }
        __syncthreads();
        const unsigned a_h = uAh + buf*10240;
        const unsigned a_l = uAl + buf*10240;
        const unsigned b_h = uBh + buf*5120;
        const unsigned b_l = uBl + buf*5120;
        #pragma unroll
        for (int ks = 0; ks < 32; ks += 16){
            unsigned afh[2][4], afl[2][4], bfh[2][4], bfl[2][4];
            #pragma unroll
            for (int mi=0;mi<2;mi++){
                ldmx4(afh[mi], a_h + (unsigned)((m0 + mi*16 + arow)*VK_STR + ks + akoff)*2);
                ldmx4(afl[mi], a_l + (unsigned)((m0 + mi*16 + arow)*VK_STR + ks + akoff)*2);
            }
            #pragma unroll
            for (int g=0; g<2; g++){
                ldmx4(bfh[g], b_h + (unsigned)((n0 + g*16 + brow)*VK_STR + ks + bkoff)*2);
                ldmx4(bfl[g], b_l + (unsigned)((n0 + g*16 + brow)*VK_STR + ks + bkoff)*2);
            }
            #pragma unroll
            for (int mi=0;mi<2;mi++)
                #pragma unroll
                for (int ni=0;ni<4;ni++){
                    unsigned h0 = bfh[ni>>1][(ni&1)*2], h1 = bfh[ni>>1][(ni&1)*2+1];
                    unsigned l0 = bfl[ni>>1][(ni&1)*2], l1 = bfl[ni>>1][(ni&1)*2+1];
                    mma16816(acc[mi][ni], afh[mi], h0, h1);
                    mma16816(acc[mi][ni], afh[mi], l0, l1);
                    mma16816(acc[mi][ni], afl[mi], h0, h1);
                }
        }
        __syncthreads();
    }

    #pragma unroll
    for (int mi=0;mi<2;mi++){
        #pragma unroll
        for (int ni=0;ni<4;ni++){
            int row = mtile*128 + m0 + mi*16 + (lane >> 2);
            int col = ntile*64  + n0 + ni*8  + (lane & 3)*2;
            float bia0 = 0.f, bia1 = 0.f;
            if (bias1){ bia0 += bias1[col]; bia1 += bias1[col+1]; }
            if (bias2){ bia0 += bias2[col]; bia1 += bias2[col+1]; }
            float* o = C + (size_t)row*ldc + col;
            o[0] = acc[mi][ni][0] + bia0;
            o[1] = acc[mi][ni][1] + bia1;
            o += 8*ldc;
            o[0] = acc[mi][ni][2] + bia0;
            o[1] = acc[mi][ni][3] + bia1;
        }
    }
}

// ---------------------------------------------------------------------------
// gates-h-part GEMM, standalone version for t=0 prologue (loads own weights)
// ---------------------------------------------------------------------------
#define GSTR 72
#define ABUF 46080

__global__ void __launch_bounds__(256)
k_gh0()
{
    extern __shared__ char dsm[];
    const int tid = threadIdx.x;
    const int ct = blockIdx.x;
    const int nt = ct & 15, z2 = ct >> 4;
    const unsigned base = smem_u32(dsm);
    const int w = tid >> 5, l = tid & 31;
    const int nbase = nt * 128;
    const int n0 = w * 16;
    const int arow  = (l & 7) + ((l >> 3) & 1) * 8;
    const int akoff = (l >> 4) * 8;
    const int brow  = (l & 7) + ((l >> 4) & 1) * 8;
    const int bkoff = ((l >> 3) & 1) * 8;

    auto issue = [&](int buf, int ck){
        const int koff = 1024 + z2*128 + ck*64;
        const unsigned uAh = base + buf*ABUF;
        const unsigned uAl = uAh + 4608;
        const unsigned uBh = uAh + 9216;
        const unsigned uBl = uAh + 27648;
        #pragma unroll
        for (int q = 0; q < 10; q++){
            int i = q*256 + tid;
            if (i < 512){
                int idx = i & 255; int row = idx >> 3, c8 = idx & 7;
                const __nv_bfloat16* src = (i < 256 ? g_Xh : g_Xl)
                                           + (size_t)row*KX + koff + c8*8;
                unsigned dst = (i < 256 ? uAh : uAl) + (unsigned)(row*GSTR + c8*8)*2;
                cpa16(dst, src);
            } else {
                int idx = (i - 512) & 1023; int row = idx >> 3, c8 = idx & 7;
                const __nv_bfloat16* src = (i < 1536 ? g_gWh : g_gWl)
                                           + (size_t)(nbase+row)*KX + koff + c8*8;
                unsigned dst = (i < 1536 ? uBh : uBl) + (unsigned)(row*GSTR + c8*8)*2;
                cpa16(dst, src);
            }
        }
    };

    float acc[2][2][4];
    #pragma unroll
    for (int mi=0;mi<2;mi++)
        #pragma unroll
        for (int ni=0;ni<2;ni++)
            #pragma unroll
            for (int q=0;q<4;q++) acc[mi][ni][q]=0.f;

    issue(0, 0); CP_COMMIT();
    for (int ck = 0; ck < 2; ck++){
        int buf = ck;
        if (ck == 0){ issue(1, 1); CP_COMMIT(); CP_WAIT(1); }
        else        { CP_WAIT(0); }
        __syncthreads();
        const unsigned uAh = base + buf*ABUF;
        const unsigned uAl = uAh + 4608;
        const unsigned uBh = uAh + 9216;
        const unsigned uBl = uAh + 27648;
        #pragma unroll
        for (int ks = 0; ks < 64; ks += 16){
            unsigned afh[2][4], afl[2][4], bfh[4], bfl[4];
            #pragma unroll
            for (int mi=0;mi<2;mi++){
                ldmx4(afh[mi], uAh + (unsigned)((mi*16 + arow)*GSTR + ks + akoff)*2);
                ldmx4(afl[mi], uAl + (unsigned)((mi*16 + arow)*GSTR + ks + akoff)*2);
            }
            ldmx4(bfh, uBh + (unsigned)((n0 + brow)*GSTR + ks + bkoff)*2);
            ldmx4(bfl, uBl + (unsigned)((n0 + brow)*GSTR + ks + bkoff)*2);
            #pragma unroll
            for (int mi=0;mi<2;mi++)
                #pragma unroll
                for (int ni=0;ni<2;ni++){
                    mma16816(acc[mi][ni], afh[mi], bfh[ni*2], bfh[ni*2+1]);
                    mma16816(acc[mi][ni], afh[mi], bfl[ni*2], bfl[ni*2+1]);
                    mma16816(acc[mi][ni], afl[mi], bfh[ni*2], bfh[ni*2+1]);
                }
        }
        __syncthreads();
    }

    #pragma unroll
    for (int mi=0;mi<2;mi++){
        #pragma unroll
        for (int ni=0;ni<2;ni++){
            int row = mi*16 + (l >> 2);
            int col = nbase + n0 + ni*8 + (l & 3)*2;
            float* gp = g_GpartH + ((size_t)z2*BB + row)*JG + col;
            gp[0] = acc[mi][ni][0];
            gp[1] = acc[mi][ni][1];
            gp += 8*JG;
            gp[0] = acc[mi][ni][2];
            gp[1] = acc[mi][ni][3];
        }
    }
}

// ---------------------------------------------------------------------------
// convW slice (in-loop idle CTAs)
// ---------------------------------------------------------------------------
__device__ __forceinline__ void convW_item(const float* __restrict__ W, unsigned i4)
{
    size_t i = (size_t)i4 * 4;
    float4 v = *(const float4*)(W + i);
    __nv_bfloat16 h0, h1, h2, h3, l0, l1, l2, l3;
    bsplit(v.x, h0, l0); bsplit(v.y, h1, l1);
    bsplit(v.z, h2, l2); bsplit(v.w, h3, l3);
    *(__nv_bfloat162*)(g_Wh + i)     = __nv_bfloat162(h0, h1);
    *(__nv_bfloat162*)(g_Wh + i + 2) = __nv_bfloat162(h2, h3);
    *(__nv_bfloat162*)(g_Wl + i)     = __nv_bfloat162(l0, l1);
    *(__nv_bfloat162*)(g_Wl + i + 2) = __nv_bfloat162(l2, l3);
}

// ---------------------------------------------------------------------------
// Persistent recurrent loop with SMEM-RESIDENT weights.
// smem layout (131072B):
//  [0, 36864)        : phase-A B weights (Bh 18432 | Bl 18432)  [all CTAs]
//  [36864, 110592)   : CTAs>=64: gatesH weights (2 chunks x 36864)
//                      CTAs<64 : phase-C XC staging (65536 used)
//  [110592, 131072)  : scratch (A-tiles 9216/18432, phase-B hh/sc)
// ---------------------------------------------------------------------------
#define OFF_WHB 36864
#define OFF_XC  36864
#define OFF_SCR 110592

__global__ void __launch_bounds__(256)
k_loop(const int* __restrict__ lens, const float* __restrict__ enc,
       const float* __restrict__ W_c, const float* __restrict__ b_c,
       const float* __restrict__ W_o)
{
    extern __shared__ char dsm[];
    const int ct  = blockIdx.x;
    const int tid = threadIdx.x;
    const int w = tid >> 5, l = tid & 31;
    const unsigned base = smem_u32(dsm);

    const int nt = ct & 15;
    const int z  = ct >> 4;
    const int nbase = nt * 128;
    const int n0 = w * 16;
    const int arow  = (l & 7) + ((l >> 3) & 1) * 8;
    const int akoff = (l >> 4) * 8;
    const int brow  = (l & 7) + ((l >> 4) & 1) * 8;
    const int bkoff = ((l >> 3) & 1) * 8;

    // W_c row for phase C (CTAs 0..63)
    float wreg[32];
    float wbias = 0.f;
    if (ct < 64){
        const int c = ct*8 + w;
        const float* wr = W_c + (size_t)c*1024;
        #pragma unroll
        for (int q=0;q<32;q++) wreg[q] = wr[l + q*32];
        wbias = b_c[c];
    }

    // ---- pre-stage resident weights ----
    {
        // phase-A B weights: 128 rows x 64 cols (koff = 512 + z*64), hi+lo
        const int koff = 512 + z*64;
        #pragma unroll
        for (int q = 0; q < 8; q++){
            int i = q*256 + tid;                 // 0..2047
            int idx = i & 1023; int row = idx >> 3, c8 = idx & 7;
            const __nv_bfloat16* src = (i < 1024 ? g_gWh : g_gWl)
                                       + (size_t)(nbase+row)*KX + koff + c8*8;
            unsigned dst = base + (i < 1024 ? 0u : 18432u)
                         + (unsigned)(row*GSTR + c8*8)*2;
            cpa16(dst, src);
        }
        // gatesH weights for CTAs >= 64
        if (ct >= 64){
            const int nt2 = (ct-64) & 15, z2 = (ct-64) >> 4;
            const int nb2 = nt2 * 128;
            #pragma unroll
            for (int ck = 0; ck < 2; ck++){
                const int koff2 = 1024 + z2*128 + ck*64;
                #pragma unroll
                for (int q = 0; q < 8; q++){
                    int i = q*256 + tid;
                    int idx = i & 1023; int row = idx >> 3, c8 = idx & 7;
                    const __nv_bfloat16* src = (i < 1024 ? g_gWh : g_gWl)
                                               + (size_t)(nb2+row)*KX + koff2 + c8*8;
                    unsigned dst = base + OFF_WHB + (unsigned)ck*36864u
                                 + (i < 1024 ? 0u : 18432u)
                                 + (unsigned)(row*GSTR + c8*8)*2;
                    cpa16(dst, src);
                }
            }
        }
        CP_COMMIT(); CP_WAIT(0);
        __syncthreads();
    }

    unsigned nb = 0;

    for (int t = 0; t < T1; t++){
        // ===== Phase A: gates ah-part; A-tile load only (weights resident) =====
        {
            const unsigned uAh = base + OFF_SCR;
            const unsigned uAl = uAh + 4608;
            const unsigned uBh = base;
            const unsigned uBl = base + 18432;
            const int koff = 512 + z*64;
            #pragma unroll
            for (int q = 0; q < 2; q++){
                int i = q*256 + tid;                 // 0..511
                int idx = i & 255; int row = idx >> 3, c8 = idx & 7;
                const __nv_bfloat16* src = (i < 256 ? g_Xh : g_Xl)
                                           + (size_t)row*KX + koff + c8*8;
                unsigned dst = (i < 256 ? uAh : uAl) + (unsigned)(row*GSTR + c8*8)*2;
                cpa16(dst, src);
            }
            CP_COMMIT(); CP_WAIT(0);
            __syncthreads();

            float acc[2][2][4];
            #pragma unroll
            for (int mi=0;mi<2;mi++)
                #pragma unroll
                for (int ni=0;ni<2;ni++)
                    #pragma unroll
                    for (int q=0;q<4;q++) acc[mi][ni][q]=0.f;

            #pragma unroll
            for (int ks = 0; ks < 64; ks += 16){
                unsigned afh[2][4], afl[2][4], bfh[4], bfl[4];
                #pragma unroll
                for (int mi=0;mi<2;mi++){
                    ldmx4(afh[mi], uAh + (unsigned)((mi*16 + arow)*GSTR + ks + akoff)*2);
                    ldmx4(afl[mi], uAl + (unsigned)((mi*16 + arow)*GSTR + ks + akoff)*2);
                }
                ldmx4(bfh, uBh + (unsigned)((n0 + brow)*GSTR + ks + bkoff)*2);
                ldmx4(bfl, uBl + (unsigned)((n0 + brow)*GSTR + ks + bkoff)*2);
                #pragma unroll
                for (int mi=0;mi<2;mi++)
                    #pragma unroll
                    for (int ni=0;ni<2;ni++){
                        mma16816(acc[mi][ni], afh[mi], bfh[ni*2], bfh[ni*2+1]);
                        mma16816(acc[mi][ni], afh[mi], bfl[ni*2], bfl[ni*2+1]);
                        mma16816(acc[mi][ni], afl[mi], bfh[ni*2], bfh[ni*2+1]);
                    }
            }
            __syncthreads();

            #pragma unroll
            for (int mi=0;mi<2;mi++){
                #pragma unroll
                for (int ni=0;ni<2;ni++){
                    int row = mi*16 + (l >> 2);
                    int col = nbase + n0 + ni*8 + (l & 3)*2;
                    float* gp = g_GpartA + ((size_t)z*BB + row)*JG + col;
                    gp[0] = acc[mi][ni][0];
                    gp[1] = acc[mi][ni][1];
                    gp += 8*JG;
                    gp[0] = acc[mi][ni][2];
                    gp[1] = acc[mi][ni][3];
                }
            }
        }
        gbar(++nb * NCTA);

        // ===== Phase B: cell+attn (0..31) | convW (32..127) =====
        if (ct < BB){
            const int b = ct;
            float* hh = (float*)(dsm + OFF_SCR);
            float* sc = hh + HH;
            const int len = lens[b];

            #pragma unroll
            for (int rep = 0; rep < 2; rep++){
                int h = tid + rep*256;
                float gv[4];
                #pragma unroll
                for (int q=0;q<4;q++){
                    int j = q*HH + h;
                    float s = g_Gemb[((size_t)t*BB + b)*JG + j];
                    #pragma unroll
                    for (int zz=0;zz<8;zz++) s += g_GpartA[((size_t)zz*BB + b)*JG + j];
                    #pragma unroll
                    for (int zz=0;zz<4;zz++) s += g_GpartH[((size_t)zz*BB + b)*JG + j];
                    gv[q] = s;
                }
                int idx = b*HH + h;
                float ig = sigf(gv[0]);
                float fg = sigf(gv[1]);
                float gg = tanhf(gv[2]);
                float og = sigf(gv[3]);
                float c  = fg * g_c[idx] + ig * gg;
                g_c[idx] = c;
                float h2 = og * tanhf(c);
                g_h[idx] = h2;
                hh[h] = h2;
                g_XC[b*1024 + h] = h2;
                __nv_bfloat16 hi, lo; bsplit(h2, hi, lo);
                g_Xh[b*KX + 1024 + h] = hi;
                g_Xl[b*KX + 1024 + h] = lo;
            }
            __syncthreads();

            #pragma unroll
            for (int i = 0; i < 8; i++){
                int s = w*8 + i;
                const float* pr = &g_proj[((size_t)s*BB + b)*HH];
                float sum = 0.f;
                #pragma unroll
                for (int k = 0; k < 16; k++) sum += hh[l + k*32] * pr[l + k*32];
                #pragma unroll
                for (int off=16; off>0; off>>=1) sum += __shfl_xor_sync(0xffffffffu, sum, off);
                if (l == 0) sc[s] = (s < len) ? sum : -1e9f;
            }
            __syncthreads();

            if (tid < 32){
                float v0 = sc[tid], v1 = sc[tid+32];
                float m = fmaxf(v0, v1);
                #pragma unroll
                for (int off=16; off>0; off>>=1) m = fmaxf(m, __shfl_xor_sync(0xffffffffu, m, off));
                float e0 = expf(v0 - m), e1 = expf(v1 - m);
                float s = e0 + e1;
                #pragma unroll
                for (int off=16; off>0; off>>=1) s += __shfl_xor_sync(0xffffffffu, s, off);
                float inv = 1.0f / s;
                sc[tid]    = e0 * inv;
                sc[tid+32] = e1 * inv;
            }
            __syncthreads();

            #pragma unroll
            for (int rep = 0; rep < 2; rep++){
                int h = tid + rep*256;
                float a0=0.f, a1=0.f, a2=0.f, a3=0.f;
                #pragma unroll 4
                for (int s0 = 0; s0 < 16; s0++){
                    a0 += sc[s0]      * enc[((size_t)(s0)*BB    + b)*HH + h];
                    a1 += sc[s0 + 16] * enc[((size_t)(s0+16)*BB + b)*HH + h];
                    a2 += sc[s0 + 32] * enc[((size_t)(s0+32)*BB + b)*HH + h];
                    a3 += sc[s0 + 48] * enc[((size_t)(s0+48)*BB + b)*HH + h];
                }
                g_XC[b*1024 + 512 + h] = (a0 + a1) + (a2 + a3);
            }
        } else {
            unsigned winbase = (unsigned)t * 147456u;
            #pragma unroll
            for (int j = 0; j < 6; j++){
                unsigned i4 = winbase + (unsigned)j*24576u + (unsigned)(ct-32)*256u + tid;
                if (i4 < WF4) convW_item(W_o, i4);
            }
        }
        gbar(++nb * NCTA);

        // ===== Phase C: ah2 (0..63) | gates-h(t+1) w/ resident weights (64..127) =====
        if (ct < 64){
            float* xc = (float*)(dsm + OFF_XC);    // 16 batches per half
            const int c = ct*8 + w;
            #pragma unroll
            for (int half = 0; half < 2; half++){
                if (half) __syncthreads();
                {
                    const float4* src = (const float4*)(g_XC + half*16*1024);
                    float4* dst = (float4*)xc;
                    #pragma unroll
                    for (int i = 0; i < 16; i++) dst[tid + i*256] = src[tid + i*256];
                }
                __syncthreads();
                for (int b = 0; b < 16; b++){
                    const float* xb = xc + b*1024;
                    float s = 0.f;
                    #pragma unroll
                    for (int q=0;q<32;q++) s += wreg[q] * xb[l + q*32];
                    #pragma unroll
                    for (int off=16; off>0; off>>=1) s += __shfl_xor_sync(0xffffffffu, s, off);
                    if (l == 0){
                        int gb = half*16 + b;
                        float v = tanhf(s + wbias);
                        __nv_bfloat16 hi, lo; bsplit(v, hi, lo);
                        int r = t*BB + gb;
                        g_Ah[(size_t)r*HH + c] = hi;
                        g_Al[(size_t)r*HH + c] = lo;
                        g_Xh[gb*KX + 512 + c] = hi;
                        g_Xl[gb*KX + 512 + c] = lo;
                    }
                }
            }
        } else if (t + 1 < T1){
            // gates-h with resident weights; only A-tiles loaded (double-buffered)
            const int z2 = (ct-64) >> 4;
            const int nb2 = ((ct-64) & 15) * 128;
            const unsigned sA = base + OFF_SCR;    // 2 x 9216

            auto issueA = [&](int buf, int ck){
                const int koff = 1024 + z2*128 + ck*64;
                const unsigned uAh = sA + buf*9216;
                const unsigned uAl = uAh + 4608;
                #pragma unroll
                for (int q = 0; q < 2; q++){
                    int i = q*256 + tid;
                    int idx = i & 255; int row = idx >> 3, c8 = idx & 7;
                    const __nv_bfloat16* src = (i < 256 ? g_Xh : g_Xl)
                                               + (size_t)row*KX + koff + c8*8;
                    unsigned dst = (i < 256 ? uAh : uAl) + (unsigned)(row*GSTR + c8*8)*2;
                    cpa16(dst, src);
                }
            };

            float acc[2][2][4];
            #pragma unroll
            for (int mi=0;mi<2;mi++)
                #pragma unroll
                for (int ni=0;ni<2;ni++)
                    #pragma unroll
                    for (int q=0;q<4;q++) acc[mi][ni][q]=0.f;

            issueA(0, 0); CP_COMMIT();
            #pragma unroll
            for (int ck = 0; ck < 2; ck++){
                if (ck == 0){ issueA(1, 1); CP_COMMIT(); CP_WAIT(1); }
                else        { CP_WAIT(0); }
                __syncthreads();
                const unsigned uAh = sA + ck*9216;
                const unsigned uAl = uAh + 4608;
                const unsigned uBh = base + OFF_WHB + ck*36864;
                const unsigned uBl = uBh + 18432;
                #pragma unroll
                for (int ks = 0; ks < 64; ks += 16){
                    unsigned afh[2][4], afl[2][4], bfh[4], bfl[4];
                    #pragma unroll
                    for (int mi=0;mi<2;mi++){
                        ldmx4(afh[mi], uAh + (unsigned)((mi*16 + arow)*GSTR + ks + akoff)*2);
                        ldmx4(afl[mi], uAl + (unsigned)((mi*16 + arow)*GSTR + ks + akoff)*2);
                    }
                    ldmx4(bfh, uBh + (unsigned)((n0 + brow)*GSTR + ks + bkoff)*2);
                    ldmx4(bfl, uBl + (unsigned)((n0 + brow)*GSTR + ks + bkoff)*2);
                    #pragma unroll
                    for (int mi=0;mi<2;mi++)
                        #pragma unroll
                        for (int ni=0;ni<2;ni++){
                            mma16816(acc[mi][ni], afh[mi], bfh[ni*2], bfh[ni*2+1]);
                            mma16816(acc[mi][ni], afh[mi], bfl[ni*2], bfl[ni*2+1]);
                            mma16816(acc[mi][ni], afl[mi], bfh[ni*2], bfh[ni*2+1]);
                        }
                }
                __syncthreads();
            }

            #pragma unroll
            for (int mi=0;mi<2;mi++){
                #pragma unroll
                for (int ni=0;ni<2;ni++){
                    int row = mi*16 + (l >> 2);
                    int col = nb2 + n0 + ni*8 + (l & 3)*2;
                    float* gp = g_GpartH + ((size_t)z2*BB + row)*JG + col;
                    gp[0] = acc[mi][ni][0];
                    gp[1] = acc[mi][ni][1];
                    gp += 8*JG;
                    gp[0] = acc[mi][ni][2];
                    gp[1] = acc[mi][ni][3];
                }
            }
        }
        gbar(++nb * NCTA);
    }
}

// ---------------------------------------------------------------------------
// Vocab GEMM (proven single-pass 3-term)
// ---------------------------------------------------------------------------
__global__ void __launch_bounds__(256, 2)
k_vocab(const float* __restrict__ b_o, float* __restrict__ logits)
{
    extern __shared__ char vsm[];
    const int tid  = threadIdx.x;
    const int wid  = tid >> 5, lane = tid & 31;
    const int mtile = blockIdx.x;
    const int ntile = blockIdx.y;

    const __nv_bfloat16* Asrc_h = g_Ah + (size_t)mtile*128*HH;
    const __nv_bfloat16* Asrc_l = g_Al + (size_t)mtile*128*HH;
    const __nv_bfloat16* Bsrc_h = g_Wh + (size_t)ntile*64*HH;
    const __nv_bfloat16* Bsrc_l = g_Wl + (size_t)ntile*64*HH;

    const unsigned base = smem_u32(vsm);
    const unsigned uAh = base;
    const unsigned uAl = base + 20480;
    const unsigned uBh = base + 40960;
    const unsigned uBl = base + 51200;

    auto issue = [&](int buf, int ch){
        const int k0 = ch*32;
        const unsigned a_h = uAh + buf*10240;
        const unsigned a_l = uAl + buf*10240;
        const unsigned b_h = uBh + buf*5120;
        const unsigned b_l = uBl + buf*5120;
        #pragma unroll
        for (int q = 0; q < 6; q++){
            int i = q*256 + tid;
            if (i < 1024){
                int j = i & 511; int r = j >> 2, c8 = (j & 3)*8;
                const __nv_bfloat16* src = (i < 512 ? Asrc_h : Asrc_l)
                                           + (size_t)r*HH + k0 + c8;
                unsigned dst = (i < 512 ? a_h : a_l) + (unsigned)(r*VK_STR + c8)*2;
                cpa16(dst, src);
            } else {
                int j = (i - 1024) & 255; int r = j >> 2, c8 = (j & 3)*8;
                const __nv_bfloat16* src = (i < 1280 ? Bsrc_h : Bsrc_l)
                                           + (size_t)r*HH + k0 + c8;
                unsigned dst = (i < 1280 ? b_h : b_l) + (unsigned)(r*VK_STR + c8)*2;
                cpa16(dst, src);
            }
        }
    };

    float acc[2][4][4];
    #pragma unroll
    for (int mi=0;mi<2;mi++)
        #pragma unroll
        for (int ni=0;ni<4;ni++)
            #pragma unroll
            for (int q=0;q<4;q++) acc[mi][ni][q]=0.f;

    const int m0 = (wid & 3) * 32;
    const int n0 = (wid >> 2) * 32;
    const int arow  = (lane & 7) + ((lane >> 3) & 1) * 8;
    const int akoff = (lane >> 4) * 8;
    const int brow  = (lane & 7) + ((lane >> 4) & 1) * 8;
    const int bkoff = ((lane >> 3) & 1) * 8;

    issue(0, 0); CP_COMMIT();
    const int NCH = 16;
    for (int ch = 0; ch < NCH; ch++){
        int buf = ch & 1;
        if (ch + 1 < NCH){ issue(buf ^ 1, ch + 1); CP_COMMIT(); CP_WAIT(1); }
        else             { CP_WAIT(0); }
        __syncthreads();
        const unsigned a_h = uAh + buf*10240;
        const unsigned a_l = uAl + buf*10240;
        const unsigned b_h = uBh + buf*5120;
        const unsigned b_l = uBl + buf*5120;
        #pragma unroll
        for (int ks = 0; ks < 32; ks += 16){
            unsigned afh[2][4], afl[2][4], bfh[2][4], bfl[2][4];
            #pragma unroll
            for (int mi=0;mi<2;mi++){
                ldmx4(afh[mi], a_h + (unsigned)((m0 + mi*16 + arow)*VK_STR + ks + akoff)*2);
                ldmx4(afl[mi], a_l + (unsigned)((m0 + mi*16 + arow)*VK_STR + ks + akoff)*2);
            }
            #pragma unroll
            for (int g=0; g<2; g++){
                ldmx4(bfh[g], b_h + (unsigned)((n0 + g*16 + brow)*VK_STR + ks + bkoff)*2);
                ldmx4(bfl[g], b_l + (unsigned)((n0 + g*16 + brow)*VK_STR + ks + bkoff)*2);
            }
            #pragma unroll
            for (int mi=0;mi<2;mi++)
                #pragma unroll
                for (int ni=0;ni<4;ni++){
                    unsigned h0 = bfh[ni>>1][(ni&1)*2], h1 = bfh[ni>>1][(ni&1)*2+1];
                    unsigned l0 = bfl[ni>>1][(ni&1)*2], l1 = bfl[ni>>1][(ni&1)*2+1];
                    mma16816(acc[mi][ni], afh[mi], h0, h1);
                    mma16816(acc[mi][ni], afh[mi], l0, l1);
                    mma16816(acc[mi][ni], afl[mi], h0, h1);
                }
        }
        __syncthreads();
    }

    #pragma unroll
    for (int mi=0;mi<2;mi++){
        #pragma unroll
        for (int ni=0;ni<4;ni++){
            int row = mtile*128 + m0 + mi*16 + (lane >> 2);
            int col = ntile*64  + n0 + ni*8  + (lane & 3)*2;
            float bia0 = b_o[col], bia1 = b_o[col+1];
            if (row < T1*BB){
                float* o = logits + (size_t)row*VV + col;
                o[0] = acc[mi][ni][0] + bia0;
                o[1] = acc[mi][ni][1] + bia1;
            }
            if (row + 8 < T1*BB){
                float* o = logits + (size_t)(row+8)*VV + col;
                o[0] = acc[mi][ni][2] + bia0;
                o[1] = acc[mi][ni][3] + bia1;
            }
        }
    }
}

// ---------------------------------------------------------------------------
// Online log-softmax + argmax
// ---------------------------------------------------------------------------
__global__ void k_lsm(float* __restrict__ logits)
{
    __shared__ float ms[256], ss[256];
    __shared__ int   ii[256];
    const int row = blockIdx.x;
    const int tid = threadIdx.x;
    float* x = logits + (size_t)row * VV;

    float m = x[tid]; float s = 1.f; int mi = tid;
    for (int c = tid + 256; c < VV; c += 256){
        float v = x[c];
        if (v > m){ s = s*fexp(m - v) + 1.f; m = v; mi = c; }
        else       s += fexp(v - m);
    }
    ms[tid]=m; ss[tid]=s; ii[tid]=mi;
    __syncthreads();
    for (int st = 128; st > 0; st >>= 1){
        if (tid < st){
            float m1=ms[tid], s1=ss[tid]; int i1=ii[tid];
            float m2=ms[tid+st], s2=ss[tid+st]; int i2=ii[tid+st];
            if (m2 > m1)      { ms[tid]=m2; ss[tid]=s1*fexp(m1-m2)+s2; ii[tid]=i2; }
            else if (m2 < m1) { ss[tid]=s1+s2*fexp(m2-m1); }
            else              { ss[tid]=s1+s2; ii[tid]=min(i1,i2); }
        }
        __syncthreads();
    }
    float lse = ms[0] + logf(ss[0]);
    if (tid == 0) g_argmax[row] = ii[0];
    for (int c = tid; c < VV; c += 256) x[c] -= lse;
}

__global__ void k_tail_f(float* __restrict__ out)
{
    int r = blockIdx.x*blockDim.x + threadIdx.x;
    if (r < T1*BB) out[TBV + r] = (float)g_argmax[r];
}
__global__ void k_tail_i(int* __restrict__ out)
{
    int r = blockIdx.x*blockDim.x + threadIdx.x;
    if (r < T1*BB) out[r] = g_argmax[r];
}

// ---------------------------------------------------------------------------
extern "C" void kernel_launch(void* const* d_in, const int* in_sizes, int n_in,
                              void* d_out, int out_size)
{
    const int*   tgt   = (const int*)  d_in[0];
    const int*   lens  = (const int*)  d_in[1];
    const float* enc   = (const float*)d_in[2];
    const float* h0    = (const float*)d_in[3];
    const float* c0    = (const float*)d_in[4];
    const float* emb   = (const float*)d_in[5];
    const float* W_ih  = (const float*)d_in[6];
    const float* W_hh  = (const float*)d_in[7];
    const float* b_ih  = (const float*)d_in[8];
    const float* b_hh  = (const float*)d_in[9];
    const float* W_a   = (const float*)d_in[10];
    const float* W_c   = (const float*)d_in[11];
    const float* b_c   = (const float*)d_in[12];
    const float* W_o   = (const float*)d_in[13];
    const float* b_o   = (const float*)d_in[14];

    float *p_proj=nullptr, *p_lg=nullptr, *p_gemb=nullptr;
    __nv_bfloat16 *p_eh=nullptr, *p_el=nullptr, *p_gwh=nullptr, *p_gwl=nullptr;
    __nv_bfloat16 *p_enh=nullptr, *p_enl=nullptr, *p_wah=nullptr, *p_wal=nullptr;
    cudaGetSymbolAddress((void**)&p_proj, g_proj);
    cudaGetSymbolAddress((void**)&p_lg,   g_logits);
    cudaGetSymbolAddress((void**)&p_gemb, g_Gemb);
    cudaGetSymbolAddress((void**)&p_eh,   g_Eh);
    cudaGetSymbolAddress((void**)&p_el,   g_El);
    cudaGetSymbolAddress((void**)&p_gwh,  g_gWh);
    cudaGetSymbolAddress((void**)&p_gwl,  g_gWl);
    cudaGetSymbolAddress((void**)&p_enh,  g_ENh);
    cudaGetSymbolAddress((void**)&p_enl,  g_ENl);
    cudaGetSymbolAddress((void**)&p_wah,  g_WAh);
    cudaGetSymbolAddress((void**)&p_wal,  g_WAl);

    const bool big = (size_t)out_size >= TBV;
    float* logits = big ? (float*)d_out : p_lg;

    cudaFuncSetAttribute(k_loop,   cudaFuncAttributeMaxDynamicSharedMemorySize, 131072);
    cudaFuncSetAttribute(k_gh0,    cudaFuncAttributeMaxDynamicSharedMemorySize, 2*ABUF);
    cudaFuncSetAttribute(k_vocab,  cudaFuncAttributeMaxDynamicSharedMemorySize, 61440);
    cudaFuncSetAttribute(k_hmm,    cudaFuncAttributeMaxDynamicSharedMemorySize, 61440);

    // prologue
    k_prep0<<<64, 256>>>(h0, c0);
    k_gemb<<<512, 256>>>(tgt, emb);
    k_convG<<<(int)(((size_t)JG*KX/4 + 255)/256), 256>>>(W_ih, W_hh);
    k_convEA<<<(int)(((2048u*HH + HH*HH)/4 + 255)/256), 256>>>(enc, W_a);
    // Gemb = E @ gW[:,0:512]^T + biases  : [1024, 2048]
    k_hmm<<<dim3(8, 32), 256, 61440>>>(p_eh, p_el, EE, p_gwh, p_gwl, KX,
                                       p_gemb, JG, b_ih, b_hh);
    // proj = enc @ W_a^T : [2048, 512]
    k_hmm<<<dim3(16, 8), 256, 61440>>>(p_enh, p_enl, HH, p_wah, p_wal, HH,
                                       p_proj, HH, nullptr, nullptr);
    k_gh0<<<64, 256, 2*ABUF>>>();

    // persistent recurrent loop (resident weights)
    k_loop<<<NCTA, 256, 131072>>>(lens, enc, W_c, b_c, W_o);

    // vocab projection + log-softmax
    k_vocab<<<dim3(8, 500), 256, 61440>>>(b_o, logits);
    k_lsm<<<T1*BB, 256>>>(logits);

    if (big && (size_t)out_size >= TBV + (size_t)T1*BB) {
        k_tail_f<<<4, 256>>>((float*)d_out);
    } else if (!big) {
        k_tail_i<<<4, 256>>>((int*)d_out);
    }
}

// round 13
// speedup vs baseline: 1.3735x; 1.0488x over previous
#include <cuda_runtime.h>
#include <cuda_bf16.h>
#include <math.h>

// Problem constants
#define BB 32
#define TT 32
#define SS 64
#define HH 512
#define EE 512
#define VV 32000
#define T1 (TT-1)
#define TBV ((size_t)T1*BB*VV)
#define BH (BB*HH)
#define MPAD 1024
#define KX 1536
#define JG 2048
#define NCTA 128
#define WF4 4096000u    // VV*HH/4

// -------- persistent device scratch --------
__device__ float g_h[BH];
__device__ float g_c[BH];
__device__ float g_proj[2048*HH];
__device__ __align__(16) float g_XC[BB*1024];
__device__ float g_GpartA[8*BB*JG];
__device__ float g_GpartH[4*BB*JG];
__device__ float g_Gemb[MPAD*JG];
__device__ int   g_argmax[T1*BB];
__device__ float g_logits[T1*BB*VV];
__device__ __align__(16) __nv_bfloat16 g_Wh[(size_t)VV*HH];
__device__ __align__(16) __nv_bfloat16 g_Wl[(size_t)VV*HH];
__device__ __align__(16) __nv_bfloat16 g_Ah[MPAD*HH];   // rows 992..1023 stay 0
__device__ __align__(16) __nv_bfloat16 g_Al[MPAD*HH];
__device__ __align__(16) __nv_bfloat16 g_gWh[JG*KX];
__device__ __align__(16) __nv_bfloat16 g_gWl[JG*KX];
__device__ __align__(16) __nv_bfloat16 g_Xh[BB*KX];
__device__ __align__(16) __nv_bfloat16 g_Xl[BB*KX];
__device__ __align__(16) __nv_bfloat16 g_Eh[MPAD*EE];
__device__ __align__(16) __nv_bfloat16 g_El[MPAD*EE];
__device__ __align__(16) __nv_bfloat16 g_ENh[2048*HH];
__device__ __align__(16) __nv_bfloat16 g_ENl[2048*HH];
__device__ __align__(16) __nv_bfloat16 g_WAh[HH*HH];
__device__ __align__(16) __nv_bfloat16 g_WAl[HH*HH];
__device__ unsigned g_barcnt;

__device__ __forceinline__ float sigf(float x){ return 1.0f/(1.0f+expf(-x)); }

__device__ __forceinline__ float fexp(float x){
    float t = x * 1.4426950408889634f;
    float n = rintf(t);
    float f = t - n;
    float p = 1.5403530e-4f;
    p = fmaf(p, f, 1.3333558e-3f);
    p = fmaf(p, f, 9.6181291e-3f);
    p = fmaf(p, f, 5.5504109e-2f);
    p = fmaf(p, f, 2.4022651e-1f);
    p = fmaf(p, f, 6.9314718e-1f);
    p = fmaf(p, f, 1.0f);
    int e = (int)n;
    e = e < -126 ? -126 : (e > 127 ? 127 : e);
    float sc = __int_as_float((e+127)<<23);
    return p*sc;
}

// ------------------ low-level helpers ------------------
__device__ __forceinline__ unsigned smem_u32(const void* p){
    unsigned a;
    asm("{ .reg .u64 t; cvta.to.shared.u64 t, %1; cvt.u32.u64 %0, t; }" : "=r"(a) : "l"(p));
    return a;
}
__device__ __forceinline__ void cpa16(unsigned dst, const void* src){
    asm volatile("cp.async.cg.shared.global [%0], [%1], 16;" :: "r"(dst), "l"(src));
}
#define CP_COMMIT() asm volatile("cp.async.commit_group;" ::: "memory")
#define CP_WAIT(n)  asm volatile("cp.async.wait_group %0;" :: "n"(n) : "memory")

__device__ __forceinline__ void ldmx4(unsigned* r, unsigned addr){
    asm volatile("ldmatrix.sync.aligned.m8n8.x4.shared.b16 {%0,%1,%2,%3}, [%4];"
        : "=r"(r[0]), "=r"(r[1]), "=r"(r[2]), "=r"(r[3]) : "r"(addr));
}
__device__ __forceinline__ void mma16816(float* d, const unsigned* a,
                                         unsigned b0, unsigned b1){
    asm volatile(
        "mma.sync.aligned.m16n8k16.row.col.f32.bf16.bf16.f32 "
        "{%0,%1,%2,%3}, {%4,%5,%6,%7}, {%8,%9}, {%0,%1,%2,%3};"
        : "+f"(d[0]), "+f"(d[1]), "+f"(d[2]), "+f"(d[3])
        : "r"(a[0]), "r"(a[1]), "r"(a[2]), "r"(a[3]), "r"(b0), "r"(b1));
}
__device__ __forceinline__ void bsplit(float v, __nv_bfloat16& hi, __nv_bfloat16& lo){
    hi = __float2bfloat16(v);
    lo = __float2bfloat16(v - __bfloat162float(hi));
}

// PROVEN R10 spin grid barrier: sc-fence + atomicAdd arrive, acquire poll.
__device__ __forceinline__ void gbar(unsigned target){
    __syncthreads();
    if (threadIdx.x == 0){
        __threadfence();
        atomicAdd(&g_barcnt, 1u);
        unsigned v;
        do {
            asm volatile("ld.global.acquire.gpu.b32 %0, [%1];"
                         : "=r"(v) : "l"(&g_barcnt));
        } while (v < target);
    }
    __syncthreads();
}

// ---------------------------------------------------------------------------
// Prologue: h,c init + X (ah=0, h=h0) + barrier reset
// ---------------------------------------------------------------------------
__global__ void k_prep0(const float* __restrict__ h0, const float* __restrict__ c0)
{
    if (blockIdx.x == 0 && threadIdx.x == 0) g_barcnt = 0;
    int idx = blockIdx.x*256 + threadIdx.x;
    int b = idx >> 9, k = idx & 511;
    g_h[idx] = h0[idx];
    g_c[idx] = c0[idx];
    __nv_bfloat16 hi, lo;
    g_Xh[b*KX + 512 + k] = __float2bfloat16(0.f);
    g_Xl[b*KX + 512 + k] = __float2bfloat16(0.f);
    bsplit(h0[idx], hi, lo);
    g_Xh[b*KX + 1024 + k] = hi;  g_Xl[b*KX + 1024 + k] = lo;
}

// ---------------------------------------------------------------------------
// Merged conversion prologue — FIXED block partition:
//  blocks [0,512)      : emb gather       (1024x512  ->  512 blocks)
//  blocks [512,3584)   : gate weights     (2048x1536 -> 3072 blocks)
//  blocks [3584,4864)  : enc + W_a split  (          -> 1280 blocks)
// ---------------------------------------------------------------------------
__global__ void k_convall(const int* __restrict__ tgt, const float* __restrict__ emb,
                          const float* __restrict__ W_ih, const float* __restrict__ W_hh,
                          const float* __restrict__ enc, const float* __restrict__ W_a)
{
    const int blk = blockIdx.x;
    if (blk < 512){
        int i = (blk*256 + threadIdx.x)*4;
        int r = i >> 9, k = i & 511;
        float4 v = make_float4(0.f,0.f,0.f,0.f);
        if (r < T1*BB){
            int t = r >> 5, b = r & 31;
            int w = tgt[b*TT + t];
            v = *(const float4*)(emb + (size_t)w*EE + k);
        }
        __nv_bfloat16 h0,h1,h2,h3,l0,l1,l2,l3;
        bsplit(v.x,h0,l0); bsplit(v.y,h1,l1); bsplit(v.z,h2,l2); bsplit(v.w,h3,l3);
        *(__nv_bfloat162*)(g_Eh + i)     = __nv_bfloat162(h0,h1);
        *(__nv_bfloat162*)(g_Eh + i + 2) = __nv_bfloat162(h2,h3);
        *(__nv_bfloat162*)(g_El + i)     = __nv_bfloat162(l0,l1);
        *(__nv_bfloat162*)(g_El + i + 2) = __nv_bfloat162(l2,l3);
    } else if (blk < 3584){
        size_t i = ((size_t)(blk-512)*256 + threadIdx.x)*4;
        if (i >= (size_t)JG*KX) return;
        int j = (int)(i / KX);
        int k = (int)(i % KX);
        float4 v = (k < 1024) ? *(const float4*)(W_ih + (size_t)j*1024 + k)
                              : *(const float4*)(W_hh + (size_t)j*512 + (k-1024));
        __nv_bfloat16 h, l;
        bsplit(v.x, h, l); g_gWh[i+0]=h; g_gWl[i+0]=l;
        bsplit(v.y, h, l); g_gWh[i+1]=h; g_gWl[i+1]=l;
        bsplit(v.z, h, l); g_gWh[i+2]=h; g_gWl[i+2]=l;
        bsplit(v.w, h, l); g_gWh[i+3]=h; g_gWl[i+3]=l;
    } else {
        size_t i = ((size_t)(blk-3584)*256 + threadIdx.x)*4;
        const size_t NE = (size_t)2048*HH;
        if (i >= NE + (size_t)HH*HH) return;
        const float* src; __nv_bfloat16 *dh, *dl; size_t off;
        if (i < NE){ src = enc;  dh = g_ENh; dl = g_ENl; off = i; }
        else       { src = W_a;  dh = g_WAh; dl = g_WAl; off = i - NE; }
        float4 v = *(const float4*)(src + off);
        __nv_bfloat16 h0,h1,h2,h3,l0,l1,l2,l3;
        bsplit(v.x,h0,l0); bsplit(v.y,h1,l1); bsplit(v.z,h2,l2); bsplit(v.w,h3,l3);
        *(__nv_bfloat162*)(dh + off)     = __nv_bfloat162(h0,h1);
        *(__nv_bfloat162*)(dh + off + 2) = __nv_bfloat162(h2,h3);
        *(__nv_bfloat162*)(dl + off)     = __nv_bfloat162(l0,l1);
        *(__nv_bfloat162*)(dl + off + 2) = __nv_bfloat162(l2,l3);
    }
}

// ---------------------------------------------------------------------------
// Generic HMMA GEMM (prologue: Gemb, proj)
// ---------------------------------------------------------------------------
#define VK_STR 40

__global__ void __launch_bounds__(256, 2)
k_hmm(const __nv_bfloat16* __restrict__ Ah, const __nv_bfloat16* __restrict__ Al, int lda,
      const __nv_bfloat16* __restrict__ Bh, const __nv_bfloat16* __restrict__ Bl, int ldb,
      float* __restrict__ C, int ldc,
      const float* __restrict__ bias1, const float* __restrict__ bias2)
{
    extern __shared__ char vsm[];
    const int tid  = threadIdx.x;
    const int wid  = tid >> 5, lane = tid & 31;
    const int mtile = blockIdx.x;
    const int ntile = blockIdx.y;

    const __nv_bfloat16* Asrc_h = Ah + (size_t)mtile*128*lda;
    const __nv_bfloat16* Asrc_l = Al + (size_t)mtile*128*lda;
    const __nv_bfloat16* Bsrc_h = Bh + (size_t)ntile*64*ldb;
    const __nv_bfloat16* Bsrc_l = Bl + (size_t)ntile*64*ldb;

    const unsigned base = smem_u32(vsm);
    const unsigned uAh = base;
    const unsigned uAl = base + 20480;
    const unsigned uBh = base + 40960;
    const unsigned uBl = base + 51200;

    auto issue = [&](int buf, int ch){
        const int k0 = ch*32;
        const unsigned a_h = uAh + buf*10240;
        const unsigned a_l = uAl + buf*10240;
        const unsigned b_h = uBh + buf*5120;
        const unsigned b_l = uBl + buf*5120;
        #pragma unroll
        for (int q = 0; q < 6; q++){
            int i = q*256 + tid;
            if (i < 1024){
                int j = i & 511; int r = j >> 2, c8 = (j & 3)*8;
                const __nv_bfloat16* src = (i < 512 ? Asrc_h : Asrc_l)
                                           + (size_t)r*lda + k0 + c8;
                unsigned dst = (i < 512 ? a_h : a_l) + (unsigned)(r*VK_STR + c8)*2;
                cpa16(dst, src);
            } else {
                int j = (i - 1024) & 255; int r = j >> 2, c8 = (j & 3)*8;
                const __nv_bfloat16* src = (i < 1280 ? Bsrc_h : Bsrc_l)
                                           + (size_t)r*ldb + k0 + c8;
                unsigned dst = (i < 1280 ? b_h : b_l) + (unsigned)(r*VK_STR + c8)*2;
                cpa16(dst, src);
            }
        }
    };

    float acc[2][4][4];
    #pragma unroll
    for (int mi=0;mi<2;mi++)
        #pragma unroll
        for (int ni=0;ni<4;ni++)
            #pragma unroll
            for (int q=0;q<4;q++) acc[mi][ni][q]=0.f;

    const int m0 = (wid & 3) * 32;
    const int n0 = (wid >> 2) * 32;
    const int arow  = (lane & 7) + ((lane >> 3) & 1) * 8;
    const int akoff = (lane >> 4) * 8;
    const int brow  = (lane & 7) + ((lane >> 4) & 1) * 8;
    const int bkoff = ((lane >> 3) & 1) * 8;

    issue(0, 0); CP_COMMIT();
    const int NCH = 16;
    for (int ch = 0; ch < NCH; ch++){
        int buf = ch & 1;
        if (ch + 1 < NCH){ issue(buf ^ 1, ch + 1); CP_COMMIT(); CP_WAIT(1); }
        else             { CP_WAIT(0); }
        __syncthreads();
        const unsigned a_h = uAh + buf*10240;
        const unsigned a_l = uAl + buf*10240;
        const unsigned b_h = uBh + buf*5120;
        const unsigned b_l = uBl + buf*5120;
        #pragma unroll
        for (int ks = 0; ks < 32; ks += 16){
            unsigned afh[2][4], afl[2][4], bfh[2][4], bfl[2][4];
            #pragma unroll
            for (int mi=0;mi<2;mi++){
                ldmx4(afh[mi], a_h + (unsigned)((m0 + mi*16 + arow)*VK_STR + ks + akoff)*2);
                ldmx4(afl[mi], a_l + (unsigned)((m0 + mi*16 + arow)*VK_STR + ks + akoff)*2);
            }
            #pragma unroll
            for (int g=0; g<2; g++){
                ldmx4(bfh[g], b_h + (unsigned)((n0 + g*16 + brow)*VK_STR + ks + bkoff)*2);
                ldmx4(bfl[g], b_l + (unsigned)((n0 + g*16 + brow)*VK_STR + ks + bkoff)*2);
            }
            #pragma unroll
            for (int mi=0;mi<2;mi++)
                #pragma unroll
                for (int ni=0;ni<4;ni++){
                    unsigned h0 = bfh[ni>>1][(ni&1)*2], h1 = bfh[ni>>1][(ni&1)*2+1];
                    unsigned l0 = bfl[ni>>1][(ni&1)*2], l1 = bfl[ni>>1][(ni&1)*2+1];
                    mma16816(acc[mi][ni], afh[mi], h0, h1);
                    mma16816(acc[mi][ni], afh[mi], l0, l1);
                    mma16816(acc[mi][ni], afl[mi], h0, h1);
                }
        }
        __syncthreads();
    }

    #pragma unroll
    for (int mi=0;mi<2;mi++){
        #pragma unroll
        for (int ni=0;ni<4;ni++){
            int row = mtile*128 + m0 + mi*16 + (lane >> 2);
            int col = ntile*64  + n0 + ni*8  + (lane & 3)*2;
            float bia0 = 0.f, bia1 = 0.f;
            if (bias1){ bia0 += bias1[col]; bia1 += bias1[col+1]; }
            if (bias2){ bia0 += bias2[col]; bia1 += bias2[col+1]; }
            float* o = C + (size_t)row*ldc + col;
            o[0] = acc[mi][ni][0] + bia0;
            o[1] = acc[mi][ni][1] + bia1;
            o += 8*ldc;
            o[0] = acc[mi][ni][2] + bia0;
            o[1] = acc[mi][ni][3] + bia1;
        }
    }
}

// ---------------------------------------------------------------------------
// gates-h-part GEMM, standalone for t=0 prologue
// ---------------------------------------------------------------------------
#define GSTR 72
#define ABUF 46080

__global__ void __launch_bounds__(256)
k_gh0()
{
    extern __shared__ char dsm[];
    const int tid = threadIdx.x;
    const int ct = blockIdx.x;
    const int nt = ct & 15, z2 = ct >> 4;
    const unsigned base = smem_u32(dsm);
    const int w = tid >> 5, l = tid & 31;
    const int nbase = nt * 128;
    const int n0 = w * 16;
    const int arow  = (l & 7) + ((l >> 3) & 1) * 8;
    const int akoff = (l >> 4) * 8;
    const int brow  = (l & 7) + ((l >> 4) & 1) * 8;
    const int bkoff = ((l >> 3) & 1) * 8;

    auto issue = [&](int buf, int ck){
        const int koff = 1024 + z2*128 + ck*64;
        const unsigned uAh = base + buf*ABUF;
        const unsigned uAl = uAh + 4608;
        const unsigned uBh = uAh + 9216;
        const unsigned uBl = uAh + 27648;
        #pragma unroll
        for (int q = 0; q < 10; q++){
            int i = q*256 + tid;
            if (i < 512){
                int idx = i & 255; int row = idx >> 3, c8 = idx & 7;
                const __nv_bfloat16* src = (i < 256 ? g_Xh : g_Xl)
                                           + (size_t)row*KX + koff + c8*8;
                unsigned dst = (i < 256 ? uAh : uAl) + (unsigned)(row*GSTR + c8*8)*2;
                cpa16(dst, src);
            } else {
                int idx = (i - 512) & 1023; int row = idx >> 3, c8 = idx & 7;
                const __nv_bfloat16* src = (i < 1536 ? g_gWh : g_gWl)
                                           + (size_t)(nbase+row)*KX + koff + c8*8;
                unsigned dst = (i < 1536 ? uBh : uBl) + (unsigned)(row*GSTR + c8*8)*2;
                cpa16(dst, src);
            }
        }
    };

    float acc[2][2][4];
    #pragma unroll
    for (int mi=0;mi<2;mi++)
        #pragma unroll
        for (int ni=0;ni<2;ni++)
            #pragma unroll
            for (int q=0;q<4;q++) acc[mi][ni][q]=0.f;

    issue(0, 0); CP_COMMIT();
    for (int ck = 0; ck < 2; ck++){
        int buf = ck;
        if (ck == 0){ issue(1, 1); CP_COMMIT(); CP_WAIT(1); }
        else        { CP_WAIT(0); }
        __syncthreads();
        const unsigned uAh = base + buf*ABUF;
        const unsigned uAl = uAh + 4608;
        const unsigned uBh = uAh + 9216;
        const unsigned uBl = uAh + 27648;
        #pragma unroll
        for (int ks = 0; ks < 64; ks += 16){
            unsigned afh[2][4], afl[2][4], bfh[4], bfl[4];
            #pragma unroll
            for (int mi=0;mi<2;mi++){
                ldmx4(afh[mi], uAh + (unsigned)((mi*16 + arow)*GSTR + ks + akoff)*2);
                ldmx4(afl[mi], uAl + (unsigned)((mi*16 + arow)*GSTR + ks + akoff)*2);
            }
            ldmx4(bfh, uBh + (unsigned)((n0 + brow)*GSTR + ks + bkoff)*2);
            ldmx4(bfl, uBl + (unsigned)((n0 + brow)*GSTR + ks + bkoff)*2);
            #pragma unroll
            for (int mi=0;mi<2;mi++)
                #pragma unroll
                for (int ni=0;ni<2;ni++){
                    mma16816(acc[mi][ni], afh[mi], bfh[ni*2], bfh[ni*2+1]);
                    mma16816(acc[mi][ni], afh[mi], bfl[ni*2], bfl[ni*2+1]);
                    mma16816(acc[mi][ni], afl[mi], bfh[ni*2], bfh[ni*2+1]);
                }
        }
        __syncthreads();
    }

    #pragma unroll
    for (int mi=0;mi<2;mi++){
        #pragma unroll
        for (int ni=0;ni<2;ni++){
            int row = mi*16 + (l >> 2);
            int col = nbase + n0 + ni*8 + (l & 3)*2;
            float* gp = g_GpartH + ((size_t)z2*BB + row)*JG + col;
            gp[0] = acc[mi][ni][0];
            gp[1] = acc[mi][ni][1];
            gp += 8*JG;
            gp[0] = acc[mi][ni][2];
            gp[1] = acc[mi][ni][3];
        }
    }
}

// ---------------------------------------------------------------------------
// convW slice (in-loop idle CTAs)
// ---------------------------------------------------------------------------
__device__ __forceinline__ void convW_item(const float* __restrict__ W, unsigned i4)
{
    size_t i = (size_t)i4 * 4;
    float4 v = *(const float4*)(W + i);
    __nv_bfloat16 h0, h1, h2, h3, l0, l1, l2, l3;
    bsplit(v.x, h0, l0); bsplit(v.y, h1, l1);
    bsplit(v.z, h2, l2); bsplit(v.w, h3, l3);
    *(__nv_bfloat162*)(g_Wh + i)     = __nv_bfloat162(h0, h1);
    *(__nv_bfloat162*)(g_Wh + i + 2) = __nv_bfloat162(h2, h3);
    *(__nv_bfloat162*)(g_Wl + i)     = __nv_bfloat162(l0, l1);
    *(__nv_bfloat162*)(g_Wl + i + 2) = __nv_bfloat162(l2, l3);
}

// ---------------------------------------------------------------------------
// Persistent recurrent loop with SMEM-resident weights (proven R10)
// ---------------------------------------------------------------------------
#define OFF_WHB 36864
#define OFF_XC  36864
#define OFF_SCR 110592

__global__ void __launch_bounds__(256)
k_loop(const int* __restrict__ lens, const float* __restrict__ enc,
       const float* __restrict__ W_c, const float* __restrict__ b_c,
       const float* __restrict__ W_o)
{
    extern __shared__ char dsm[];
    const int ct  = blockIdx.x;
    const int tid = threadIdx.x;
    const int w = tid >> 5, l = tid & 31;
    const unsigned base = smem_u32(dsm);

    const int nt = ct & 15;
    const int z  = ct >> 4;
    const int nbase = nt * 128;
    const int n0 = w * 16;
    const int arow  = (l & 7) + ((l >> 3) & 1) * 8;
    const int akoff = (l >> 4) * 8;
    const int brow  = (l & 7) + ((l >> 4) & 1) * 8;
    const int bkoff = ((l >> 3) & 1) * 8;

    float wreg[32];
    float wbias = 0.f;
    if (ct < 64){
        const int c = ct*8 + w;
        const float* wr = W_c + (size_t)c*1024;
        #pragma unroll
        for (int q=0;q<32;q++) wreg[q] = wr[l + q*32];
        wbias = b_c[c];
    }

    // pre-stage resident weights
    {
        const int koff = 512 + z*64;
        #pragma unroll
        for (int q = 0; q < 8; q++){
            int i = q*256 + tid;
            int idx = i & 1023; int row = idx >> 3, c8 = idx & 7;
            const __nv_bfloat16* src = (i < 1024 ? g_gWh : g_gWl)
                                       + (size_t)(nbase+row)*KX + koff + c8*8;
            unsigned dst = base + (i < 1024 ? 0u : 18432u)
                         + (unsigned)(row*GSTR + c8*8)*2;
            cpa16(dst, src);
        }
        if (ct >= 64){
            const int nt2 = (ct-64) & 15, z2 = (ct-64) >> 4;
            const int nb2 = nt2 * 128;
            #pragma unroll
            for (int ck = 0; ck < 2; ck++){
                const int koff2 = 1024 + z2*128 + ck*64;
                #pragma unroll
                for (int q = 0; q < 8; q++){
                    int i = q*256 + tid;
                    int idx = i & 1023; int row = idx >> 3, c8 = idx & 7;
                    const __nv_bfloat16* src = (i < 1024 ? g_gWh : g_gWl)
                                               + (size_t)(nb2+row)*KX + koff2 + c8*8;
                    unsigned dst = base + OFF_WHB + (unsigned)ck*36864u
                                 + (i < 1024 ? 0u : 18432u)
                                 + (unsigned)(row*GSTR + c8*8)*2;
                    cpa16(dst, src);
                }
            }
        }
        CP_COMMIT(); CP_WAIT(0);
        __syncthreads();
    }

    unsigned nb = 0;

    for (int t = 0; t < T1; t++){
        // ===== Phase A =====
        {
            const unsigned uAh = base + OFF_SCR;
            const unsigned uAl = uAh + 4608;
            const unsigned uBh = base;
            const unsigned uBl = base + 18432;
            const int koff = 512 + z*64;
            #pragma unroll
            for (int q = 0; q < 2; q++){
                int i = q*256 + tid;
                int idx = i & 255; int row = idx >> 3, c8 = idx & 7;
                const __nv_bfloat16* src = (i < 256 ? g_Xh : g_Xl)
                                           + (size_t)row*KX + koff + c8*8;
                unsigned dst = (i < 256 ? uAh : uAl) + (unsigned)(row*GSTR + c8*8)*2;
                cpa16(dst, src);
            }
            CP_COMMIT(); CP_WAIT(0);
            __syncthreads();

            float acc[2][2][4];
            #pragma unroll
            for (int mi=0;mi<2;mi++)
                #pragma unroll
                for (int ni=0;ni<2;ni++)
                    #pragma unroll
                    for (int q=0;q<4;q++) acc[mi][ni][q]=0.f;

            #pragma unroll
            for (int ks = 0; ks < 64; ks += 16){
                unsigned afh[2][4], afl[2][4], bfh[4], bfl[4];
                #pragma unroll
                for (int mi=0;mi<2;mi++){
                    ldmx4(afh[mi], uAh + (unsigned)((mi*16 + arow)*GSTR + ks + akoff)*2);
                    ldmx4(afl[mi], uAl + (unsigned)((mi*16 + arow)*GSTR + ks + akoff)*2);
                }
                ldmx4(bfh, uBh + (unsigned)((n0 + brow)*GSTR + ks + bkoff)*2);
                ldmx4(bfl, uBl + (unsigned)((n0 + brow)*GSTR + ks + bkoff)*2);
                #pragma unroll
                for (int mi=0;mi<2;mi++)
                    #pragma unroll
                    for (int ni=0;ni<2;ni++){
                        mma16816(acc[mi][ni], afh[mi], bfh[ni*2], bfh[ni*2+1]);
                        mma16816(acc[mi][ni], afh[mi], bfl[ni*2], bfl[ni*2+1]);
                        mma16816(acc[mi][ni], afl[mi], bfh[ni*2], bfh[ni*2+1]);
                    }
            }
            __syncthreads();

            #pragma unroll
            for (int mi=0;mi<2;mi++){
                #pragma unroll
                for (int ni=0;ni<2;ni++){
                    int row = mi*16 + (l >> 2);
                    int col = nbase + n0 + ni*8 + (l & 3)*2;
                    float* gp = g_GpartA + ((size_t)z*BB + row)*JG + col;
                    gp[0] = acc[mi][ni][0];
                    gp[1] = acc[mi][ni][1];
                    gp += 8*JG;
                    gp[0] = acc[mi][ni][2];
                    gp[1] = acc[mi][ni][3];
                }
            }
        }
        gbar(++nb * NCTA);

        // ===== Phase B =====
        if (ct < BB){
            const int b = ct;
            float* hh = (float*)(dsm + OFF_SCR);
            float* sc = hh + HH;
            const int len = lens[b];

            #pragma unroll
            for (int rep = 0; rep < 2; rep++){
                int h = tid + rep*256;
                float gv[4];
                #pragma unroll
                for (int q=0;q<4;q++){
                    int j = q*HH + h;
                    float s = g_Gemb[((size_t)t*BB + b)*JG + j];
                    #pragma unroll
                    for (int zz=0;zz<8;zz++) s += g_GpartA[((size_t)zz*BB + b)*JG + j];
                    #pragma unroll
                    for (int zz=0;zz<4;zz++) s += g_GpartH[((size_t)zz*BB + b)*JG + j];
                    gv[q] = s;
                }
                int idx = b*HH + h;
                float ig = sigf(gv[0]);
                float fg = sigf(gv[1]);
                float gg = tanhf(gv[2]);
                float og = sigf(gv[3]);
                float c  = fg * g_c[idx] + ig * gg;
                g_c[idx] = c;
                float h2 = og * tanhf(c);
                g_h[idx] = h2;
                hh[h] = h2;
                g_XC[b*1024 + h] = h2;
                __nv_bfloat16 hi, lo; bsplit(h2, hi, lo);
                g_Xh[b*KX + 1024 + h] = hi;
                g_Xl[b*KX + 1024 + h] = lo;
            }
            __syncthreads();

            #pragma unroll
            for (int i = 0; i < 8; i++){
                int s = w*8 + i;
                const float* pr = &g_proj[((size_t)s*BB + b)*HH];
                float sum = 0.f;
                #pragma unroll
                for (int k = 0; k < 16; k++) sum += hh[l + k*32] * pr[l + k*32];
                #pragma unroll
                for (int off=16; off>0; off>>=1) sum += __shfl_xor_sync(0xffffffffu, sum, off);
                if (l == 0) sc[s] = (s < len) ? sum : -1e9f;
            }
            __syncthreads();

            if (tid < 32){
                float v0 = sc[tid], v1 = sc[tid+32];
                float m = fmaxf(v0, v1);
                #pragma unroll
                for (int off=16; off>0; off>>=1) m = fmaxf(m, __shfl_xor_sync(0xffffffffu, m, off));
                float e0 = expf(v0 - m), e1 = expf(v1 - m);
                float s = e0 + e1;
                #pragma unroll
                for (int off=16; off>0; off>>=1) s += __shfl_xor_sync(0xffffffffu, s, off);
                float inv = 1.0f / s;
                sc[tid]    = e0 * inv;
                sc[tid+32] = e1 * inv;
            }
            __syncthreads();

            #pragma unroll
            for (int rep = 0; rep < 2; rep++){
                int h = tid + rep*256;
                float a0=0.f, a1=0.f, a2=0.f, a3=0.f;
                #pragma unroll 4
                for (int s0 = 0; s0 < 16; s0++){
                    a0 += sc[s0]      * enc[((size_t)(s0)*BB    + b)*HH + h];
                    a1 += sc[s0 + 16] * enc[((size_t)(s0+16)*BB + b)*HH + h];
                    a2 += sc[s0 + 32] * enc[((size_t)(s0+32)*BB + b)*HH + h];
                    a3 += sc[s0 + 48] * enc[((size_t)(s0+48)*BB + b)*HH + h];
                }
                g_XC[b*1024 + 512 + h] = (a0 + a1) + (a2 + a3);
            }
        } else {
            unsigned winbase = (unsigned)t * 147456u;
            #pragma unroll
            for (int j = 0; j < 6; j++){
                unsigned i4 = winbase + (unsigned)j*24576u + (unsigned)(ct-32)*256u + tid;
                if (i4 < WF4) convW_item(W_o, i4);
            }
        }
        gbar(++nb * NCTA);

        // ===== Phase C =====
        if (ct < 64){
            float* xc = (float*)(dsm + OFF_XC);
            const int c = ct*8 + w;
            #pragma unroll
            for (int half = 0; half < 2; half++){
                if (half) __syncthreads();
                {
                    const float4* src = (const float4*)(g_XC + half*16*1024);
                    float4* dst = (float4*)xc;
                    #pragma unroll
                    for (int i = 0; i < 16; i++) dst[tid + i*256] = src[tid + i*256];
                }
                __syncthreads();
                for (int b = 0; b < 16; b++){
                    const float* xb = xc + b*1024;
                    float s = 0.f;
                    #pragma unroll
                    for (int q=0;q<32;q++) s += wreg[q] * xb[l + q*32];
                    #pragma unroll
                    for (int off=16; off>0; off>>=1) s += __shfl_xor_sync(0xffffffffu, s, off);
                    if (l == 0){
                        int gb = half*16 + b;
                        float v = tanhf(s + wbias);
                        __nv_bfloat16 hi, lo; bsplit(v, hi, lo);
                        int r = t*BB + gb;
                        g_Ah[(size_t)r*HH + c] = hi;
                        g_Al[(size_t)r*HH + c] = lo;
                        g_Xh[gb*KX + 512 + c] = hi;
                        g_Xl[gb*KX + 512 + c] = lo;
                    }
                }
            }
        } else if (t + 1 < T1){
            const int z2 = (ct-64) >> 4;
            const int nb2 = ((ct-64) & 15) * 128;
            const unsigned sA = base + OFF_SCR;

            auto issueA = [&](int buf, int ck){
                const int koff = 1024 + z2*128 + ck*64;
                const unsigned uAh = sA + buf*9216;
                const unsigned uAl = uAh + 4608;
                #pragma unroll
                for (int q = 0; q < 2; q++){
                    int i = q*256 + tid;
                    int idx = i & 255; int row = idx >> 3, c8 = idx & 7;
                    const __nv_bfloat16* src = (i < 256 ? g_Xh : g_Xl)
                                               + (size_t)row*KX + koff + c8*8;
                    unsigned dst = (i < 256 ? uAh : uAl) + (unsigned)(row*GSTR + c8*8)*2;
                    cpa16(dst, src);
                }
            };

            float acc[2][2][4];
            #pragma unroll
            for (int mi=0;mi<2;mi++)
                #pragma unroll
                for (int ni=0;ni<2;ni++)
                    #pragma unroll
                    for (int q=0;q<4;q++) acc[mi][ni][q]=0.f;

            issueA(0, 0); CP_COMMIT();
            #pragma unroll
            for (int ck = 0; ck < 2; ck++){
                if (ck == 0){ issueA(1, 1); CP_COMMIT(); CP_WAIT(1); }
                else        { CP_WAIT(0); }
                __syncthreads();
                const unsigned uAh = sA + ck*9216;
                const unsigned uAl = uAh + 4608;
                const unsigned uBh = base + OFF_WHB + ck*36864;
                const unsigned uBl = uBh + 18432;
                #pragma unroll
                for (int ks = 0; ks < 64; ks += 16){
                    unsigned afh[2][4], afl[2][4], bfh[4], bfl[4];
                    #pragma unroll
                    for (int mi=0;mi<2;mi++){
                        ldmx4(afh[mi], uAh + (unsigned)((mi*16 + arow)*GSTR + ks + akoff)*2);
                        ldmx4(afl[mi], uAl + (unsigned)((mi*16 + arow)*GSTR + ks + akoff)*2);
                    }
                    ldmx4(bfh, uBh + (unsigned)((n0 + brow)*GSTR + ks + bkoff)*2);
                    ldmx4(bfl, uBl + (unsigned)((n0 + brow)*GSTR + ks + bkoff)*2);
                    #pragma unroll
                    for (int mi=0;mi<2;mi++)
                        #pragma unroll
                        for (int ni=0;ni<2;ni++){
                            mma16816(acc[mi][ni], afh[mi], bfh[ni*2], bfh[ni*2+1]);
                            mma16816(acc[mi][ni], afh[mi], bfl[ni*2], bfl[ni*2+1]);
                            mma16816(acc[mi][ni], afl[mi], bfh[ni*2], bfh[ni*2+1]);
                        }
                }
                __syncthreads();
            }

            #pragma unroll
            for (int mi=0;mi<2;mi++){
                #pragma unroll
                for (int ni=0;ni<2;ni++){
                    int row = mi*16 + (l >> 2);
                    int col = nb2 + n0 + ni*8 + (l & 3)*2;
                    float* gp = g_GpartH + ((size_t)z2*BB + row)*JG + col;
                    gp[0] = acc[mi][ni][0];
                    gp[1] = acc[mi][ni][1];
                    gp += 8*JG;
                    gp[0] = acc[mi][ni][2];
                    gp[1] = acc[mi][ni][3];
                }
            }
        }
        gbar(++nb * NCTA);
    }
}

// ---------------------------------------------------------------------------
// Vocab GEMM: single K-pass 3-term, software-pipelined fragments
// ---------------------------------------------------------------------------
__global__ void __launch_bounds__(256, 2)
k_vocab(const float* __restrict__ b_o, float* __restrict__ logits)
{
    extern __shared__ char vsm[];
    const int tid  = threadIdx.x;
    const int wid  = tid >> 5, lane = tid & 31;
    const int mtile = blockIdx.x;
    const int ntile = blockIdx.y;

    const __nv_bfloat16* Asrc_h = g_Ah + (size_t)mtile*128*HH;
    const __nv_bfloat16* Asrc_l = g_Al + (size_t)mtile*128*HH;
    const __nv_bfloat16* Bsrc_h = g_Wh + (size_t)ntile*64*HH;
    const __nv_bfloat16* Bsrc_l = g_Wl + (size_t)ntile*64*HH;

    const unsigned base = smem_u32(vsm);
    const unsigned uAh = base;
    const unsigned uAl = base + 20480;
    const unsigned uBh = base + 40960;
    const unsigned uBl = base + 51200;

    auto issue = [&](int buf, int ch){
        const int k0 = ch*32;
        const unsigned a_h = uAh + buf*10240;
        const unsigned a_l = uAl + buf*10240;
        const unsigned b_h = uBh + buf*5120;
        const unsigned b_l = uBl + buf*5120;
        #pragma unroll
        for (int q = 0; q < 6; q++){
            int i = q*256 + tid;
            if (i < 1024){
                int j = i & 511; int r = j >> 2, c8 = (j & 3)*8;
                const __nv_bfloat16* src = (i < 512 ? Asrc_h : Asrc_l)
                                           + (size_t)r*HH + k0 + c8;
                unsigned dst = (i < 512 ? a_h : a_l) + (unsigned)(r*VK_STR + c8)*2;
                cpa16(dst, src);
            } else {
                int j = (i - 1024) & 255; int r = j >> 2, c8 = (j & 3)*8;
                const __nv_bfloat16* src = (i < 1280 ? Bsrc_h : Bsrc_l)
                                           + (size_t)r*HH + k0 + c8;
                unsigned dst = (i < 1280 ? b_h : b_l) + (unsigned)(r*VK_STR + c8)*2;
                cpa16(dst, src);
            }
        }
    };

    float acc[2][4][4];
    #pragma unroll
    for (int mi=0;mi<2;mi++)
        #pragma unroll
        for (int ni=0;ni<4;ni++)
            #pragma unroll
            for (int q=0;q<4;q++) acc[mi][ni][q]=0.f;

    const int m0 = (wid & 3) * 32;
    const int n0 = (wid >> 2) * 32;
    const int arow  = (lane & 7) + ((lane >> 3) & 1) * 8;
    const int akoff = (lane >> 4) * 8;
    const int brow  = (lane & 7) + ((lane >> 4) & 1) * 8;
    const int bkoff = ((lane >> 3) & 1) * 8;

    issue(0, 0); CP_COMMIT();
    const int NCH = 16;
    for (int ch = 0; ch < NCH; ch++){
        int buf = ch & 1;
        if (ch + 1 < NCH){ issue(buf ^ 1, ch + 1); CP_COMMIT(); CP_WAIT(1); }
        else             { CP_WAIT(0); }
        __syncthreads();
        const unsigned a_h = uAh + buf*10240;
        const unsigned a_l = uAl + buf*10240;
        const unsigned b_h = uBh + buf*5120;
        const unsigned b_l = uBl + buf*5120;

        unsigned afh[2][2][4], afl[2][2][4], bfh[2][2][4], bfl[2][2][4];
        #pragma unroll
        for (int s2 = 0; s2 < 2; s2++){
            const int ks = s2*16;
            #pragma unroll
            for (int mi=0;mi<2;mi++){
                ldmx4(afh[s2][mi], a_h + (unsigned)((m0 + mi*16 + arow)*VK_STR + ks + akoff)*2);
                ldmx4(afl[s2][mi], a_l + (unsigned)((m0 + mi*16 + arow)*VK_STR + ks + akoff)*2);
            }
            #pragma unroll
            for (int g=0; g<2; g++){
                ldmx4(bfh[s2][g], b_h + (unsigned)((n0 + g*16 + brow)*VK_STR + ks + bkoff)*2);
                ldmx4(bfl[s2][g], b_l + (unsigned)((n0 + g*16 + brow)*VK_STR + ks + bkoff)*2);
            }
        }
        #pragma unroll
        for (int s2 = 0; s2 < 2; s2++)
            #pragma unroll
            for (int mi=0;mi<2;mi++)
                #pragma unroll
                for (int ni=0;ni<4;ni++){
                    unsigned h0 = bfh[s2][ni>>1][(ni&1)*2], h1 = bfh[s2][ni>>1][(ni&1)*2+1];
                    unsigned l0 = bfl[s2][ni>>1][(ni&1)*2], l1 = bfl[s2][ni>>1][(ni&1)*2+1];
                    mma16816(acc[mi][ni], afh[s2][mi], h0, h1);
                    mma16816(acc[mi][ni], afh[s2][mi], l0, l1);
                    mma16816(acc[mi][ni], afl[s2][mi], h0, h1);
                }
        __syncthreads();
    }

    #pragma unroll
    for (int mi=0;mi<2;mi++){
        #pragma unroll
        for (int ni=0;ni<4;ni++){
            int row = mtile*128 + m0 + mi*16 + (lane >> 2);
            int col = ntile*64  + n0 + ni*8  + (lane & 3)*2;
            float bia0 = b_o[col], bia1 = b_o[col+1];
            if (row < T1*BB){
                float* o = logits + (size_t)row*VV + col;
                o[0] = acc[mi][ni][0] + bia0;
                o[1] = acc[mi][ni][1] + bia1;
            }
            if (row + 8 < T1*BB){
                float* o = logits + (size_t)(row+8)*VV + col;
                o[0] = acc[mi][ni][2] + bia0;
                o[1] = acc[mi][ni][3] + bia1;
            }
        }
    }
}

// ---------------------------------------------------------------------------
// Online log-softmax + argmax : 512 threads, float4
// ---------------------------------------------------------------------------
__global__ void __launch_bounds__(512)
k_lsm(float* __restrict__ logits)
{
    __shared__ float ms[512], ss[512];
    __shared__ int   ii[512];
    const int row = blockIdx.x;
    const int tid = threadIdx.x;
    float* x = logits + (size_t)row * VV;
    const float4* x4 = (const float4*)x;
    const int N4 = VV/4;     // 8000

    float4 v0 = x4[tid];
    float m = v0.x; int mi = tid*4; float s = 1.f;
    {
        float vals[3] = {v0.y, v0.z, v0.w};
        #pragma unroll
        for (int j=0;j<3;j++){
            float v = vals[j];
            if (v > m){ s = s*fexp(m - v) + 1.f; m = v; mi = tid*4 + j + 1; }
            else        s += fexp(v - m);
        }
    }
    for (int i4 = tid + 512; i4 < N4; i4 += 512){
        float4 v4 = x4[i4];
        float vals[4] = {v4.x, v4.y, v4.z, v4.w};
        #pragma unroll
        for (int j=0;j<4;j++){
            float v = vals[j];
            if (v > m){ s = s*fexp(m - v) + 1.f; m = v; mi = i4*4 + j; }
            else        s += fexp(v - m);
        }
    }
    ms[tid]=m; ss[tid]=s; ii[tid]=mi;
    __syncthreads();
    for (int st = 256; st > 0; st >>= 1){
        if (tid < st){
            float m1=ms[tid], s1=ss[tid]; int i1=ii[tid];
            float m2=ms[tid+st], s2=ss[tid+st]; int i2=ii[tid+st];
            if (m2 > m1)      { ms[tid]=m2; ss[tid]=s1*fexp(m1-m2)+s2; ii[tid]=i2; }
            else if (m2 < m1) { ss[tid]=s1+s2*fexp(m2-m1); }
            else              { ss[tid]=s1+s2; ii[tid]=min(i1,i2); }
        }
        __syncthreads();
    }
    float lse = ms[0] + logf(ss[0]);
    if (tid == 0) g_argmax[row] = ii[0];

    float4* xw = (float4*)x;
    for (int i4 = tid; i4 < N4; i4 += 512){
        float4 v4 = xw[i4];
        v4.x -= lse; v4.y -= lse; v4.z -= lse; v4.w -= lse;
        xw[i4] = v4;
    }
}

__global__ void k_tail_f(float* __restrict__ out)
{
    int r = blockIdx.x*blockDim.x + threadIdx.x;
    if (r < T1*BB) out[TBV + r] = (float)g_argmax[r];
}
__global__ void k_tail_i(int* __restrict__ out)
{
    int r = blockIdx.x*blockDim.x + threadIdx.x;
    if (r < T1*BB) out[r] = g_argmax[r];
}

// ---------------------------------------------------------------------------
extern "C" void kernel_launch(void* const* d_in, const int* in_sizes, int n_in,
                              void* d_out, int out_size)
{
    const int*   tgt   = (const int*)  d_in[0];
    const int*   lens  = (const int*)  d_in[1];
    const float* enc   = (const float*)d_in[2];
    const float* h0    = (const float*)d_in[3];
    const float* c0    = (const float*)d_in[4];
    const float* emb   = (const float*)d_in[5];
    const float* W_ih  = (const float*)d_in[6];
    const float* W_hh  = (const float*)d_in[7];
    const float* b_ih  = (const float*)d_in[8];
    const float* b_hh  = (const float*)d_in[9];
    const float* W_a   = (const float*)d_in[10];
    const float* W_c   = (const float*)d_in[11];
    const float* b_c   = (const float*)d_in[12];
    const float* W_o   = (const float*)d_in[13];
    const float* b_o   = (const float*)d_in[14];

    float *p_proj=nullptr, *p_lg=nullptr, *p_gemb=nullptr;
    __nv_bfloat16 *p_eh=nullptr, *p_el=nullptr, *p_gwh=nullptr, *p_gwl=nullptr;
    __nv_bfloat16 *p_enh=nullptr, *p_enl=nullptr, *p_wah=nullptr, *p_wal=nullptr;
    cudaGetSymbolAddress((void**)&p_proj, g_proj);
    cudaGetSymbolAddress((void**)&p_lg,   g_logits);
    cudaGetSymbolAddress((void**)&p_gemb, g_Gemb);
    cudaGetSymbolAddress((void**)&p_eh,   g_Eh);
    cudaGetSymbolAddress((void**)&p_el,   g_El);
    cudaGetSymbolAddress((void**)&p_gwh,  g_gWh);
    cudaGetSymbolAddress((void**)&p_gwl,  g_gWl);
    cudaGetSymbolAddress((void**)&p_enh,  g_ENh);
    cudaGetSymbolAddress((void**)&p_enl,  g_ENl);
    cudaGetSymbolAddress((void**)&p_wah,  g_WAh);
    cudaGetSymbolAddress((void**)&p_wal,  g_WAl);

    const bool big = (size_t)out_size >= TBV;
    float* logits = big ? (float*)d_out : p_lg;

    cudaFuncSetAttribute(k_loop,   cudaFuncAttributeMaxDynamicSharedMemorySize, 131072);
    cudaFuncSetAttribute(k_gh0,    cudaFuncAttributeMaxDynamicSharedMemorySize, 2*ABUF);
    cudaFuncSetAttribute(k_vocab,  cudaFuncAttributeMaxDynamicSharedMemorySize, 61440);
    cudaFuncSetAttribute(k_hmm,    cudaFuncAttributeMaxDynamicSharedMemorySize, 61440);

    // prologue
    k_prep0<<<64, 256>>>(h0, c0);
    k_convall<<<4864, 256>>>(tgt, emb, W_ih, W_hh, enc, W_a);
    k_hmm<<<dim3(8, 32), 256, 61440>>>(p_eh, p_el, EE, p_gwh, p_gwl, KX,
                                       p_gemb, JG, b_ih, b_hh);
    k_hmm<<<dim3(16, 8), 256, 61440>>>(p_enh, p_enl, HH, p_wah, p_wal, HH,
                                       p_proj, HH, nullptr, nullptr);
    k_gh0<<<64, 256, 2*ABUF>>>();

    // persistent recurrent loop
    k_loop<<<NCTA, 256, 131072>>>(lens, enc, W_c, b_c, W_o);

    // vocab projection + log-softmax
    k_vocab<<<dim3(8, 500), 256, 61440>>>(b_o, logits);
    k_lsm<<<T1*BB, 512>>>(logits);

    if (big && (size_t)out_size >= TBV + (size_t)T1*BB) {
        k_tail_f<<<4, 256>>>((float*)d_out);
    } else if (!big) {
        k_tail_i<<<4, 256>>>((int*)d_out);
    }
}